// round 1
// baseline (speedup 1.0000x reference)
#include <cuda_runtime.h>
#include <cstddef>

// Problem constants
#define BATCH   16
#define NQ      4096
#define QD      320
#define CD      1024
#define CTX     93
#define TXT     77
#define IMG     16
#define HEADS   8
#define DH      64
#define ID      512            // HEADS*DH
#define MQ      (BATCH*NQ)     // 65536
#define ATT_SCALE 0.125f       // 64^-0.5

// ---------------- scratch (static device allocations) ----------------
__device__ float g_Q[MQ * ID];            // 128 MiB
__device__ float g_A[MQ * ID];            // 128 MiB
__device__ float g_K [BATCH * TXT * ID];
__device__ float g_V [BATCH * TXT * ID];
__device__ float g_Ki[BATCH * IMG * ID];
__device__ float g_Vi[BATCH * IMG * ID];

// ---------------- generic fp32 tiled GEMM ----------------
// C[b] = A[b] @ Bw (+ bias), A: MxK row-major (batch stride sA),
// Bw: KxN row-major (shared), C: MxN row-major (batch stride sC).
// Requires N % 64 == 0, K % 16 == 0. M arbitrary (guarded).
#define BM 128
#define BN 64
#define BKK 16

__global__ __launch_bounds__(256)
void sgemm_kernel(const float* __restrict__ A, const float* __restrict__ Bw,
                  float* __restrict__ C, const float* __restrict__ bias,
                  int M, int N, int K, size_t sA, size_t sC)
{
    __shared__ float As[BKK][BM + 4];
    __shared__ float Bs[BKK][BN];

    const int tid = threadIdx.x;
    A += (size_t)blockIdx.z * sA;
    C += (size_t)blockIdx.z * sC;
    const int m0 = blockIdx.y * BM;
    const int n0 = blockIdx.x * BN;

    const int a_row = tid >> 2;          // 0..63
    const int a_col = (tid & 3) * 4;     // 0,4,8,12
    const int b_row = tid >> 4;          // 0..15
    const int b_col = (tid & 15) * 4;

    const int ty = tid >> 4;             // 0..15 -> rows ty*8
    const int tx = tid & 15;             // 0..15 -> cols tx*4

    float acc[8][4];
    #pragma unroll
    for (int i = 0; i < 8; i++)
        #pragma unroll
        for (int j = 0; j < 4; j++) acc[i][j] = 0.f;

    for (int k0 = 0; k0 < K; k0 += BKK) {
        #pragma unroll
        for (int r = 0; r < 2; r++) {
            const int row = m0 + a_row + r * 64;
            float4 v = make_float4(0.f, 0.f, 0.f, 0.f);
            if (row < M)
                v = *(const float4*)(A + (size_t)row * K + k0 + a_col);
            As[a_col + 0][a_row + r * 64] = v.x;
            As[a_col + 1][a_row + r * 64] = v.y;
            As[a_col + 2][a_row + r * 64] = v.z;
            As[a_col + 3][a_row + r * 64] = v.w;
        }
        *(float4*)&Bs[b_row][b_col] =
            *(const float4*)(Bw + (size_t)(k0 + b_row) * N + n0 + b_col);
        __syncthreads();

        #pragma unroll
        for (int kk = 0; kk < BKK; kk++) {
            float a[8], b[4];
            #pragma unroll
            for (int i = 0; i < 8; i++) a[i] = As[kk][ty * 8 + i];
            #pragma unroll
            for (int j = 0; j < 4; j++) b[j] = Bs[kk][tx * 4 + j];
            #pragma unroll
            for (int i = 0; i < 8; i++)
                #pragma unroll
                for (int j = 0; j < 4; j++)
                    acc[i][j] += a[i] * b[j];
        }
        __syncthreads();
    }

    #pragma unroll
    for (int i = 0; i < 8; i++) {
        const int row = m0 + ty * 8 + i;
        if (row < M) {
            const int col = n0 + tx * 4;
            float4 v = make_float4(acc[i][0], acc[i][1], acc[i][2], acc[i][3]);
            if (bias) {
                v.x += bias[col];     v.y += bias[col + 1];
                v.z += bias[col + 2]; v.w += bias[col + 3];
            }
            *(float4*)(C + (size_t)row * N + col) = v;
        }
    }
}

// ---------------- attention ----------------
// One block: (b, h, 128 query rows). Dual-branch softmax (77 text / 16 img),
// scales folded into epilogue.
#define ROWS 128

__global__ __launch_bounds__(ROWS)
void attn_kernel(const float* __restrict__ Q,
                 const float* __restrict__ Kt, const float* __restrict__ Vt,
                 const float* __restrict__ Ki, const float* __restrict__ Vi,
                 float* __restrict__ Aout,
                 const float* __restrict__ ts_p, const float* __restrict__ is_p)
{
    extern __shared__ float sm[];
    float* Ks  = sm;                       // 77*64
    float* Vs  = Ks  + TXT * DH;           // 77*64
    float* Kis = Vs  + TXT * DH;           // 16*64
    float* Vis = Kis + IMG * DH;           // 16*64
    float* Sc  = Vis + IMG * DH;           // 93*128

    const int b = blockIdx.z, h = blockIdx.y;
    const int t = threadIdx.x;
    const int row = b * NQ + blockIdx.x * ROWS + t;

    // cooperative tile load (float4)
    {
        const float4* ksrc = (const float4*)(Kt + ((size_t)b * TXT) * ID + h * DH);
        const float4* vsrc = (const float4*)(Vt + ((size_t)b * TXT) * ID + h * DH);
        for (int i4 = t; i4 < TXT * (DH / 4); i4 += ROWS) {
            const int j = i4 / (DH / 4), d4 = i4 % (DH / 4);
            ((float4*)Ks)[j * (DH / 4) + d4] = ksrc[j * (ID / 4) + d4];
            ((float4*)Vs)[j * (DH / 4) + d4] = vsrc[j * (ID / 4) + d4];
        }
        const float4* kisrc = (const float4*)(Ki + ((size_t)b * IMG) * ID + h * DH);
        const float4* visrc = (const float4*)(Vi + ((size_t)b * IMG) * ID + h * DH);
        for (int i4 = t; i4 < IMG * (DH / 4); i4 += ROWS) {
            const int j = i4 / (DH / 4), d4 = i4 % (DH / 4);
            ((float4*)Kis)[j * (DH / 4) + d4] = kisrc[j * (ID / 4) + d4];
            ((float4*)Vis)[j * (DH / 4) + d4] = visrc[j * (ID / 4) + d4];
        }
    }
    __syncthreads();

    // per-thread query row
    float q[DH];
    {
        const float4* qp = (const float4*)(Q + (size_t)row * ID + h * DH);
        #pragma unroll
        for (int d4 = 0; d4 < DH / 4; d4++) {
            float4 v = qp[d4];
            q[d4 * 4 + 0] = v.x; q[d4 * 4 + 1] = v.y;
            q[d4 * 4 + 2] = v.z; q[d4 * 4 + 3] = v.w;
        }
    }

    // scores: text then img, staged in Sc[j][t]
    for (int j = 0; j < TXT; j++) {
        const float4* kr = (const float4*)(Ks + j * DH);
        float s = 0.f;
        #pragma unroll
        for (int d4 = 0; d4 < DH / 4; d4++) {
            float4 kv = kr[d4];
            s += q[d4 * 4 + 0] * kv.x + q[d4 * 4 + 1] * kv.y
               + q[d4 * 4 + 2] * kv.z + q[d4 * 4 + 3] * kv.w;
        }
        Sc[j * ROWS + t] = s * ATT_SCALE;
    }
    for (int j = 0; j < IMG; j++) {
        const float4* kr = (const float4*)(Kis + j * DH);
        float s = 0.f;
        #pragma unroll
        for (int d4 = 0; d4 < DH / 4; d4++) {
            float4 kv = kr[d4];
            s += q[d4 * 4 + 0] * kv.x + q[d4 * 4 + 1] * kv.y
               + q[d4 * 4 + 2] * kv.z + q[d4 * 4 + 3] * kv.w;
        }
        Sc[(TXT + j) * ROWS + t] = s * ATT_SCALE;
    }

    // softmax statistics (per branch), replace scores with exp(s - m)
    float m_t = -1e30f, m_i = -1e30f;
    for (int j = 0; j < TXT; j++) m_t = fmaxf(m_t, Sc[j * ROWS + t]);
    for (int j = 0; j < IMG; j++) m_i = fmaxf(m_i, Sc[(TXT + j) * ROWS + t]);
    float l_t = 0.f, l_i = 0.f;
    for (int j = 0; j < TXT; j++) {
        float e = __expf(Sc[j * ROWS + t] - m_t);
        l_t += e; Sc[j * ROWS + t] = e;
    }
    for (int j = 0; j < IMG; j++) {
        float e = __expf(Sc[(TXT + j) * ROWS + t] - m_i);
        l_i += e; Sc[(TXT + j) * ROWS + t] = e;
    }

    // PV accumulation
    float acc[DH];
    #pragma unroll
    for (int d = 0; d < DH; d++) acc[d] = 0.f;

    for (int j = 0; j < TXT; j++) {
        const float w = Sc[j * ROWS + t];
        const float4* vr = (const float4*)(Vs + j * DH);
        #pragma unroll
        for (int d4 = 0; d4 < DH / 4; d4++) {
            float4 vv = vr[d4];
            acc[d4 * 4 + 0] += w * vv.x; acc[d4 * 4 + 1] += w * vv.y;
            acc[d4 * 4 + 2] += w * vv.z; acc[d4 * 4 + 3] += w * vv.w;
        }
    }
    const float ct = ts_p[0] / l_t;
    #pragma unroll
    for (int d = 0; d < DH; d++) acc[d] *= ct;

    const float ci = is_p[0] / l_i;
    for (int j = 0; j < IMG; j++) {
        const float w = Sc[(TXT + j) * ROWS + t] * ci;
        const float4* vr = (const float4*)(Vis + j * DH);
        #pragma unroll
        for (int d4 = 0; d4 < DH / 4; d4++) {
            float4 vv = vr[d4];
            acc[d4 * 4 + 0] += w * vv.x; acc[d4 * 4 + 1] += w * vv.y;
            acc[d4 * 4 + 2] += w * vv.z; acc[d4 * 4 + 3] += w * vv.w;
        }
    }

    float4* op = (float4*)(Aout + (size_t)row * ID + h * DH);
    #pragma unroll
    for (int d4 = 0; d4 < DH / 4; d4++)
        op[d4] = make_float4(acc[d4 * 4 + 0], acc[d4 * 4 + 1],
                             acc[d4 * 4 + 2], acc[d4 * 4 + 3]);
}

// ---------------- launch ----------------
extern "C" void kernel_launch(void* const* d_in, const int* in_sizes, int n_in,
                              void* d_out, int out_size)
{
    const float* x    = (const float*)d_in[0];
    const float* ctx  = (const float*)d_in[1];
    const float* Wq   = (const float*)d_in[2];
    const float* Wk   = (const float*)d_in[3];
    const float* Wv   = (const float*)d_in[4];
    const float* Wkip = (const float*)d_in[5];
    const float* Wvip = (const float*)d_in[6];
    const float* Wo   = (const float*)d_in[7];
    const float* bo   = (const float*)d_in[8];
    const float* ts   = (const float*)d_in[9];
    const float* isc  = (const float*)d_in[10];
    float* out = (float*)d_out;

    float *gQ, *gA, *gK, *gV, *gKi, *gVi;
    cudaGetSymbolAddress((void**)&gQ,  g_Q);
    cudaGetSymbolAddress((void**)&gA,  g_A);
    cudaGetSymbolAddress((void**)&gK,  g_K);
    cudaGetSymbolAddress((void**)&gV,  g_V);
    cudaGetSymbolAddress((void**)&gKi, g_Ki);
    cudaGetSymbolAddress((void**)&gVi, g_Vi);

    const int attn_smem = (TXT * DH * 2 + IMG * DH * 2 + CTX * ROWS) * 4;
    cudaFuncSetAttribute(attn_kernel,
                         cudaFuncAttributeMaxDynamicSharedMemorySize, attn_smem);

    // context projections (batched over B, strided text/img slices)
    {
        dim3 g(ID / BN, 1, BATCH);
        sgemm_kernel<<<g, 256>>>(ctx,                Wk,   gK,  nullptr,
                                 TXT, ID, CD, (size_t)CTX * CD, (size_t)TXT * ID);
        sgemm_kernel<<<g, 256>>>(ctx,                Wv,   gV,  nullptr,
                                 TXT, ID, CD, (size_t)CTX * CD, (size_t)TXT * ID);
        sgemm_kernel<<<g, 256>>>(ctx + (size_t)TXT * CD, Wkip, gKi, nullptr,
                                 IMG, ID, CD, (size_t)CTX * CD, (size_t)IMG * ID);
        sgemm_kernel<<<g, 256>>>(ctx + (size_t)TXT * CD, Wvip, gVi, nullptr,
                                 IMG, ID, CD, (size_t)CTX * CD, (size_t)IMG * ID);
    }

    // Q projection
    {
        dim3 g(ID / BN, MQ / BM, 1);
        sgemm_kernel<<<g, 256>>>(x, Wq, gQ, nullptr, MQ, ID, QD, 0, 0);
    }

    // attention
    {
        dim3 g(NQ / ROWS, HEADS, BATCH);
        attn_kernel<<<g, ROWS, attn_smem>>>(gQ, gK, gV, gKi, gVi, gA, ts, isc);
    }

    // output projection + bias
    {
        dim3 g(QD / BN, MQ / BM, 1);
        sgemm_kernel<<<g, 256>>>(gA, Wo, out, bo, MQ, QD, ID, 0, 0);
    }
}

// round 3
// speedup vs baseline: 1.3399x; 1.3399x over previous
#include <cuda_runtime.h>
#include <cuda_bf16.h>
#include <cstdint>
#include <cstddef>

// Problem constants
#define BATCH   16
#define NQ      4096
#define QD      320
#define CD      1024
#define CTX     93
#define TXT     77
#define IMG     16
#define HEADS   8
#define DH      64
#define ID      512            // HEADS*DH
#define MQ      (BATCH*NQ)     // 65536
#define ATT_SCALE 0.125f

// ---------------- scratch ----------------
__device__ float g_Q[MQ * ID];
__device__ __nv_bfloat16 g_Ah[MQ * ID];
__device__ __nv_bfloat16 g_Al[MQ * ID];
__device__ __nv_bfloat16 g_xh[MQ * QD];
__device__ __nv_bfloat16 g_xl[MQ * QD];
__device__ __nv_bfloat16 g_Wqh[ID * QD];   // [N=512][K=320]
__device__ __nv_bfloat16 g_Wql[ID * QD];
__device__ __nv_bfloat16 g_Woh[QD * ID];   // [N=320][K=512]
__device__ __nv_bfloat16 g_Wol[QD * ID];
__device__ float g_K [BATCH * TXT * ID];
__device__ float g_V [BATCH * TXT * ID];
__device__ float g_Ki[BATCH * IMG * ID];
__device__ float g_Vi[BATCH * IMG * ID];

// ---------------- mma.sync bf16 split GEMM ----------------
// C[M,N] = (Ah+Al)[M,K] @ (Wh+Wl)[N,K]^T (+bias), fp32 out.
// Block tile 128x64, 4 warps of 64x32. K % 32 == 0, M % 128 == 0, N % 64 == 0.
#define GBK 32
#define SSTR 40   // padded bf16 stride

__device__ __forceinline__ void mma_bf16(float* c, const uint32_t* a, const uint32_t* b)
{
    asm volatile(
        "mma.sync.aligned.m16n8k16.row.col.f32.bf16.bf16.f32 "
        "{%0,%1,%2,%3}, {%4,%5,%6,%7}, {%8,%9}, {%0,%1,%2,%3};"
        : "+f"(c[0]), "+f"(c[1]), "+f"(c[2]), "+f"(c[3])
        : "r"(a[0]), "r"(a[1]), "r"(a[2]), "r"(a[3]), "r"(b[0]), "r"(b[1]));
}

__global__ __launch_bounds__(128)
void mma_gemm_kernel(const __nv_bfloat16* __restrict__ Ah,
                     const __nv_bfloat16* __restrict__ Al,
                     const __nv_bfloat16* __restrict__ Wh,
                     const __nv_bfloat16* __restrict__ Wl,
                     float* __restrict__ C, const float* __restrict__ bias,
                     int M, int N, int K)
{
    __shared__ __nv_bfloat16 Ash[128 * SSTR];
    __shared__ __nv_bfloat16 Asl[128 * SSTR];
    __shared__ __nv_bfloat16 Bsh[64 * SSTR];
    __shared__ __nv_bfloat16 Bsl[64 * SSTR];

    const int tid = threadIdx.x;
    const int wid = tid >> 5;
    const int lid = tid & 31;
    const int grp = lid >> 2;
    const int t4  = lid & 3;
    const int wm  = wid >> 1;       // 0..1 -> rows wm*64
    const int wn  = wid & 1;        // 0..1 -> cols wn*32
    const int m0  = blockIdx.y * 128;
    const int n0  = blockIdx.x * 64;

    float acc[4][4][4];
    #pragma unroll
    for (int m = 0; m < 4; m++)
        #pragma unroll
        for (int n = 0; n < 4; n++)
            #pragma unroll
            for (int j = 0; j < 4; j++) acc[m][n][j] = 0.f;

    for (int k0 = 0; k0 < K; k0 += GBK) {
        // A tile: 128 rows x 32 bf16 (hi/lo). 512 16B-chunks each; 4/thread.
        #pragma unroll
        for (int i = 0; i < 4; i++) {
            const int c = tid + i * 128;
            const int r = c >> 2, cb = (c & 3) * 8;
            const size_t g = (size_t)(m0 + r) * K + k0 + cb;
            *(uint4*)(Ash + r * SSTR + cb) = *(const uint4*)(Ah + g);
            *(uint4*)(Asl + r * SSTR + cb) = *(const uint4*)(Al + g);
        }
        // B tile: 64 rows x 32 bf16 (hi/lo). 256 chunks; 2/thread.
        #pragma unroll
        for (int i = 0; i < 2; i++) {
            const int c = tid + i * 128;
            const int r = c >> 2, cb = (c & 3) * 8;
            const size_t g = (size_t)(n0 + r) * K + k0 + cb;
            *(uint4*)(Bsh + r * SSTR + cb) = *(const uint4*)(Wh + g);
            *(uint4*)(Bsl + r * SSTR + cb) = *(const uint4*)(Wl + g);
        }
        __syncthreads();

        #pragma unroll
        for (int kk = 0; kk < GBK; kk += 16) {
            uint32_t bh[4][2], bl[4][2];
            #pragma unroll
            for (int n = 0; n < 4; n++) {
                const int br = wn * 32 + n * 8 + grp;
                bh[n][0] = *(const uint32_t*)(Bsh + br * SSTR + kk + t4 * 2);
                bh[n][1] = *(const uint32_t*)(Bsh + br * SSTR + kk + t4 * 2 + 8);
                bl[n][0] = *(const uint32_t*)(Bsl + br * SSTR + kk + t4 * 2);
                bl[n][1] = *(const uint32_t*)(Bsl + br * SSTR + kk + t4 * 2 + 8);
            }
            #pragma unroll
            for (int m = 0; m < 4; m++) {
                const int ar0 = wm * 64 + m * 16 + grp;
                uint32_t ah[4], al[4];
                ah[0] = *(const uint32_t*)(Ash + ar0 * SSTR + kk + t4 * 2);
                ah[1] = *(const uint32_t*)(Ash + (ar0 + 8) * SSTR + kk + t4 * 2);
                ah[2] = *(const uint32_t*)(Ash + ar0 * SSTR + kk + t4 * 2 + 8);
                ah[3] = *(const uint32_t*)(Ash + (ar0 + 8) * SSTR + kk + t4 * 2 + 8);
                al[0] = *(const uint32_t*)(Asl + ar0 * SSTR + kk + t4 * 2);
                al[1] = *(const uint32_t*)(Asl + (ar0 + 8) * SSTR + kk + t4 * 2);
                al[2] = *(const uint32_t*)(Asl + ar0 * SSTR + kk + t4 * 2 + 8);
                al[3] = *(const uint32_t*)(Asl + (ar0 + 8) * SSTR + kk + t4 * 2 + 8);
                #pragma unroll
                for (int n = 0; n < 4; n++) {
                    mma_bf16(acc[m][n], ah, bh[n]);
                    mma_bf16(acc[m][n], ah, bl[n]);
                    mma_bf16(acc[m][n], al, bh[n]);
                }
            }
        }
        __syncthreads();
    }

    // epilogue
    #pragma unroll
    for (int m = 0; m < 4; m++) {
        const int row0 = m0 + wm * 64 + m * 16 + grp;
        #pragma unroll
        for (int n = 0; n < 4; n++) {
            const int col = n0 + wn * 32 + n * 8 + t4 * 2;
            float b0 = 0.f, b1 = 0.f;
            if (bias) { b0 = bias[col]; b1 = bias[col + 1]; }
            *(float2*)(C + (size_t)row0 * N + col) =
                make_float2(acc[m][n][0] + b0, acc[m][n][1] + b1);
            *(float2*)(C + (size_t)(row0 + 8) * N + col) =
                make_float2(acc[m][n][2] + b0, acc[m][n][3] + b1);
        }
    }
}

// ---------------- split / transpose prep ----------------
__global__ void split_kernel(const float* __restrict__ X,
                             __nv_bfloat16* __restrict__ H,
                             __nv_bfloat16* __restrict__ L, int n4)
{
    int i = blockIdx.x * blockDim.x + threadIdx.x;
    if (i >= n4) return;
    float4 v = ((const float4*)X)[i];
    float f[4] = {v.x, v.y, v.z, v.w};
    __nv_bfloat16 h[4], l[4];
    #pragma unroll
    for (int j = 0; j < 4; j++) {
        h[j] = __float2bfloat16(f[j]);
        l[j] = __float2bfloat16(f[j] - __bfloat162float(h[j]));
    }
    ((__nv_bfloat162*)H)[2 * i]     = __nv_bfloat162(h[0], h[1]);
    ((__nv_bfloat162*)H)[2 * i + 1] = __nv_bfloat162(h[2], h[3]);
    ((__nv_bfloat162*)L)[2 * i]     = __nv_bfloat162(l[0], l[1]);
    ((__nv_bfloat162*)L)[2 * i + 1] = __nv_bfloat162(l[2], l[3]);
}

// W[K,N] fp32 -> Ht/Lt[N,K] bf16 (transposed split)
__global__ void wsplit_t_kernel(const float* __restrict__ W,
                                __nv_bfloat16* __restrict__ Ht,
                                __nv_bfloat16* __restrict__ Lt, int K, int N)
{
    int idx = blockIdx.x * blockDim.x + threadIdx.x;
    if (idx >= K * N) return;
    int k = idx / N, n = idx % N;
    float v = W[idx];
    __nv_bfloat16 h = __float2bfloat16(v);
    __nv_bfloat16 l = __float2bfloat16(v - __bfloat162float(h));
    Ht[(size_t)n * K + k] = h;
    Lt[(size_t)n * K + k] = l;
}

// ---------------- fused ctx projections (fp32 SIMT) ----------------
#define BM 128
#define BN 64
#define BKK 16

__device__ __forceinline__
void gemm_body(const float* __restrict__ A, const float* __restrict__ Bw,
               float* __restrict__ C, int M, int N, int K, int n0blk)
{
    __shared__ float As[BKK][BM + 4];
    __shared__ float Bs[BKK][BN];
    const int tid = threadIdx.x;
    const int n0 = n0blk * BN;

    const int a_row = tid >> 2;
    const int a_col = (tid & 3) * 4;
    const int b_row = tid >> 4;
    const int b_col = (tid & 15) * 4;
    const int ty = tid >> 4;
    const int tx = tid & 15;

    float acc[8][4];
    #pragma unroll
    for (int i = 0; i < 8; i++)
        #pragma unroll
        for (int j = 0; j < 4; j++) acc[i][j] = 0.f;

    for (int k0 = 0; k0 < K; k0 += BKK) {
        #pragma unroll
        for (int r = 0; r < 2; r++) {
            const int row = a_row + r * 64;
            float4 v = make_float4(0.f, 0.f, 0.f, 0.f);
            if (row < M) v = *(const float4*)(A + (size_t)row * K + k0 + a_col);
            As[a_col + 0][row] = v.x;
            As[a_col + 1][row] = v.y;
            As[a_col + 2][row] = v.z;
            As[a_col + 3][row] = v.w;
        }
        *(float4*)&Bs[b_row][b_col] =
            *(const float4*)(Bw + (size_t)(k0 + b_row) * N + n0 + b_col);
        __syncthreads();
        #pragma unroll
        for (int kk = 0; kk < BKK; kk++) {
            float a[8], b[4];
            #pragma unroll
            for (int i = 0; i < 8; i++) a[i] = As[kk][ty * 8 + i];
            #pragma unroll
            for (int j = 0; j < 4; j++) b[j] = Bs[kk][tx * 4 + j];
            #pragma unroll
            for (int i = 0; i < 8; i++)
                #pragma unroll
                for (int j = 0; j < 4; j++) acc[i][j] += a[i] * b[j];
        }
        __syncthreads();
    }
    #pragma unroll
    for (int i = 0; i < 8; i++) {
        const int row = ty * 8 + i;
        if (row < M)
            *(float4*)(C + (size_t)row * N + n0 + tx * 4) =
                make_float4(acc[i][0], acc[i][1], acc[i][2], acc[i][3]);
    }
}

__global__ __launch_bounds__(256)
void ctx_proj_kernel(const float* __restrict__ ctx,
                     const float* __restrict__ Wk,  const float* __restrict__ Wv,
                     const float* __restrict__ Wkip,const float* __restrict__ Wvip,
                     float* __restrict__ Ko, float* __restrict__ Vo,
                     float* __restrict__ Kio, float* __restrict__ Vio)
{
    const int z = blockIdx.z;
    const int which = z >> 4, b = z & 15;
    const float* A = ctx + (size_t)b * CTX * CD + (which >= 2 ? (size_t)TXT * CD : 0);
    const float* W = (which == 0) ? Wk : (which == 1) ? Wv : (which == 2) ? Wkip : Wvip;
    float* C = (which == 0) ? Ko  + (size_t)b * TXT * ID
             : (which == 1) ? Vo  + (size_t)b * TXT * ID
             : (which == 2) ? Kio + (size_t)b * IMG * ID
             :                Vio + (size_t)b * IMG * ID;
    const int M = (which < 2) ? TXT : IMG;
    gemm_body(A, W, C, M, ID, CD, blockIdx.x);
}

// ---------------- attention (fp32, bf16 hi/lo output) ----------------
#define ROWS 128

__global__ __launch_bounds__(ROWS)
void attn_kernel(const float* __restrict__ Q,
                 const float* __restrict__ Kt, const float* __restrict__ Vt,
                 const float* __restrict__ Ki, const float* __restrict__ Vi,
                 __nv_bfloat16* __restrict__ Ah, __nv_bfloat16* __restrict__ Al,
                 const float* __restrict__ ts_p, const float* __restrict__ is_p)
{
    extern __shared__ float sm[];
    float* Ks  = sm;
    float* Vs  = Ks  + TXT * DH;
    float* Kis = Vs  + TXT * DH;
    float* Vis = Kis + IMG * DH;
    float* Sc  = Vis + IMG * DH;           // 93*128

    const int b = blockIdx.z, h = blockIdx.y;
    const int t = threadIdx.x;
    const int row = b * NQ + blockIdx.x * ROWS + t;

    {
        const float4* ksrc = (const float4*)(Kt + ((size_t)b * TXT) * ID + h * DH);
        const float4* vsrc = (const float4*)(Vt + ((size_t)b * TXT) * ID + h * DH);
        for (int i4 = t; i4 < TXT * (DH / 4); i4 += ROWS) {
            const int j = i4 / (DH / 4), d4 = i4 % (DH / 4);
            ((float4*)Ks)[j * (DH / 4) + d4] = ksrc[j * (ID / 4) + d4];
            ((float4*)Vs)[j * (DH / 4) + d4] = vsrc[j * (ID / 4) + d4];
        }
        const float4* kisrc = (const float4*)(Ki + ((size_t)b * IMG) * ID + h * DH);
        const float4* visrc = (const float4*)(Vi + ((size_t)b * IMG) * ID + h * DH);
        for (int i4 = t; i4 < IMG * (DH / 4); i4 += ROWS) {
            const int j = i4 / (DH / 4), d4 = i4 % (DH / 4);
            ((float4*)Kis)[j * (DH / 4) + d4] = kisrc[j * (ID / 4) + d4];
            ((float4*)Vis)[j * (DH / 4) + d4] = visrc[j * (ID / 4) + d4];
        }
    }
    __syncthreads();

    float q[DH];
    {
        const float4* qp = (const float4*)(Q + (size_t)row * ID + h * DH);
        #pragma unroll
        for (int d4 = 0; d4 < DH / 4; d4++) {
            float4 v = qp[d4];
            q[d4 * 4 + 0] = v.x; q[d4 * 4 + 1] = v.y;
            q[d4 * 4 + 2] = v.z; q[d4 * 4 + 3] = v.w;
        }
    }

    for (int j = 0; j < CTX; j++) {
        const float* kbase = (j < TXT) ? (Ks + j * DH) : (Kis + (j - TXT) * DH);
        const float4* kr = (const float4*)kbase;
        float s = 0.f;
        #pragma unroll
        for (int d4 = 0; d4 < DH / 4; d4++) {
            float4 kv = kr[d4];
            s += q[d4 * 4 + 0] * kv.x + q[d4 * 4 + 1] * kv.y
               + q[d4 * 4 + 2] * kv.z + q[d4 * 4 + 3] * kv.w;
        }
        Sc[j * ROWS + t] = s * ATT_SCALE;
    }

    float m_t = -1e30f, m_i = -1e30f;
    for (int j = 0; j < TXT; j++) m_t = fmaxf(m_t, Sc[j * ROWS + t]);
    for (int j = 0; j < IMG; j++) m_i = fmaxf(m_i, Sc[(TXT + j) * ROWS + t]);
    float l_t = 0.f, l_i = 0.f;
    for (int j = 0; j < TXT; j++) {
        float e = __expf(Sc[j * ROWS + t] - m_t);
        l_t += e; Sc[j * ROWS + t] = e;
    }
    for (int j = 0; j < IMG; j++) {
        float e = __expf(Sc[(TXT + j) * ROWS + t] - m_i);
        l_i += e; Sc[(TXT + j) * ROWS + t] = e;
    }

    float acc[DH];
    #pragma unroll
    for (int d = 0; d < DH; d++) acc[d] = 0.f;

    for (int j = 0; j < TXT; j++) {
        const float w = Sc[j * ROWS + t];
        const float4* vr = (const float4*)(Vs + j * DH);
        #pragma unroll
        for (int d4 = 0; d4 < DH / 4; d4++) {
            float4 vv = vr[d4];
            acc[d4 * 4 + 0] += w * vv.x; acc[d4 * 4 + 1] += w * vv.y;
            acc[d4 * 4 + 2] += w * vv.z; acc[d4 * 4 + 3] += w * vv.w;
        }
    }
    const float ct = ts_p[0] / l_t;
    #pragma unroll
    for (int d = 0; d < DH; d++) acc[d] *= ct;

    const float ci = is_p[0] / l_i;
    for (int j = 0; j < IMG; j++) {
        const float w = Sc[(TXT + j) * ROWS + t] * ci;
        const float4* vr = (const float4*)(Vis + j * DH);
        #pragma unroll
        for (int d4 = 0; d4 < DH / 4; d4++) {
            float4 vv = vr[d4];
            acc[d4 * 4 + 0] += w * vv.x; acc[d4 * 4 + 1] += w * vv.y;
            acc[d4 * 4 + 2] += w * vv.z; acc[d4 * 4 + 3] += w * vv.w;
        }
    }

    __nv_bfloat162* oh = (__nv_bfloat162*)(Ah + (size_t)row * ID + h * DH);
    __nv_bfloat162* ol = (__nv_bfloat162*)(Al + (size_t)row * ID + h * DH);
    #pragma unroll
    for (int d2 = 0; d2 < DH / 2; d2++) {
        float a0 = acc[2 * d2], a1 = acc[2 * d2 + 1];
        __nv_bfloat16 h0 = __float2bfloat16(a0);
        __nv_bfloat16 h1 = __float2bfloat16(a1);
        __nv_bfloat16 l0 = __float2bfloat16(a0 - __bfloat162float(h0));
        __nv_bfloat16 l1 = __float2bfloat16(a1 - __bfloat162float(h1));
        oh[d2] = __nv_bfloat162(h0, h1);
        ol[d2] = __nv_bfloat162(l0, l1);
    }
}

// ---------------- launch ----------------
extern "C" void kernel_launch(void* const* d_in, const int* in_sizes, int n_in,
                              void* d_out, int out_size)
{
    const float* x    = (const float*)d_in[0];
    const float* ctx  = (const float*)d_in[1];
    const float* Wq   = (const float*)d_in[2];
    const float* Wk   = (const float*)d_in[3];
    const float* Wv   = (const float*)d_in[4];
    const float* Wkip = (const float*)d_in[5];
    const float* Wvip = (const float*)d_in[6];
    const float* Wo   = (const float*)d_in[7];
    const float* bo   = (const float*)d_in[8];
    const float* ts   = (const float*)d_in[9];
    const float* isc  = (const float*)d_in[10];
    float* out = (float*)d_out;

    float *gQ, *gK, *gV, *gKi, *gVi;
    __nv_bfloat16 *gAh, *gAl, *gxh, *gxl, *gWqh, *gWql, *gWoh, *gWol;
    cudaGetSymbolAddress((void**)&gQ,  g_Q);
    cudaGetSymbolAddress((void**)&gAh, g_Ah);
    cudaGetSymbolAddress((void**)&gAl, g_Al);
    cudaGetSymbolAddress((void**)&gxh, g_xh);
    cudaGetSymbolAddress((void**)&gxl, g_xl);
    cudaGetSymbolAddress((void**)&gWqh, g_Wqh);
    cudaGetSymbolAddress((void**)&gWql, g_Wql);
    cudaGetSymbolAddress((void**)&gWoh, g_Woh);
    cudaGetSymbolAddress((void**)&gWol, g_Wol);
    cudaGetSymbolAddress((void**)&gK,  g_K);
    cudaGetSymbolAddress((void**)&gV,  g_V);
    cudaGetSymbolAddress((void**)&gKi, g_Ki);
    cudaGetSymbolAddress((void**)&gVi, g_Vi);

    const int attn_smem = (TXT * DH * 2 + IMG * DH * 2 + CTX * ROWS) * 4;
    cudaFuncSetAttribute(attn_kernel,
                         cudaFuncAttributeMaxDynamicSharedMemorySize, attn_smem);

    // weight transpose+split (tiny)
    wsplit_t_kernel<<<(QD * ID + 255) / 256, 256>>>(Wq, gWqh, gWql, QD, ID);
    wsplit_t_kernel<<<(ID * QD + 255) / 256, 256>>>(Wo, gWoh, gWol, ID, QD);

    // x split
    split_kernel<<<(MQ * QD / 4 + 255) / 256, 256>>>(x, gxh, gxl, MQ * QD / 4);

    // fused ctx projections (fp32 SIMT)
    {
        dim3 g(ID / BN, 1, 64);
        ctx_proj_kernel<<<g, 256>>>(ctx, Wk, Wv, Wkip, Wvip, gK, gV, gKi, gVi);
    }

    // Q projection (mma.sync bf16-split): [65536,320] x [320,512] -> fp32
    {
        dim3 g(ID / 64, MQ / 128);
        mma_gemm_kernel<<<g, 128>>>(gxh, gxl, gWqh, gWql, gQ, nullptr, MQ, ID, QD);
    }

    // attention
    {
        dim3 g(NQ / ROWS, HEADS, BATCH);
        attn_kernel<<<g, ROWS, attn_smem>>>(gQ, gK, gV, gKi, gVi, gAh, gAl, ts, isc);
    }

    // out projection (mma.sync bf16-split): [65536,512] x [512,320] + bias
    {
        dim3 g(QD / 64, MQ / 128);
        mma_gemm_kernel<<<g, 128>>>(gAh, gAl, gWoh, gWol, out, bo, MQ, QD, ID);
    }
}

// round 4
// speedup vs baseline: 1.4594x; 1.0892x over previous
#include <cuda_runtime.h>
#include <cuda_bf16.h>
#include <cstdint>
#include <cstddef>

// Problem constants
#define BATCH   16
#define NQ      4096
#define QD      320
#define CD      1024
#define CTX     93
#define TXT     77
#define IMG     16
#define HEADS   8
#define DH      64
#define ID      512            // HEADS*DH
#define MQ      (BATCH*NQ)     // 65536
#define ATT_SCALE 0.125f

#define TXT_ROWS (BATCH*TXT)       // 1232
#define TXT_PAD  1280              // padded to 128 multiple
#define IMG_ROWS (BATCH*IMG)       // 256

// ---------------- scratch ----------------
__device__ float g_Q[MQ * ID];
__device__ __nv_bfloat16 g_Ah[MQ * ID];
__device__ __nv_bfloat16 g_Al[MQ * ID];
__device__ __nv_bfloat16 g_xh[MQ * QD];
__device__ __nv_bfloat16 g_xl[MQ * QD];
__device__ __nv_bfloat16 g_Wqh[ID * QD];    // [512][320]
__device__ __nv_bfloat16 g_Wql[ID * QD];
__device__ __nv_bfloat16 g_Woh[QD * ID];    // [320][512]
__device__ __nv_bfloat16 g_Wol[QD * ID];
__device__ __nv_bfloat16 g_Wkh[ID * CD];    // [512][1024]
__device__ __nv_bfloat16 g_Wkl[ID * CD];
__device__ __nv_bfloat16 g_Wvh[ID * CD];
__device__ __nv_bfloat16 g_Wvl[ID * CD];
__device__ __nv_bfloat16 g_Wikh[ID * CD];
__device__ __nv_bfloat16 g_Wikl[ID * CD];
__device__ __nv_bfloat16 g_Wivh[ID * CD];
__device__ __nv_bfloat16 g_Wivl[ID * CD];
__device__ __nv_bfloat16 g_cth[TXT_PAD * CD];   // packed ctx text hi/lo
__device__ __nv_bfloat16 g_ctl[TXT_PAD * CD];
__device__ __nv_bfloat16 g_cih[IMG_ROWS * CD];  // packed ctx img hi/lo
__device__ __nv_bfloat16 g_cil[IMG_ROWS * CD];
__device__ float g_K [TXT_PAD * ID];
__device__ float g_V [TXT_PAD * ID];
__device__ float g_Ki[IMG_ROWS * ID];
__device__ float g_Vi[IMG_ROWS * ID];

// ---------------- helpers ----------------
__device__ __forceinline__ uint32_t smem_u32(const void* p) {
    uint32_t a;
    asm("{ .reg .u64 t; cvta.to.shared.u64 t, %1; cvt.u32.u64 %0, t; }"
        : "=r"(a) : "l"(p));
    return a;
}
__device__ __forceinline__ void cp16(uint32_t dst, const void* src) {
    asm volatile("cp.async.cg.shared.global [%0], [%1], 16;" :: "r"(dst), "l"(src));
}
#define CP_COMMIT() asm volatile("cp.async.commit_group;" ::: "memory")
#define CP_WAIT(n)  asm volatile("cp.async.wait_group %0;" :: "n"(n) : "memory")

__device__ __forceinline__ void mma_bf16(float* c, const uint32_t* a, const uint32_t* b)
{
    asm volatile(
        "mma.sync.aligned.m16n8k16.row.col.f32.bf16.bf16.f32 "
        "{%0,%1,%2,%3}, {%4,%5,%6,%7}, {%8,%9}, {%0,%1,%2,%3};"
        : "+f"(c[0]), "+f"(c[1]), "+f"(c[2]), "+f"(c[3])
        : "r"(a[0]), "r"(a[1]), "r"(a[2]), "r"(a[3]), "r"(b[0]), "r"(b[1]));
}

// ---------------- mma.sync bf16 split GEMM (2-stage cp.async pipeline) ----
// C[M,N] = (Ah+Al)[M,K] @ (Wh+Wl)[N,K]^T (+bias), fp32 out.
// Block 128x64, 4 warps of 64x32. M%128==0, N%64==0, K%32==0.
#define GBK 32
#define SSTR 40   // padded bf16 row stride

#define A_ELEM (128 * SSTR)
#define B_ELEM (64 * SSTR)
#define STAGE_ELEM (2 * A_ELEM + 2 * B_ELEM)
#define GEMM_SMEM (2 * STAGE_ELEM * 2)   // bytes = 61440

__global__ __launch_bounds__(128)
void mma_gemm_kernel(const __nv_bfloat16* __restrict__ Ah,
                     const __nv_bfloat16* __restrict__ Al,
                     const __nv_bfloat16* __restrict__ Wh,
                     const __nv_bfloat16* __restrict__ Wl,
                     float* __restrict__ C, const float* __restrict__ bias,
                     int M, int N, int K)
{
    extern __shared__ __nv_bfloat16 smem[];
    const uint32_t sbase = smem_u32(smem);

    const int tid = threadIdx.x;
    const int wid = tid >> 5;
    const int lid = tid & 31;
    const int grp = lid >> 2;
    const int t4  = lid & 3;
    const int wm  = wid >> 1;
    const int wn  = wid & 1;
    const int m0  = blockIdx.y * 128;
    const int n0  = blockIdx.x * 64;

    float acc[4][4][4];
    #pragma unroll
    for (int m = 0; m < 4; m++)
        #pragma unroll
        for (int n = 0; n < 4; n++)
            #pragma unroll
            for (int j = 0; j < 4; j++) acc[m][n][j] = 0.f;

    const int nch = K / GBK;

    // stage s offsets (elements)
    // sAh = s*STAGE, sAl = +A_ELEM, sBh = +2A, sBl = +2A+B
    auto load_stage = [&](int ch, int s) {
        const int k0 = ch * GBK;
        const uint32_t base = sbase + (uint32_t)s * STAGE_ELEM * 2;
        #pragma unroll
        for (int i = 0; i < 4; i++) {
            const int c = tid + i * 128;
            const int r = c >> 2, cb = (c & 3) * 8;
            const uint32_t so = (uint32_t)(r * SSTR + cb) * 2;
            const size_t g = (size_t)(m0 + r) * K + k0 + cb;
            cp16(base + so, Ah + g);
            cp16(base + A_ELEM * 2 + so, Al + g);
        }
        #pragma unroll
        for (int i = 0; i < 2; i++) {
            const int c = tid + i * 128;
            const int r = c >> 2, cb = (c & 3) * 8;
            const uint32_t so = (uint32_t)(r * SSTR + cb) * 2;
            const size_t g = (size_t)(n0 + r) * K + k0 + cb;
            cp16(base + 2 * A_ELEM * 2 + so, Wh + g);
            cp16(base + (2 * A_ELEM + B_ELEM) * 2 + so, Wl + g);
        }
        CP_COMMIT();
    };

    load_stage(0, 0);
    if (nch > 1) load_stage(1, 1);

    for (int ch = 0; ch < nch; ch++) {
        if (ch + 2 <= nch) { CP_WAIT(1); } else { CP_WAIT(0); }
        __syncthreads();

        const int s = ch & 1;
        const __nv_bfloat16* Ash = smem + s * STAGE_ELEM;
        const __nv_bfloat16* Asl = Ash + A_ELEM;
        const __nv_bfloat16* Bsh = Asl + A_ELEM;
        const __nv_bfloat16* Bsl = Bsh + B_ELEM;

        #pragma unroll
        for (int kk = 0; kk < GBK; kk += 16) {
            uint32_t bh[4][2], bl[4][2];
            #pragma unroll
            for (int n = 0; n < 4; n++) {
                const int br = wn * 32 + n * 8 + grp;
                bh[n][0] = *(const uint32_t*)(Bsh + br * SSTR + kk + t4 * 2);
                bh[n][1] = *(const uint32_t*)(Bsh + br * SSTR + kk + t4 * 2 + 8);
                bl[n][0] = *(const uint32_t*)(Bsl + br * SSTR + kk + t4 * 2);
                bl[n][1] = *(const uint32_t*)(Bsl + br * SSTR + kk + t4 * 2 + 8);
            }
            #pragma unroll
            for (int m = 0; m < 4; m++) {
                const int ar0 = wm * 64 + m * 16 + grp;
                uint32_t ah[4], al[4];
                ah[0] = *(const uint32_t*)(Ash + ar0 * SSTR + kk + t4 * 2);
                ah[1] = *(const uint32_t*)(Ash + (ar0 + 8) * SSTR + kk + t4 * 2);
                ah[2] = *(const uint32_t*)(Ash + ar0 * SSTR + kk + t4 * 2 + 8);
                ah[3] = *(const uint32_t*)(Ash + (ar0 + 8) * SSTR + kk + t4 * 2 + 8);
                al[0] = *(const uint32_t*)(Asl + ar0 * SSTR + kk + t4 * 2);
                al[1] = *(const uint32_t*)(Asl + (ar0 + 8) * SSTR + kk + t4 * 2);
                al[2] = *(const uint32_t*)(Asl + ar0 * SSTR + kk + t4 * 2 + 8);
                al[3] = *(const uint32_t*)(Asl + (ar0 + 8) * SSTR + kk + t4 * 2 + 8);
                #pragma unroll
                for (int n = 0; n < 4; n++) {
                    mma_bf16(acc[m][n], ah, bh[n]);
                    mma_bf16(acc[m][n], ah, bl[n]);
                    mma_bf16(acc[m][n], al, bh[n]);
                }
            }
        }
        __syncthreads();
        if (ch + 2 < nch) load_stage(ch + 2, s);
    }

    // epilogue
    #pragma unroll
    for (int m = 0; m < 4; m++) {
        const int row0 = m0 + wm * 64 + m * 16 + grp;
        #pragma unroll
        for (int n = 0; n < 4; n++) {
            const int col = n0 + wn * 32 + n * 8 + t4 * 2;
            float b0 = 0.f, b1 = 0.f;
            if (bias) { b0 = bias[col]; b1 = bias[col + 1]; }
            *(float2*)(C + (size_t)row0 * N + col) =
                make_float2(acc[m][n][0] + b0, acc[m][n][1] + b1);
            *(float2*)(C + (size_t)(row0 + 8) * N + col) =
                make_float2(acc[m][n][2] + b0, acc[m][n][3] + b1);
        }
    }
}

// ---------------- split / pack prep ----------------
__global__ void split_kernel(const float* __restrict__ X,
                             __nv_bfloat16* __restrict__ H,
                             __nv_bfloat16* __restrict__ L, int n4)
{
    int i = blockIdx.x * blockDim.x + threadIdx.x;
    if (i >= n4) return;
    float4 v = ((const float4*)X)[i];
    float f[4] = {v.x, v.y, v.z, v.w};
    __nv_bfloat16 h[4], l[4];
    #pragma unroll
    for (int j = 0; j < 4; j++) {
        h[j] = __float2bfloat16(f[j]);
        l[j] = __float2bfloat16(f[j] - __bfloat162float(h[j]));
    }
    ((__nv_bfloat162*)H)[2 * i]     = __nv_bfloat162(h[0], h[1]);
    ((__nv_bfloat162*)H)[2 * i + 1] = __nv_bfloat162(h[2], h[3]);
    ((__nv_bfloat162*)L)[2 * i]     = __nv_bfloat162(l[0], l[1]);
    ((__nv_bfloat162*)L)[2 * i + 1] = __nv_bfloat162(l[2], l[3]);
}

// W[K,N] fp32 -> Ht/Lt[N,K] bf16 (transposed split)
__global__ void wsplit_t_kernel(const float* __restrict__ W,
                                __nv_bfloat16* __restrict__ Ht,
                                __nv_bfloat16* __restrict__ Lt, int K, int N)
{
    int idx = blockIdx.x * blockDim.x + threadIdx.x;
    if (idx >= K * N) return;
    int k = idx / N, n = idx % N;
    float v = W[idx];
    __nv_bfloat16 h = __float2bfloat16(v);
    __nv_bfloat16 l = __float2bfloat16(v - __bfloat162float(h));
    Ht[(size_t)n * K + k] = h;
    Lt[(size_t)n * K + k] = l;
}

// pack ctx text rows -> padded [TXT_PAD][CD] bf16 hi/lo (zero pad)
__global__ void pack_txt_kernel(const float* __restrict__ ctx,
                                __nv_bfloat16* __restrict__ H,
                                __nv_bfloat16* __restrict__ L)
{
    int i = blockIdx.x * blockDim.x + threadIdx.x;   // float4 index
    if (i >= TXT_PAD * CD / 4) return;
    int r = i / (CD / 4), c4 = i % (CD / 4);
    float4 v = make_float4(0.f, 0.f, 0.f, 0.f);
    if (r < TXT_ROWS) {
        int b = r / TXT, j = r % TXT;
        v = *(const float4*)(ctx + ((size_t)b * CTX + j) * CD + c4 * 4);
    }
    float f[4] = {v.x, v.y, v.z, v.w};
    __nv_bfloat16 h[4], l[4];
    #pragma unroll
    for (int j = 0; j < 4; j++) {
        h[j] = __float2bfloat16(f[j]);
        l[j] = __float2bfloat16(f[j] - __bfloat162float(h[j]));
    }
    ((__nv_bfloat162*)H)[2 * i]     = __nv_bfloat162(h[0], h[1]);
    ((__nv_bfloat162*)H)[2 * i + 1] = __nv_bfloat162(h[2], h[3]);
    ((__nv_bfloat162*)L)[2 * i]     = __nv_bfloat162(l[0], l[1]);
    ((__nv_bfloat162*)L)[2 * i + 1] = __nv_bfloat162(l[2], l[3]);
}

// pack ctx img rows -> [IMG_ROWS][CD] bf16 hi/lo
__global__ void pack_img_kernel(const float* __restrict__ ctx,
                                __nv_bfloat16* __restrict__ H,
                                __nv_bfloat16* __restrict__ L)
{
    int i = blockIdx.x * blockDim.x + threadIdx.x;
    if (i >= IMG_ROWS * CD / 4) return;
    int r = i / (CD / 4), c4 = i % (CD / 4);
    int b = r / IMG, j = r % IMG;
    float4 v = *(const float4*)(ctx + ((size_t)b * CTX + TXT + j) * CD + c4 * 4);
    float f[4] = {v.x, v.y, v.z, v.w};
    __nv_bfloat16 h[4], l[4];
    #pragma unroll
    for (int jj = 0; jj < 4; jj++) {
        h[jj] = __float2bfloat16(f[jj]);
        l[jj] = __float2bfloat16(f[jj] - __bfloat162float(h[jj]));
    }
    ((__nv_bfloat162*)H)[2 * i]     = __nv_bfloat162(h[0], h[1]);
    ((__nv_bfloat162*)H)[2 * i + 1] = __nv_bfloat162(h[2], h[3]);
    ((__nv_bfloat162*)L)[2 * i]     = __nv_bfloat162(l[0], l[1]);
    ((__nv_bfloat162*)L)[2 * i + 1] = __nv_bfloat162(l[2], l[3]);
}

// ---------------- attention (fp32, bf16 hi/lo output) ----------------
#define ROWS 128

__global__ __launch_bounds__(ROWS)
void attn_kernel(const float* __restrict__ Q,
                 const float* __restrict__ Kt, const float* __restrict__ Vt,
                 const float* __restrict__ Ki, const float* __restrict__ Vi,
                 __nv_bfloat16* __restrict__ Ah, __nv_bfloat16* __restrict__ Al,
                 const float* __restrict__ ts_p, const float* __restrict__ is_p)
{
    extern __shared__ float sm[];
    float* Ks  = sm;
    float* Vs  = Ks  + TXT * DH;
    float* Kis = Vs  + TXT * DH;
    float* Vis = Kis + IMG * DH;
    float* Sc  = Vis + IMG * DH;           // 93*128

    const int b = blockIdx.z, h = blockIdx.y;
    const int t = threadIdx.x;
    const int row = b * NQ + blockIdx.x * ROWS + t;

    {
        const float4* ksrc = (const float4*)(Kt + ((size_t)b * TXT) * ID + h * DH);
        const float4* vsrc = (const float4*)(Vt + ((size_t)b * TXT) * ID + h * DH);
        for (int i4 = t; i4 < TXT * (DH / 4); i4 += ROWS) {
            const int j = i4 / (DH / 4), d4 = i4 % (DH / 4);
            ((float4*)Ks)[j * (DH / 4) + d4] = ksrc[j * (ID / 4) + d4];
            ((float4*)Vs)[j * (DH / 4) + d4] = vsrc[j * (ID / 4) + d4];
        }
        const float4* kisrc = (const float4*)(Ki + ((size_t)b * IMG) * ID + h * DH);
        const float4* visrc = (const float4*)(Vi + ((size_t)b * IMG) * ID + h * DH);
        for (int i4 = t; i4 < IMG * (DH / 4); i4 += ROWS) {
            const int j = i4 / (DH / 4), d4 = i4 % (DH / 4);
            ((float4*)Kis)[j * (DH / 4) + d4] = kisrc[j * (ID / 4) + d4];
            ((float4*)Vis)[j * (DH / 4) + d4] = visrc[j * (ID / 4) + d4];
        }
    }
    __syncthreads();

    float q[DH];
    {
        const float4* qp = (const float4*)(Q + (size_t)row * ID + h * DH);
        #pragma unroll
        for (int d4 = 0; d4 < DH / 4; d4++) {
            float4 v = qp[d4];
            q[d4 * 4 + 0] = v.x; q[d4 * 4 + 1] = v.y;
            q[d4 * 4 + 2] = v.z; q[d4 * 4 + 3] = v.w;
        }
    }

    for (int j = 0; j < CTX; j++) {
        const float* kbase = (j < TXT) ? (Ks + j * DH) : (Kis + (j - TXT) * DH);
        const float4* kr = (const float4*)kbase;
        float s = 0.f;
        #pragma unroll
        for (int d4 = 0; d4 < DH / 4; d4++) {
            float4 kv = kr[d4];
            s += q[d4 * 4 + 0] * kv.x + q[d4 * 4 + 1] * kv.y
               + q[d4 * 4 + 2] * kv.z + q[d4 * 4 + 3] * kv.w;
        }
        Sc[j * ROWS + t] = s * ATT_SCALE;
    }

    float m_t = -1e30f, m_i = -1e30f;
    for (int j = 0; j < TXT; j++) m_t = fmaxf(m_t, Sc[j * ROWS + t]);
    for (int j = 0; j < IMG; j++) m_i = fmaxf(m_i, Sc[(TXT + j) * ROWS + t]);
    float l_t = 0.f, l_i = 0.f;
    for (int j = 0; j < TXT; j++) {
        float e = __expf(Sc[j * ROWS + t] - m_t);
        l_t += e; Sc[j * ROWS + t] = e;
    }
    for (int j = 0; j < IMG; j++) {
        float e = __expf(Sc[(TXT + j) * ROWS + t] - m_i);
        l_i += e; Sc[(TXT + j) * ROWS + t] = e;
    }

    float acc[DH];
    #pragma unroll
    for (int d = 0; d < DH; d++) acc[d] = 0.f;

    for (int j = 0; j < TXT; j++) {
        const float w = Sc[j * ROWS + t];
        const float4* vr = (const float4*)(Vs + j * DH);
        #pragma unroll
        for (int d4 = 0; d4 < DH / 4; d4++) {
            float4 vv = vr[d4];
            acc[d4 * 4 + 0] += w * vv.x; acc[d4 * 4 + 1] += w * vv.y;
            acc[d4 * 4 + 2] += w * vv.z; acc[d4 * 4 + 3] += w * vv.w;
        }
    }
    const float ct = ts_p[0] / l_t;
    #pragma unroll
    for (int d = 0; d < DH; d++) acc[d] *= ct;

    const float ci = is_p[0] / l_i;
    for (int j = 0; j < IMG; j++) {
        const float w = Sc[(TXT + j) * ROWS + t] * ci;
        const float4* vr = (const float4*)(Vis + j * DH);
        #pragma unroll
        for (int d4 = 0; d4 < DH / 4; d4++) {
            float4 vv = vr[d4];
            acc[d4 * 4 + 0] += w * vv.x; acc[d4 * 4 + 1] += w * vv.y;
            acc[d4 * 4 + 2] += w * vv.z; acc[d4 * 4 + 3] += w * vv.w;
        }
    }

    __nv_bfloat162* oh = (__nv_bfloat162*)(Ah + (size_t)row * ID + h * DH);
    __nv_bfloat162* ol = (__nv_bfloat162*)(Al + (size_t)row * ID + h * DH);
    #pragma unroll
    for (int d2 = 0; d2 < DH / 2; d2++) {
        float a0 = acc[2 * d2], a1 = acc[2 * d2 + 1];
        __nv_bfloat16 h0 = __float2bfloat16(a0);
        __nv_bfloat16 h1 = __float2bfloat16(a1);
        __nv_bfloat16 l0 = __float2bfloat16(a0 - __bfloat162float(h0));
        __nv_bfloat16 l1 = __float2bfloat16(a1 - __bfloat162float(h1));
        oh[d2] = __nv_bfloat162(h0, h1);
        ol[d2] = __nv_bfloat162(l0, l1);
    }
}

// ---------------- launch ----------------
extern "C" void kernel_launch(void* const* d_in, const int* in_sizes, int n_in,
                              void* d_out, int out_size)
{
    const float* x    = (const float*)d_in[0];
    const float* ctx  = (const float*)d_in[1];
    const float* Wq   = (const float*)d_in[2];
    const float* Wk   = (const float*)d_in[3];
    const float* Wv   = (const float*)d_in[4];
    const float* Wkip = (const float*)d_in[5];
    const float* Wvip = (const float*)d_in[6];
    const float* Wo   = (const float*)d_in[7];
    const float* bo   = (const float*)d_in[8];
    const float* ts   = (const float*)d_in[9];
    const float* isc  = (const float*)d_in[10];
    float* out = (float*)d_out;

    float *gQ, *gK, *gV, *gKi, *gVi;
    __nv_bfloat16 *gAh, *gAl, *gxh, *gxl, *gWqh, *gWql, *gWoh, *gWol;
    __nv_bfloat16 *gWkh, *gWkl, *gWvh, *gWvl, *gWikh, *gWikl, *gWivh, *gWivl;
    __nv_bfloat16 *gcth, *gctl, *gcih, *gcil;
    cudaGetSymbolAddress((void**)&gQ,  g_Q);
    cudaGetSymbolAddress((void**)&gAh, g_Ah);
    cudaGetSymbolAddress((void**)&gAl, g_Al);
    cudaGetSymbolAddress((void**)&gxh, g_xh);
    cudaGetSymbolAddress((void**)&gxl, g_xl);
    cudaGetSymbolAddress((void**)&gWqh, g_Wqh);
    cudaGetSymbolAddress((void**)&gWql, g_Wql);
    cudaGetSymbolAddress((void**)&gWoh, g_Woh);
    cudaGetSymbolAddress((void**)&gWol, g_Wol);
    cudaGetSymbolAddress((void**)&gWkh, g_Wkh);
    cudaGetSymbolAddress((void**)&gWkl, g_Wkl);
    cudaGetSymbolAddress((void**)&gWvh, g_Wvh);
    cudaGetSymbolAddress((void**)&gWvl, g_Wvl);
    cudaGetSymbolAddress((void**)&gWikh, g_Wikh);
    cudaGetSymbolAddress((void**)&gWikl, g_Wikl);
    cudaGetSymbolAddress((void**)&gWivh, g_Wivh);
    cudaGetSymbolAddress((void**)&gWivl, g_Wivl);
    cudaGetSymbolAddress((void**)&gcth, g_cth);
    cudaGetSymbolAddress((void**)&gctl, g_ctl);
    cudaGetSymbolAddress((void**)&gcih, g_cih);
    cudaGetSymbolAddress((void**)&gcil, g_cil);
    cudaGetSymbolAddress((void**)&gK,  g_K);
    cudaGetSymbolAddress((void**)&gV,  g_V);
    cudaGetSymbolAddress((void**)&gKi, g_Ki);
    cudaGetSymbolAddress((void**)&gVi, g_Vi);

    const int attn_smem = (TXT * DH * 2 + IMG * DH * 2 + CTX * ROWS) * 4;
    cudaFuncSetAttribute(attn_kernel,
                         cudaFuncAttributeMaxDynamicSharedMemorySize, attn_smem);
    cudaFuncSetAttribute(mma_gemm_kernel,
                         cudaFuncAttributeMaxDynamicSharedMemorySize, GEMM_SMEM);

    // weight splits (transposed)
    wsplit_t_kernel<<<(QD * ID + 255) / 256, 256>>>(Wq, gWqh, gWql, QD, ID);
    wsplit_t_kernel<<<(ID * QD + 255) / 256, 256>>>(Wo, gWoh, gWol, ID, QD);
    wsplit_t_kernel<<<(CD * ID + 255) / 256, 256>>>(Wk, gWkh, gWkl, CD, ID);
    wsplit_t_kernel<<<(CD * ID + 255) / 256, 256>>>(Wv, gWvh, gWvl, CD, ID);
    wsplit_t_kernel<<<(CD * ID + 255) / 256, 256>>>(Wkip, gWikh, gWikl, CD, ID);
    wsplit_t_kernel<<<(CD * ID + 255) / 256, 256>>>(Wvip, gWivh, gWivl, CD, ID);

    // ctx pack+split (padded)
    pack_txt_kernel<<<(TXT_PAD * CD / 4 + 255) / 256, 256>>>(ctx, gcth, gctl);
    pack_img_kernel<<<(IMG_ROWS * CD / 4 + 255) / 256, 256>>>(ctx, gcih, gcil);

    // x split
    split_kernel<<<(MQ * QD / 4 + 255) / 256, 256>>>(x, gxh, gxl, MQ * QD / 4);

    // ctx projections via mma (K/V text + img)
    {
        dim3 gt(ID / 64, TXT_PAD / 128);
        mma_gemm_kernel<<<gt, 128, GEMM_SMEM>>>(gcth, gctl, gWkh, gWkl, gK, nullptr,
                                                TXT_PAD, ID, CD);
        mma_gemm_kernel<<<gt, 128, GEMM_SMEM>>>(gcth, gctl, gWvh, gWvl, gV, nullptr,
                                                TXT_PAD, ID, CD);
        dim3 gi(ID / 64, IMG_ROWS / 128);
        mma_gemm_kernel<<<gi, 128, GEMM_SMEM>>>(gcih, gcil, gWikh, gWikl, gKi, nullptr,
                                                IMG_ROWS, ID, CD);
        mma_gemm_kernel<<<gi, 128, GEMM_SMEM>>>(gcih, gcil, gWivh, gWivl, gVi, nullptr,
                                                IMG_ROWS, ID, CD);
    }

    // Q projection
    {
        dim3 g(ID / 64, MQ / 128);
        mma_gemm_kernel<<<g, 128, GEMM_SMEM>>>(gxh, gxl, gWqh, gWql, gQ, nullptr,
                                               MQ, ID, QD);
    }

    // attention
    {
        dim3 g(NQ / ROWS, HEADS, BATCH);
        attn_kernel<<<g, ROWS, attn_smem>>>(gQ, gK, gV, gKi, gVi, gAh, gAl, ts, isc);
    }

    // out projection + bias
    {
        dim3 g(QD / 64, MQ / 128);
        mma_gemm_kernel<<<g, 128, GEMM_SMEM>>>(gAh, gAl, gWoh, gWol, out, bo,
                                               MQ, QD, ID);
    }
}

// round 5
// speedup vs baseline: 1.5567x; 1.0666x over previous
#include <cuda_runtime.h>
#include <cuda_bf16.h>
#include <cstdint>
#include <cstddef>

// Problem constants
#define BATCH   16
#define NQ      4096
#define QD      320
#define CD      1024
#define CTX     93
#define TXT     77
#define IMG     16
#define HEADS   8
#define DH      64
#define ID      512
#define MQ      (BATCH*NQ)
#define ATT_SCALE 0.125f

#define TXT_ROWS (BATCH*TXT)
#define TXT_PAD  1280
#define IMG_ROWS (BATCH*IMG)

typedef __nv_bfloat16 bf16;
typedef __nv_bfloat162 bf162;

// ---------------- scratch ----------------
__device__ bf16 g_Qh[MQ * ID];
__device__ bf16 g_Ql[MQ * ID];
__device__ bf16 g_Ah[MQ * ID];
__device__ bf16 g_Al[MQ * ID];
__device__ bf16 g_xh[MQ * QD];
__device__ bf16 g_xl[MQ * QD];
__device__ bf16 g_Wqh[ID * QD];
__device__ bf16 g_Wql[ID * QD];
__device__ bf16 g_Woh[QD * ID];
__device__ bf16 g_Wol[QD * ID];
__device__ bf16 g_Wc_h[4][ID * CD];   // Wk, Wv, Wkip, Wvip transposed hi
__device__ bf16 g_Wc_l[4][ID * CD];
__device__ bf16 g_cth[TXT_PAD * CD];
__device__ bf16 g_ctl[TXT_PAD * CD];
__device__ bf16 g_cih[IMG_ROWS * CD];
__device__ bf16 g_cil[IMG_ROWS * CD];
__device__ bf16 g_Kh [TXT_PAD * ID];
__device__ bf16 g_Kl [TXT_PAD * ID];
__device__ bf16 g_Vh [TXT_PAD * ID];
__device__ bf16 g_Vl [TXT_PAD * ID];
__device__ bf16 g_Kih[IMG_ROWS * ID];
__device__ bf16 g_Kil[IMG_ROWS * ID];
__device__ bf16 g_Vih[IMG_ROWS * ID];
__device__ bf16 g_Vil[IMG_ROWS * ID];

// ---------------- helpers ----------------
__device__ __forceinline__ uint32_t smem_u32(const void* p) {
    uint32_t a;
    asm("{ .reg .u64 t; cvta.to.shared.u64 t, %1; cvt.u32.u64 %0, t; }"
        : "=r"(a) : "l"(p));
    return a;
}
__device__ __forceinline__ void cp16(uint32_t dst, const void* src) {
    asm volatile("cp.async.cg.shared.global [%0], [%1], 16;" :: "r"(dst), "l"(src));
}
#define CP_COMMIT() asm volatile("cp.async.commit_group;" ::: "memory")
#define CP_WAIT(n)  asm volatile("cp.async.wait_group %0;" :: "n"(n) : "memory")

__device__ __forceinline__ void mma_bf16(float* c, const uint32_t* a, const uint32_t* b)
{
    asm volatile(
        "mma.sync.aligned.m16n8k16.row.col.f32.bf16.bf16.f32 "
        "{%0,%1,%2,%3}, {%4,%5,%6,%7}, {%8,%9}, {%0,%1,%2,%3};"
        : "+f"(c[0]), "+f"(c[1]), "+f"(c[2]), "+f"(c[3])
        : "r"(a[0]), "r"(a[1]), "r"(a[2]), "r"(a[3]), "r"(b[0]), "r"(b[1]));
}
__device__ __forceinline__ uint32_t ldb(const bf16* p) { return *(const uint32_t*)p; }
__device__ __forceinline__ void split_bf16(float v, bf16& h, bf16& l) {
    h = __float2bfloat16(v);
    l = __float2bfloat16(v - __bfloat162float(h));
}

// ---------------- mma.sync bf16 split GEMM (2-stage cp.async) ----------------
// If C != null: fp32 out (+bias). Else: bf16 hi/lo out to Ch/Cl.
#define GBK 32
#define SSTR 40
#define A_ELEM (128 * SSTR)
#define B_ELEM (64 * SSTR)
#define STAGE_ELEM (2 * A_ELEM + 2 * B_ELEM)
#define GEMM_SMEM (2 * STAGE_ELEM * 2)

__global__ __launch_bounds__(128)
void mma_gemm_kernel(const bf16* __restrict__ Ah, const bf16* __restrict__ Al,
                     const bf16* __restrict__ Wh, const bf16* __restrict__ Wl,
                     float* __restrict__ C, bf16* __restrict__ Ch,
                     bf16* __restrict__ Cl, const float* __restrict__ bias,
                     int M, int N, int K)
{
    extern __shared__ bf16 smem[];
    const uint32_t sbase = smem_u32(smem);

    const int tid = threadIdx.x;
    const int wid = tid >> 5;
    const int lid = tid & 31;
    const int grp = lid >> 2;
    const int t4  = lid & 3;
    const int wm  = wid >> 1;
    const int wn  = wid & 1;
    const int m0  = blockIdx.y * 128;
    const int n0  = blockIdx.x * 64;

    float acc[4][4][4];
    #pragma unroll
    for (int m = 0; m < 4; m++)
        #pragma unroll
        for (int n = 0; n < 4; n++)
            #pragma unroll
            for (int j = 0; j < 4; j++) acc[m][n][j] = 0.f;

    const int nch = K / GBK;

    auto load_stage = [&](int ch, int s) {
        const int k0 = ch * GBK;
        const uint32_t base = sbase + (uint32_t)s * STAGE_ELEM * 2;
        #pragma unroll
        for (int i = 0; i < 4; i++) {
            const int c = tid + i * 128;
            const int r = c >> 2, cb = (c & 3) * 8;
            const uint32_t so = (uint32_t)(r * SSTR + cb) * 2;
            const size_t g = (size_t)(m0 + r) * K + k0 + cb;
            cp16(base + so, Ah + g);
            cp16(base + A_ELEM * 2 + so, Al + g);
        }
        #pragma unroll
        for (int i = 0; i < 2; i++) {
            const int c = tid + i * 128;
            const int r = c >> 2, cb = (c & 3) * 8;
            const uint32_t so = (uint32_t)(r * SSTR + cb) * 2;
            const size_t g = (size_t)(n0 + r) * K + k0 + cb;
            cp16(base + 2 * A_ELEM * 2 + so, Wh + g);
            cp16(base + (2 * A_ELEM + B_ELEM) * 2 + so, Wl + g);
        }
        CP_COMMIT();
    };

    load_stage(0, 0);
    if (nch > 1) load_stage(1, 1);

    for (int ch = 0; ch < nch; ch++) {
        if (ch + 2 <= nch) { CP_WAIT(1); } else { CP_WAIT(0); }
        __syncthreads();

        const int s = ch & 1;
        const bf16* Ash = smem + s * STAGE_ELEM;
        const bf16* Asl = Ash + A_ELEM;
        const bf16* Bsh = Asl + A_ELEM;
        const bf16* Bsl = Bsh + B_ELEM;

        #pragma unroll
        for (int kk = 0; kk < GBK; kk += 16) {
            uint32_t bh[4][2], bl[4][2];
            #pragma unroll
            for (int n = 0; n < 4; n++) {
                const int br = wn * 32 + n * 8 + grp;
                bh[n][0] = ldb(Bsh + br * SSTR + kk + t4 * 2);
                bh[n][1] = ldb(Bsh + br * SSTR + kk + t4 * 2 + 8);
                bl[n][0] = ldb(Bsl + br * SSTR + kk + t4 * 2);
                bl[n][1] = ldb(Bsl + br * SSTR + kk + t4 * 2 + 8);
            }
            #pragma unroll
            for (int m = 0; m < 4; m++) {
                const int ar0 = wm * 64 + m * 16 + grp;
                uint32_t ah[4], al[4];
                ah[0] = ldb(Ash + ar0 * SSTR + kk + t4 * 2);
                ah[1] = ldb(Ash + (ar0 + 8) * SSTR + kk + t4 * 2);
                ah[2] = ldb(Ash + ar0 * SSTR + kk + t4 * 2 + 8);
                ah[3] = ldb(Ash + (ar0 + 8) * SSTR + kk + t4 * 2 + 8);
                al[0] = ldb(Asl + ar0 * SSTR + kk + t4 * 2);
                al[1] = ldb(Asl + (ar0 + 8) * SSTR + kk + t4 * 2);
                al[2] = ldb(Asl + ar0 * SSTR + kk + t4 * 2 + 8);
                al[3] = ldb(Asl + (ar0 + 8) * SSTR + kk + t4 * 2 + 8);
                #pragma unroll
                for (int n = 0; n < 4; n++) {
                    mma_bf16(acc[m][n], ah, bh[n]);
                    mma_bf16(acc[m][n], ah, bl[n]);
                    mma_bf16(acc[m][n], al, bh[n]);
                }
            }
        }
        __syncthreads();
        if (ch + 2 < nch) load_stage(ch + 2, s);
    }

    #pragma unroll
    for (int m = 0; m < 4; m++) {
        const int row0 = m0 + wm * 64 + m * 16 + grp;
        #pragma unroll
        for (int n = 0; n < 4; n++) {
            const int col = n0 + wn * 32 + n * 8 + t4 * 2;
            if (C) {
                float b0 = 0.f, b1 = 0.f;
                if (bias) { b0 = bias[col]; b1 = bias[col + 1]; }
                *(float2*)(C + (size_t)row0 * N + col) =
                    make_float2(acc[m][n][0] + b0, acc[m][n][1] + b1);
                *(float2*)(C + (size_t)(row0 + 8) * N + col) =
                    make_float2(acc[m][n][2] + b0, acc[m][n][3] + b1);
            } else {
                bf16 h0, l0, h1, l1;
                split_bf16(acc[m][n][0], h0, l0);
                split_bf16(acc[m][n][1], h1, l1);
                *(bf162*)(Ch + (size_t)row0 * N + col) = bf162(h0, h1);
                *(bf162*)(Cl + (size_t)row0 * N + col) = bf162(l0, l1);
                split_bf16(acc[m][n][2], h0, l0);
                split_bf16(acc[m][n][3], h1, l1);
                *(bf162*)(Ch + (size_t)(row0 + 8) * N + col) = bf162(h0, h1);
                *(bf162*)(Cl + (size_t)(row0 + 8) * N + col) = bf162(l0, l1);
            }
        }
    }
}

// ---------------- prep kernels ----------------
__global__ void split_kernel(const float* __restrict__ X,
                             bf16* __restrict__ H, bf16* __restrict__ L, int n4)
{
    int i = blockIdx.x * blockDim.x + threadIdx.x;
    if (i >= n4) return;
    float4 v = ((const float4*)X)[i];
    float f[4] = {v.x, v.y, v.z, v.w};
    bf16 h[4], l[4];
    #pragma unroll
    for (int j = 0; j < 4; j++) split_bf16(f[j], h[j], l[j]);
    ((bf162*)H)[2 * i]     = bf162(h[0], h[1]);
    ((bf162*)H)[2 * i + 1] = bf162(h[2], h[3]);
    ((bf162*)L)[2 * i]     = bf162(l[0], l[1]);
    ((bf162*)L)[2 * i + 1] = bf162(l[2], l[3]);
}

__global__ void wsplit_t_kernel(const float* __restrict__ W,
                                bf16* __restrict__ Ht, bf16* __restrict__ Lt,
                                int K, int N)
{
    int idx = blockIdx.x * blockDim.x + threadIdx.x;
    if (idx >= K * N) return;
    int k = idx / N, n = idx % N;
    bf16 h, l;
    split_bf16(W[idx], h, l);
    Ht[(size_t)n * K + k] = h;
    Lt[(size_t)n * K + k] = l;
}

// 4 context weights [CD][ID] -> transposed hi/lo, one launch
__global__ void wsplit4_kernel(const float* __restrict__ W0, const float* __restrict__ W1,
                               const float* __restrict__ W2, const float* __restrict__ W3,
                               bf16* __restrict__ Hbase, bf16* __restrict__ Lbase)
{
    int idx = blockIdx.x * blockDim.x + threadIdx.x;
    if (idx >= CD * ID) return;
    const int which = blockIdx.y;
    const float* W = (which == 0) ? W0 : (which == 1) ? W1 : (which == 2) ? W2 : W3;
    int k = idx / ID, n = idx % ID;
    bf16 h, l;
    split_bf16(W[idx], h, l);
    Hbase[(size_t)which * ID * CD + (size_t)n * CD + k] = h;
    Lbase[(size_t)which * ID * CD + (size_t)n * CD + k] = l;
}

__global__ void pack_txt_kernel(const float* __restrict__ ctx,
                                bf16* __restrict__ H, bf16* __restrict__ L)
{
    int i = blockIdx.x * blockDim.x + threadIdx.x;
    if (i >= TXT_PAD * CD / 4) return;
    int r = i / (CD / 4), c4 = i % (CD / 4);
    float4 v = make_float4(0.f, 0.f, 0.f, 0.f);
    if (r < TXT_ROWS) {
        int b = r / TXT, j = r % TXT;
        v = *(const float4*)(ctx + ((size_t)b * CTX + j) * CD + c4 * 4);
    }
    float f[4] = {v.x, v.y, v.z, v.w};
    bf16 h[4], l[4];
    #pragma unroll
    for (int j = 0; j < 4; j++) split_bf16(f[j], h[j], l[j]);
    ((bf162*)H)[2 * i]     = bf162(h[0], h[1]);
    ((bf162*)H)[2 * i + 1] = bf162(h[2], h[3]);
    ((bf162*)L)[2 * i]     = bf162(l[0], l[1]);
    ((bf162*)L)[2 * i + 1] = bf162(l[2], l[3]);
}

__global__ void pack_img_kernel(const float* __restrict__ ctx,
                                bf16* __restrict__ H, bf16* __restrict__ L)
{
    int i = blockIdx.x * blockDim.x + threadIdx.x;
    if (i >= IMG_ROWS * CD / 4) return;
    int r = i / (CD / 4), c4 = i % (CD / 4);
    int b = r / IMG, j = r % IMG;
    float4 v = *(const float4*)(ctx + ((size_t)b * CTX + TXT + j) * CD + c4 * 4);
    float f[4] = {v.x, v.y, v.z, v.w};
    bf16 h[4], l[4];
    #pragma unroll
    for (int jj = 0; jj < 4; jj++) split_bf16(f[jj], h[jj], l[jj]);
    ((bf162*)H)[2 * i]     = bf162(h[0], h[1]);
    ((bf162*)H)[2 * i + 1] = bf162(h[2], h[3]);
    ((bf162*)L)[2 * i]     = bf162(l[0], l[1]);
    ((bf162*)L)[2 * i + 1] = bf162(l[2], l[3]);
}

// ---------------- tensor-core attention ----------------
// Block: (b, h, 128 q rows), 256 threads (8 warps, 16 rows each).
// Keys padded to 96: txt 0..76, zero 77..79, img 80..95.
#define AT_THREADS 256
#define QSTR 72     // bf16 stride for Q/K tiles
#define PSTR 104    // bf16 stride for P / V^T tiles
#define SSTR_F 97   // fp32 stride for scores

#define OFF_QH 0
#define OFF_QL (OFF_QH + 128*QSTR)
#define OFF_KH (OFF_QL + 128*QSTR)
#define OFF_KL (OFF_KH + 96*QSTR)
#define OFF_VH (OFF_KL + 96*QSTR)
#define OFF_VL (OFF_VH + 64*PSTR)
#define OFF_PH (OFF_VL + 64*PSTR)
#define OFF_PL (OFF_PH + 128*PSTR)
#define OFF_S  (OFF_PL + 128*PSTR)
#define ATT_SMEM (OFF_S*2 + 128*SSTR_F*4)

__global__ __launch_bounds__(AT_THREADS)
void attn_mma_kernel(const bf16* __restrict__ Qh, const bf16* __restrict__ Ql,
                     const bf16* __restrict__ Kh, const bf16* __restrict__ Kl,
                     const bf16* __restrict__ Vh, const bf16* __restrict__ Vl,
                     const bf16* __restrict__ Kih, const bf16* __restrict__ Kil,
                     const bf16* __restrict__ Vih, const bf16* __restrict__ Vil,
                     bf16* __restrict__ Ah, bf16* __restrict__ Al,
                     const float* __restrict__ ts_p, const float* __restrict__ is_p)
{
    extern __shared__ bf16 sm[];
    bf16* sQh = sm + OFF_QH;
    bf16* sQl = sm + OFF_QL;
    bf16* sKh = sm + OFF_KH;
    bf16* sKl = sm + OFF_KL;
    bf16* sVh = sm + OFF_VH;   // transposed [d][key]
    bf16* sVl = sm + OFF_VL;
    bf16* sPh = sm + OFF_PH;
    bf16* sPl = sm + OFF_PL;
    float* S  = (float*)(sm + OFF_S);

    const int b = blockIdx.z, h = blockIdx.y;
    const int tid = threadIdx.x;
    const int wid = tid >> 5, lid = tid & 31;
    const int grp = lid >> 2, t4 = lid & 3;
    const size_t qrow0 = (size_t)b * NQ + blockIdx.x * 128;

    // Q tiles: 128 rows x 64 -> 8 uint4 chunks per row
    for (int i = tid; i < 128 * 8; i += AT_THREADS) {
        const int r = i >> 3, c = i & 7;
        const size_t g = (qrow0 + r) * ID + h * DH + c * 8;
        *(uint4*)(sQh + r * QSTR + c * 8) = *(const uint4*)(Qh + g);
        *(uint4*)(sQl + r * QSTR + c * 8) = *(const uint4*)(Ql + g);
    }
    // K tiles: 96 rows (77 txt / 3 zero / 16 img)
    for (int i = tid; i < 96 * 8; i += AT_THREADS) {
        const int r = i >> 3, c = i & 7;
        uint4 vh = make_uint4(0, 0, 0, 0), vl = make_uint4(0, 0, 0, 0);
        if (r < TXT) {
            const size_t g = ((size_t)b * TXT + r) * ID + h * DH + c * 8;
            vh = *(const uint4*)(Kh + g); vl = *(const uint4*)(Kl + g);
        } else if (r >= 80) {
            const size_t g = ((size_t)b * IMG + (r - 80)) * ID + h * DH + c * 8;
            vh = *(const uint4*)(Kih + g); vl = *(const uint4*)(Kil + g);
        }
        *(uint4*)(sKh + r * QSTR + c * 8) = vh;
        *(uint4*)(sKl + r * QSTR + c * 8) = vl;
    }
    // V transposed: [d][key], bf16x2 over d
    for (int i = tid; i < 96 * 32; i += AT_THREADS) {
        const int j = i >> 5, d = (i & 31) * 2;
        bf162 vh = bf162(__float2bfloat16(0.f), __float2bfloat16(0.f));
        bf162 vl = vh;
        if (j < TXT) {
            const size_t g = ((size_t)b * TXT + j) * ID + h * DH + d;
            vh = *(const bf162*)(Vh + g); vl = *(const bf162*)(Vl + g);
        } else if (j >= 80) {
            const size_t g = ((size_t)b * IMG + (j - 80)) * ID + h * DH + d;
            vh = *(const bf162*)(Vih + g); vl = *(const bf162*)(Vil + g);
        }
        sVh[d * PSTR + j] = vh.x; sVh[(d + 1) * PSTR + j] = vh.y;
        sVl[d * PSTR + j] = vl.x; sVl[(d + 1) * PSTR + j] = vl.y;
    }
    __syncthreads();

    // ---- QK^T: warp = 16 rows x 96 keys
    {
        const int m0w = wid * 16;
        float acc[12][4];
        #pragma unroll
        for (int n = 0; n < 12; n++)
            #pragma unroll
            for (int j = 0; j < 4; j++) acc[n][j] = 0.f;

        #pragma unroll
        for (int kk = 0; kk < 64; kk += 16) {
            const bf16* qb = sQh + (m0w + grp) * QSTR + kk + t4 * 2;
            const bf16* ql = sQl + (m0w + grp) * QSTR + kk + t4 * 2;
            uint32_t ah[4], al[4];
            ah[0] = ldb(qb);            ah[1] = ldb(qb + 8 * QSTR);
            ah[2] = ldb(qb + 8);        ah[3] = ldb(qb + 8 * QSTR + 8);
            al[0] = ldb(ql);            al[1] = ldb(ql + 8 * QSTR);
            al[2] = ldb(ql + 8);        al[3] = ldb(ql + 8 * QSTR + 8);
            #pragma unroll
            for (int n = 0; n < 12; n++) {
                const bf16* kb = sKh + (n * 8 + grp) * QSTR + kk + t4 * 2;
                const bf16* kl = sKl + (n * 8 + grp) * QSTR + kk + t4 * 2;
                uint32_t bh[2] = { ldb(kb), ldb(kb + 8) };
                uint32_t bl[2] = { ldb(kl), ldb(kl + 8) };
                mma_bf16(acc[n], ah, bh);
                mma_bf16(acc[n], ah, bl);
                mma_bf16(acc[n], al, bh);
            }
        }
        #pragma unroll
        for (int n = 0; n < 12; n++) {
            const int cb = n * 8 + 2 * t4;
            S[(m0w + grp) * SSTR_F + cb]     = acc[n][0] * ATT_SCALE;
            S[(m0w + grp) * SSTR_F + cb + 1] = acc[n][1] * ATT_SCALE;
            S[(m0w + grp + 8) * SSTR_F + cb]     = acc[n][2] * ATT_SCALE;
            S[(m0w + grp + 8) * SSTR_F + cb + 1] = acc[n][3] * ATT_SCALE;
        }
    }
    __syncthreads();

    // ---- softmax per row (threads 0..127), fold branch scales into P
    if (tid < 128) {
        float* Sr = S + tid * SSTR_F;
        float mt = -1e30f, mi = -1e30f;
        for (int j = 0; j < TXT; j++) mt = fmaxf(mt, Sr[j]);
        for (int j = 80; j < 96; j++) mi = fmaxf(mi, Sr[j]);
        float lt = 0.f, li = 0.f;
        for (int j = 0; j < TXT; j++) { float e = __expf(Sr[j] - mt); lt += e; Sr[j] = e; }
        for (int j = 80; j < 96; j++) { float e = __expf(Sr[j] - mi); li += e; Sr[j] = e; }
        const float ct = ts_p[0] / lt;
        const float ci = is_p[0] / li;
        bf16* ph = sPh + tid * PSTR;
        bf16* pl = sPl + tid * PSTR;
        for (int j = 0; j < 96; j++) {
            float p = (j < TXT) ? Sr[j] * ct : ((j >= 80) ? Sr[j] * ci : 0.f);
            bf16 hh, ll;
            split_bf16(p, hh, ll);
            ph[j] = hh; pl[j] = ll;
        }
    }
    __syncthreads();

    // ---- PV: warp = 16 rows x 64 dims, K = 96
    {
        const int m0w = wid * 16;
        float acc[8][4];
        #pragma unroll
        for (int n = 0; n < 8; n++)
            #pragma unroll
            for (int j = 0; j < 4; j++) acc[n][j] = 0.f;

        #pragma unroll
        for (int kk = 0; kk < 96; kk += 16) {
            const bf16* pb = sPh + (m0w + grp) * PSTR + kk + t4 * 2;
            const bf16* pls = sPl + (m0w + grp) * PSTR + kk + t4 * 2;
            uint32_t ah[4], al[4];
            ah[0] = ldb(pb);            ah[1] = ldb(pb + 8 * PSTR);
            ah[2] = ldb(pb + 8);        ah[3] = ldb(pb + 8 * PSTR + 8);
            al[0] = ldb(pls);           al[1] = ldb(pls + 8 * PSTR);
            al[2] = ldb(pls + 8);       al[3] = ldb(pls + 8 * PSTR + 8);
            #pragma unroll
            for (int n = 0; n < 8; n++) {
                const bf16* vb = sVh + (n * 8 + grp) * PSTR + kk + t4 * 2;
                const bf16* vls = sVl + (n * 8 + grp) * PSTR + kk + t4 * 2;
                uint32_t bh[2] = { ldb(vb), ldb(vb + 8) };
                uint32_t bl[2] = { ldb(vls), ldb(vls + 8) };
                mma_bf16(acc[n], ah, bh);
                mma_bf16(acc[n], ah, bl);
                mma_bf16(acc[n], al, bh);
            }
        }
        // epilogue: write bf16 hi/lo to Ah/Al
        const size_t rg = qrow0 + m0w + grp;
        #pragma unroll
        for (int n = 0; n < 8; n++) {
            const int col = h * DH + n * 8 + 2 * t4;
            bf16 h0, l0, h1, l1;
            split_bf16(acc[n][0], h0, l0);
            split_bf16(acc[n][1], h1, l1);
            *(bf162*)(Ah + rg * ID + col) = bf162(h0, h1);
            *(bf162*)(Al + rg * ID + col) = bf162(l0, l1);
            split_bf16(acc[n][2], h0, l0);
            split_bf16(acc[n][3], h1, l1);
            *(bf162*)(Ah + (rg + 8) * ID + col) = bf162(h0, h1);
            *(bf162*)(Al + (rg + 8) * ID + col) = bf162(l0, l1);
        }
    }
}

// ---------------- launch ----------------
extern "C" void kernel_launch(void* const* d_in, const int* in_sizes, int n_in,
                              void* d_out, int out_size)
{
    const float* x    = (const float*)d_in[0];
    const float* ctx  = (const float*)d_in[1];
    const float* Wq   = (const float*)d_in[2];
    const float* Wk   = (const float*)d_in[3];
    const float* Wv   = (const float*)d_in[4];
    const float* Wkip = (const float*)d_in[5];
    const float* Wvip = (const float*)d_in[6];
    const float* Wo   = (const float*)d_in[7];
    const float* bo   = (const float*)d_in[8];
    const float* ts   = (const float*)d_in[9];
    const float* isc  = (const float*)d_in[10];
    float* out = (float*)d_out;

    bf16 *gQh, *gQl, *gAh, *gAl, *gxh, *gxl, *gWqh, *gWql, *gWoh, *gWol;
    bf16 *gWch, *gWcl, *gcth, *gctl, *gcih, *gcil;
    bf16 *gKh, *gKl, *gVh, *gVl, *gKih, *gKil, *gVih, *gVil;
    cudaGetSymbolAddress((void**)&gQh, g_Qh);
    cudaGetSymbolAddress((void**)&gQl, g_Ql);
    cudaGetSymbolAddress((void**)&gAh, g_Ah);
    cudaGetSymbolAddress((void**)&gAl, g_Al);
    cudaGetSymbolAddress((void**)&gxh, g_xh);
    cudaGetSymbolAddress((void**)&gxl, g_xl);
    cudaGetSymbolAddress((void**)&gWqh, g_Wqh);
    cudaGetSymbolAddress((void**)&gWql, g_Wql);
    cudaGetSymbolAddress((void**)&gWoh, g_Woh);
    cudaGetSymbolAddress((void**)&gWol, g_Wol);
    cudaGetSymbolAddress((void**)&gWch, g_Wc_h);
    cudaGetSymbolAddress((void**)&gWcl, g_Wc_l);
    cudaGetSymbolAddress((void**)&gcth, g_cth);
    cudaGetSymbolAddress((void**)&gctl, g_ctl);
    cudaGetSymbolAddress((void**)&gcih, g_cih);
    cudaGetSymbolAddress((void**)&gcil, g_cil);
    cudaGetSymbolAddress((void**)&gKh, g_Kh);
    cudaGetSymbolAddress((void**)&gKl, g_Kl);
    cudaGetSymbolAddress((void**)&gVh, g_Vh);
    cudaGetSymbolAddress((void**)&gVl, g_Vl);
    cudaGetSymbolAddress((void**)&gKih, g_Kih);
    cudaGetSymbolAddress((void**)&gKil, g_Kil);
    cudaGetSymbolAddress((void**)&gVih, g_Vih);
    cudaGetSymbolAddress((void**)&gVil, g_Vil);

    cudaFuncSetAttribute(mma_gemm_kernel,
                         cudaFuncAttributeMaxDynamicSharedMemorySize, GEMM_SMEM);
    cudaFuncSetAttribute(attn_mma_kernel,
                         cudaFuncAttributeMaxDynamicSharedMemorySize, ATT_SMEM);

    // ---- prep (splits / packs)
    wsplit_t_kernel<<<(QD * ID + 255) / 256, 256>>>(Wq, gWqh, gWql, QD, ID);
    wsplit_t_kernel<<<(ID * QD + 255) / 256, 256>>>(Wo, gWoh, gWol, ID, QD);
    {
        dim3 g((CD * ID + 255) / 256, 4);
        wsplit4_kernel<<<g, 256>>>(Wk, Wv, Wkip, Wvip, gWch, gWcl);
    }
    pack_txt_kernel<<<(TXT_PAD * CD / 4 + 255) / 256, 256>>>(ctx, gcth, gctl);
    pack_img_kernel<<<(IMG_ROWS * CD / 4 + 255) / 256, 256>>>(ctx, gcih, gcil);
    split_kernel<<<(MQ * QD / 4 + 255) / 256, 256>>>(x, gxh, gxl, MQ * QD / 4);

    // ---- ctx projections (bf16 hi/lo outputs)
    {
        dim3 gt(ID / 64, TXT_PAD / 128);
        mma_gemm_kernel<<<gt, 128, GEMM_SMEM>>>(gcth, gctl, gWch + 0 * (size_t)ID * CD,
            gWcl + 0 * (size_t)ID * CD, nullptr, gKh, gKl, nullptr, TXT_PAD, ID, CD);
        mma_gemm_kernel<<<gt, 128, GEMM_SMEM>>>(gcth, gctl, gWch + 1 * (size_t)ID * CD,
            gWcl + 1 * (size_t)ID * CD, nullptr, gVh, gVl, nullptr, TXT_PAD, ID, CD);
        dim3 gi(ID / 64, IMG_ROWS / 128);
        mma_gemm_kernel<<<gi, 128, GEMM_SMEM>>>(gcih, gcil, gWch + 2 * (size_t)ID * CD,
            gWcl + 2 * (size_t)ID * CD, nullptr, gKih, gKil, nullptr, IMG_ROWS, ID, CD);
        mma_gemm_kernel<<<gi, 128, GEMM_SMEM>>>(gcih, gcil, gWch + 3 * (size_t)ID * CD,
            gWcl + 3 * (size_t)ID * CD, nullptr, gVih, gVil, nullptr, IMG_ROWS, ID, CD);
    }

    // ---- Q projection (bf16 hi/lo output)
    {
        dim3 g(ID / 64, MQ / 128);
        mma_gemm_kernel<<<g, 128, GEMM_SMEM>>>(gxh, gxl, gWqh, gWql,
                                               nullptr, gQh, gQl, nullptr, MQ, ID, QD);
    }

    // ---- attention (tensor cores)
    {
        dim3 g(NQ / 128, HEADS, BATCH);
        attn_mma_kernel<<<g, AT_THREADS, ATT_SMEM>>>(gQh, gQl, gKh, gKl, gVh, gVl,
                                                     gKih, gKil, gVih, gVil,
                                                     gAh, gAl, ts, isc);
    }

    // ---- out projection (fp32 + bias)
    {
        dim3 g(QD / 64, MQ / 128);
        mma_gemm_kernel<<<g, 128, GEMM_SMEM>>>(gAh, gAl, gWoh, gWol,
                                               out, nullptr, nullptr, bo, MQ, QD, ID);
    }
}

// round 6
// speedup vs baseline: 1.6462x; 1.0575x over previous
#include <cuda_runtime.h>
#include <cuda_bf16.h>
#include <cstdint>
#include <cstddef>

// Problem constants
#define BATCH   16
#define NQ      4096
#define QD      320
#define CD      1024
#define CTX     93
#define TXT     77
#define IMG     16
#define HEADS   8
#define DH      64
#define ID      512
#define MQ      (BATCH*NQ)
#define ATT_SCALE 0.125f

#define TXT_ROWS (BATCH*TXT)
#define TXT_PAD  1280
#define IMG_ROWS (BATCH*IMG)

typedef __nv_bfloat16 bf16;
typedef __nv_bfloat162 bf162;

// ---------------- scratch ----------------
__device__ bf16 g_Ah[MQ * ID];
__device__ bf16 g_Al[MQ * ID];
__device__ bf16 g_xh[MQ * QD];
__device__ bf16 g_xl[MQ * QD];
__device__ bf16 g_Wqh[ID * QD];    // [512][320] transposed
__device__ bf16 g_Wql[ID * QD];
__device__ bf16 g_Woh[QD * ID];
__device__ bf16 g_Wol[QD * ID];
__device__ bf16 g_Wc_h[4][ID * CD];
__device__ bf16 g_Wc_l[4][ID * CD];
__device__ bf16 g_cth[TXT_PAD * CD];
__device__ bf16 g_ctl[TXT_PAD * CD];
__device__ bf16 g_cih[IMG_ROWS * CD];
__device__ bf16 g_cil[IMG_ROWS * CD];
__device__ bf16 g_Kh [TXT_PAD * ID];
__device__ bf16 g_Kl [TXT_PAD * ID];
__device__ bf16 g_Vh [TXT_PAD * ID];
__device__ bf16 g_Vl [TXT_PAD * ID];
__device__ bf16 g_Kih[IMG_ROWS * ID];
__device__ bf16 g_Kil[IMG_ROWS * ID];
__device__ bf16 g_Vih[IMG_ROWS * ID];
__device__ bf16 g_Vil[IMG_ROWS * ID];

// ---------------- helpers ----------------
__device__ __forceinline__ uint32_t smem_u32(const void* p) {
    uint32_t a;
    asm("{ .reg .u64 t; cvta.to.shared.u64 t, %1; cvt.u32.u64 %0, t; }"
        : "=r"(a) : "l"(p));
    return a;
}
__device__ __forceinline__ void cp16(uint32_t dst, const void* src) {
    asm volatile("cp.async.cg.shared.global [%0], [%1], 16;" :: "r"(dst), "l"(src));
}
#define CP_COMMIT() asm volatile("cp.async.commit_group;" ::: "memory")
#define CP_WAIT(n)  asm volatile("cp.async.wait_group %0;" :: "n"(n) : "memory")

__device__ __forceinline__ void mma_bf16(float* c, const uint32_t* a, const uint32_t* b)
{
    asm volatile(
        "mma.sync.aligned.m16n8k16.row.col.f32.bf16.bf16.f32 "
        "{%0,%1,%2,%3}, {%4,%5,%6,%7}, {%8,%9}, {%0,%1,%2,%3};"
        : "+f"(c[0]), "+f"(c[1]), "+f"(c[2]), "+f"(c[3])
        : "r"(a[0]), "r"(a[1]), "r"(a[2]), "r"(a[3]), "r"(b[0]), "r"(b[1]));
}
__device__ __forceinline__ uint32_t ldb(const bf16* p) { return *(const uint32_t*)p; }
__device__ __forceinline__ void split_bf16(float v, bf16& h, bf16& l) {
    h = __float2bfloat16(v);
    l = __float2bfloat16(v - __bfloat162float(h));
}
__device__ __forceinline__ uint32_t pack_hi(float a, float b) {
    bf162 p(__float2bfloat16(a), __float2bfloat16(b));
    return *(uint32_t*)&p;
}
__device__ __forceinline__ uint32_t pack_lo(float a, float b) {
    bf16 ha = __float2bfloat16(a), hb = __float2bfloat16(b);
    bf162 p(__float2bfloat16(a - __bfloat162float(ha)),
            __float2bfloat16(b - __bfloat162float(hb)));
    return *(uint32_t*)&p;
}

// ---------------- mma.sync bf16 split GEMM (2-stage cp.async) ----------------
#define GBK 32
#define SSTR 40
#define A_ELEM (128 * SSTR)
#define B_ELEM (64 * SSTR)
#define STAGE_ELEM (2 * A_ELEM + 2 * B_ELEM)
#define GEMM_SMEM (2 * STAGE_ELEM * 2)

__global__ __launch_bounds__(128)
void mma_gemm_kernel(const bf16* __restrict__ Ah, const bf16* __restrict__ Al,
                     const bf16* __restrict__ Wh, const bf16* __restrict__ Wl,
                     float* __restrict__ C, bf16* __restrict__ Ch,
                     bf16* __restrict__ Cl, const float* __restrict__ bias,
                     int M, int N, int K)
{
    extern __shared__ bf16 smem[];
    const uint32_t sbase = smem_u32(smem);

    const int tid = threadIdx.x;
    const int wid = tid >> 5;
    const int lid = tid & 31;
    const int grp = lid >> 2;
    const int t4  = lid & 3;
    const int wm  = wid >> 1;
    const int wn  = wid & 1;
    const int m0  = blockIdx.y * 128;
    const int n0  = blockIdx.x * 64;

    float acc[4][4][4];
    #pragma unroll
    for (int m = 0; m < 4; m++)
        #pragma unroll
        for (int n = 0; n < 4; n++)
            #pragma unroll
            for (int j = 0; j < 4; j++) acc[m][n][j] = 0.f;

    const int nch = K / GBK;

    auto load_stage = [&](int ch, int s) {
        const int k0 = ch * GBK;
        const uint32_t base = sbase + (uint32_t)s * STAGE_ELEM * 2;
        #pragma unroll
        for (int i = 0; i < 4; i++) {
            const int c = tid + i * 128;
            const int r = c >> 2, cb = (c & 3) * 8;
            const uint32_t so = (uint32_t)(r * SSTR + cb) * 2;
            const size_t g = (size_t)(m0 + r) * K + k0 + cb;
            cp16(base + so, Ah + g);
            cp16(base + A_ELEM * 2 + so, Al + g);
        }
        #pragma unroll
        for (int i = 0; i < 2; i++) {
            const int c = tid + i * 128;
            const int r = c >> 2, cb = (c & 3) * 8;
            const uint32_t so = (uint32_t)(r * SSTR + cb) * 2;
            const size_t g = (size_t)(n0 + r) * K + k0 + cb;
            cp16(base + 2 * A_ELEM * 2 + so, Wh + g);
            cp16(base + (2 * A_ELEM + B_ELEM) * 2 + so, Wl + g);
        }
        CP_COMMIT();
    };

    load_stage(0, 0);
    if (nch > 1) load_stage(1, 1);

    for (int ch = 0; ch < nch; ch++) {
        if (ch + 2 <= nch) { CP_WAIT(1); } else { CP_WAIT(0); }
        __syncthreads();

        const int s = ch & 1;
        const bf16* Ash = smem + s * STAGE_ELEM;
        const bf16* Asl = Ash + A_ELEM;
        const bf16* Bsh = Asl + A_ELEM;
        const bf16* Bsl = Bsh + B_ELEM;

        #pragma unroll
        for (int kk = 0; kk < GBK; kk += 16) {
            uint32_t bh[4][2], bl[4][2];
            #pragma unroll
            for (int n = 0; n < 4; n++) {
                const int br = wn * 32 + n * 8 + grp;
                bh[n][0] = ldb(Bsh + br * SSTR + kk + t4 * 2);
                bh[n][1] = ldb(Bsh + br * SSTR + kk + t4 * 2 + 8);
                bl[n][0] = ldb(Bsl + br * SSTR + kk + t4 * 2);
                bl[n][1] = ldb(Bsl + br * SSTR + kk + t4 * 2 + 8);
            }
            #pragma unroll
            for (int m = 0; m < 4; m++) {
                const int ar0 = wm * 64 + m * 16 + grp;
                uint32_t ah[4], al[4];
                ah[0] = ldb(Ash + ar0 * SSTR + kk + t4 * 2);
                ah[1] = ldb(Ash + (ar0 + 8) * SSTR + kk + t4 * 2);
                ah[2] = ldb(Ash + ar0 * SSTR + kk + t4 * 2 + 8);
                ah[3] = ldb(Ash + (ar0 + 8) * SSTR + kk + t4 * 2 + 8);
                al[0] = ldb(Asl + ar0 * SSTR + kk + t4 * 2);
                al[1] = ldb(Asl + (ar0 + 8) * SSTR + kk + t4 * 2);
                al[2] = ldb(Asl + ar0 * SSTR + kk + t4 * 2 + 8);
                al[3] = ldb(Asl + (ar0 + 8) * SSTR + kk + t4 * 2 + 8);
                #pragma unroll
                for (int n = 0; n < 4; n++) {
                    mma_bf16(acc[m][n], ah, bh[n]);
                    mma_bf16(acc[m][n], ah, bl[n]);
                    mma_bf16(acc[m][n], al, bh[n]);
                }
            }
        }
        __syncthreads();
        if (ch + 2 < nch) load_stage(ch + 2, s);
    }

    #pragma unroll
    for (int m = 0; m < 4; m++) {
        const int row0 = m0 + wm * 64 + m * 16 + grp;
        #pragma unroll
        for (int n = 0; n < 4; n++) {
            const int col = n0 + wn * 32 + n * 8 + t4 * 2;
            if (C) {
                float b0 = 0.f, b1 = 0.f;
                if (bias) { b0 = bias[col]; b1 = bias[col + 1]; }
                *(float2*)(C + (size_t)row0 * N + col) =
                    make_float2(acc[m][n][0] + b0, acc[m][n][1] + b1);
                *(float2*)(C + (size_t)(row0 + 8) * N + col) =
                    make_float2(acc[m][n][2] + b0, acc[m][n][3] + b1);
            } else {
                bf16 h0, l0, h1, l1;
                split_bf16(acc[m][n][0], h0, l0);
                split_bf16(acc[m][n][1], h1, l1);
                *(bf162*)(Ch + (size_t)row0 * N + col) = bf162(h0, h1);
                *(bf162*)(Cl + (size_t)row0 * N + col) = bf162(l0, l1);
                split_bf16(acc[m][n][2], h0, l0);
                split_bf16(acc[m][n][3], h1, l1);
                *(bf162*)(Ch + (size_t)(row0 + 8) * N + col) = bf162(h0, h1);
                *(bf162*)(Cl + (size_t)(row0 + 8) * N + col) = bf162(l0, l1);
            }
        }
    }
}

// ---------------- prep kernels ----------------
__global__ void split_kernel(const float* __restrict__ X,
                             bf16* __restrict__ H, bf16* __restrict__ L, int n4)
{
    int i = blockIdx.x * blockDim.x + threadIdx.x;
    if (i >= n4) return;
    float4 v = ((const float4*)X)[i];
    float f[4] = {v.x, v.y, v.z, v.w};
    bf16 h[4], l[4];
    #pragma unroll
    for (int j = 0; j < 4; j++) split_bf16(f[j], h[j], l[j]);
    ((bf162*)H)[2 * i]     = bf162(h[0], h[1]);
    ((bf162*)H)[2 * i + 1] = bf162(h[2], h[3]);
    ((bf162*)L)[2 * i]     = bf162(l[0], l[1]);
    ((bf162*)L)[2 * i + 1] = bf162(l[2], l[3]);
}

__global__ void wsplit_t_kernel(const float* __restrict__ W,
                                bf16* __restrict__ Ht, bf16* __restrict__ Lt,
                                int K, int N)
{
    int idx = blockIdx.x * blockDim.x + threadIdx.x;
    if (idx >= K * N) return;
    int k = idx / N, n = idx % N;
    bf16 h, l;
    split_bf16(W[idx], h, l);
    Ht[(size_t)n * K + k] = h;
    Lt[(size_t)n * K + k] = l;
}

__global__ void wsplit4_kernel(const float* __restrict__ W0, const float* __restrict__ W1,
                               const float* __restrict__ W2, const float* __restrict__ W3,
                               bf16* __restrict__ Hbase, bf16* __restrict__ Lbase)
{
    int idx = blockIdx.x * blockDim.x + threadIdx.x;
    if (idx >= CD * ID) return;
    const int which = blockIdx.y;
    const float* W = (which == 0) ? W0 : (which == 1) ? W1 : (which == 2) ? W2 : W3;
    int k = idx / ID, n = idx % ID;
    bf16 h, l;
    split_bf16(W[idx], h, l);
    Hbase[(size_t)which * ID * CD + (size_t)n * CD + k] = h;
    Lbase[(size_t)which * ID * CD + (size_t)n * CD + k] = l;
}

__global__ void pack_txt_kernel(const float* __restrict__ ctx,
                                bf16* __restrict__ H, bf16* __restrict__ L)
{
    int i = blockIdx.x * blockDim.x + threadIdx.x;
    if (i >= TXT_PAD * CD / 4) return;
    int r = i / (CD / 4), c4 = i % (CD / 4);
    float4 v = make_float4(0.f, 0.f, 0.f, 0.f);
    if (r < TXT_ROWS) {
        int b = r / TXT, j = r % TXT;
        v = *(const float4*)(ctx + ((size_t)b * CTX + j) * CD + c4 * 4);
    }
    float f[4] = {v.x, v.y, v.z, v.w};
    bf16 h[4], l[4];
    #pragma unroll
    for (int j = 0; j < 4; j++) split_bf16(f[j], h[j], l[j]);
    ((bf162*)H)[2 * i]     = bf162(h[0], h[1]);
    ((bf162*)H)[2 * i + 1] = bf162(h[2], h[3]);
    ((bf162*)L)[2 * i]     = bf162(l[0], l[1]);
    ((bf162*)L)[2 * i + 1] = bf162(l[2], l[3]);
}

__global__ void pack_img_kernel(const float* __restrict__ ctx,
                                bf16* __restrict__ H, bf16* __restrict__ L)
{
    int i = blockIdx.x * blockDim.x + threadIdx.x;
    if (i >= IMG_ROWS * CD / 4) return;
    int r = i / (CD / 4), c4 = i % (CD / 4);
    int b = r / IMG, j = r % IMG;
    float4 v = *(const float4*)(ctx + ((size_t)b * CTX + TXT + j) * CD + c4 * 4);
    float f[4] = {v.x, v.y, v.z, v.w};
    bf16 h[4], l[4];
    #pragma unroll
    for (int jj = 0; jj < 4; jj++) split_bf16(f[jj], h[jj], l[jj]);
    ((bf162*)H)[2 * i]     = bf162(h[0], h[1]);
    ((bf162*)H)[2 * i + 1] = bf162(h[2], h[3]);
    ((bf162*)L)[2 * i]     = bf162(l[0], l[1]);
    ((bf162*)L)[2 * i + 1] = bf162(l[2], l[3]);
}

// ---------------- fused Q-proj + attention ----------------
// Block: (b, h, 128 q rows), 256 threads (8 warps, 16 rows each).
// Phase 1: Q = x @ Wq[:, h*64:(h+1)*64] via pipelined mma (Q stays in regs).
// Phase 2: QK^T (A-frags direct from Q accumulators), softmax, PV -> Ah/Al.
#define AT_THREADS 256
#define QSTR 72
#define PSTR 104
#define SSTR_F 97
#define XSTR 40

#define F_KH 0
#define F_KL (F_KH + 96*QSTR)
#define F_VH (F_KL + 96*QSTR)
#define F_VL (F_VH + 64*PSTR)
#define F_PH (F_VL + 64*PSTR)
#define F_PL (F_PH + 128*PSTR)
#define F_S  (F_PL + 128*PSTR)
#define F_X  (F_S + 128*SSTR_F*2)          // fp32 area = 2 bf16 el each
#define XSTAGE (128*XSTR)
#define F_W  (F_X + 4*XSTAGE)              // 2 stages x (hi+lo)
#define WSTAGE (64*XSTR)
#define ATT_SMEM ((F_W + 4*WSTAGE) * 2)    // bytes

__global__ __launch_bounds__(AT_THREADS)
void fused_qattn_kernel(const bf16* __restrict__ xh, const bf16* __restrict__ xl,
                        const bf16* __restrict__ Wqh, const bf16* __restrict__ Wql,
                        const bf16* __restrict__ Kh, const bf16* __restrict__ Kl,
                        const bf16* __restrict__ Vh, const bf16* __restrict__ Vl,
                        const bf16* __restrict__ Kih, const bf16* __restrict__ Kil,
                        const bf16* __restrict__ Vih, const bf16* __restrict__ Vil,
                        bf16* __restrict__ Ah, bf16* __restrict__ Al,
                        const float* __restrict__ ts_p, const float* __restrict__ is_p)
{
    extern __shared__ bf16 sm[];
    bf16* sKh = sm + F_KH;
    bf16* sKl = sm + F_KL;
    bf16* sVh = sm + F_VH;   // transposed [d][key]
    bf16* sVl = sm + F_VL;
    bf16* sPh = sm + F_PH;
    bf16* sPl = sm + F_PL;
    float* S  = (float*)(sm + F_S);
    const uint32_t sbase = smem_u32(sm);

    const int b = blockIdx.z, h = blockIdx.y;
    const int tid = threadIdx.x;
    const int wid = tid >> 5, lid = tid & 31;
    const int grp = lid >> 2, t4 = lid & 3;
    const int m0w = wid * 16;
    const size_t qrow0 = (size_t)b * NQ + blockIdx.x * 128;

    // ---- Q-proj pipeline: x[qrow0..+128, :320] @ Wq[h*64..+64, :320]^T
    auto load_stage = [&](int ch, int s) {
        const int k0 = ch * GBK;
        const uint32_t xb = sbase + (F_X + s * 2 * XSTAGE) * 2;
        const uint32_t wb = sbase + (F_W + s * 2 * WSTAGE) * 2;
        #pragma unroll
        for (int i = 0; i < 2; i++) {
            const int c = tid + i * AT_THREADS;
            const int r = c >> 2, cb = (c & 3) * 8;
            const uint32_t so = (uint32_t)(r * XSTR + cb) * 2;
            const size_t g = (qrow0 + r) * QD + k0 + cb;
            cp16(xb + so, xh + g);
            cp16(xb + XSTAGE * 2 + so, xl + g);
        }
        {
            const int c = tid;           // 256 chunks = 64 rows x 4
            const int r = c >> 2, cb = (c & 3) * 8;
            const uint32_t so = (uint32_t)(r * XSTR + cb) * 2;
            const size_t g = (size_t)(h * DH + r) * QD + k0 + cb;
            cp16(wb + so, Wqh + g);
            cp16(wb + WSTAGE * 2 + so, Wql + g);
        }
        CP_COMMIT();
    };

    load_stage(0, 0);
    load_stage(1, 1);

    // ---- stage K/V tiles (overlaps with cp.async in flight)
    for (int i = tid; i < 96 * 8; i += AT_THREADS) {
        const int r = i >> 3, c = i & 7;
        uint4 vh = make_uint4(0, 0, 0, 0), vl = make_uint4(0, 0, 0, 0);
        if (r < TXT) {
            const size_t g = ((size_t)b * TXT + r) * ID + h * DH + c * 8;
            vh = *(const uint4*)(Kh + g); vl = *(const uint4*)(Kl + g);
        } else if (r >= 80) {
            const size_t g = ((size_t)b * IMG + (r - 80)) * ID + h * DH + c * 8;
            vh = *(const uint4*)(Kih + g); vl = *(const uint4*)(Kil + g);
        }
        *(uint4*)(sKh + r * QSTR + c * 8) = vh;
        *(uint4*)(sKl + r * QSTR + c * 8) = vl;
    }
    for (int i = tid; i < 96 * 32; i += AT_THREADS) {
        const int j = i >> 5, d = (i & 31) * 2;
        bf162 vh = bf162(__float2bfloat16(0.f), __float2bfloat16(0.f));
        bf162 vl = vh;
        if (j < TXT) {
            const size_t g = ((size_t)b * TXT + j) * ID + h * DH + d;
            vh = *(const bf162*)(Vh + g); vl = *(const bf162*)(Vl + g);
        } else if (j >= 80) {
            const size_t g = ((size_t)b * IMG + (j - 80)) * ID + h * DH + d;
            vh = *(const bf162*)(Vih + g); vl = *(const bf162*)(Vil + g);
        }
        sVh[d * PSTR + j] = vh.x; sVh[(d + 1) * PSTR + j] = vh.y;
        sVl[d * PSTR + j] = vl.x; sVl[(d + 1) * PSTR + j] = vl.y;
    }

    float qacc[8][4];
    #pragma unroll
    for (int n = 0; n < 8; n++)
        #pragma unroll
        for (int j = 0; j < 4; j++) qacc[n][j] = 0.f;

    const int nch = QD / GBK;   // 10
    for (int ch = 0; ch < nch; ch++) {
        if (ch + 2 <= nch) { CP_WAIT(1); } else { CP_WAIT(0); }
        __syncthreads();

        const int s = ch & 1;
        const bf16* Xsh = sm + F_X + s * 2 * XSTAGE;
        const bf16* Xsl = Xsh + XSTAGE;
        const bf16* Wsh = sm + F_W + s * 2 * WSTAGE;
        const bf16* Wsl = Wsh + WSTAGE;

        #pragma unroll
        for (int kk = 0; kk < GBK; kk += 16) {
            const bf16* xb = Xsh + (m0w + grp) * XSTR + kk + t4 * 2;
            const bf16* xlp = Xsl + (m0w + grp) * XSTR + kk + t4 * 2;
            uint32_t ah[4], al[4];
            ah[0] = ldb(xb);       ah[1] = ldb(xb + 8 * XSTR);
            ah[2] = ldb(xb + 8);   ah[3] = ldb(xb + 8 * XSTR + 8);
            al[0] = ldb(xlp);      al[1] = ldb(xlp + 8 * XSTR);
            al[2] = ldb(xlp + 8);  al[3] = ldb(xlp + 8 * XSTR + 8);
            #pragma unroll
            for (int n = 0; n < 8; n++) {
                const bf16* wb = Wsh + (n * 8 + grp) * XSTR + kk + t4 * 2;
                const bf16* wl = Wsl + (n * 8 + grp) * XSTR + kk + t4 * 2;
                uint32_t bh[2] = { ldb(wb), ldb(wb + 8) };
                uint32_t bl[2] = { ldb(wl), ldb(wl + 8) };
                mma_bf16(qacc[n], ah, bh);
                mma_bf16(qacc[n], ah, bl);
                mma_bf16(qacc[n], al, bh);
            }
        }
        __syncthreads();
        if (ch + 2 < nch) load_stage(ch + 2, s);
    }

    // ---- reshape Q accumulators -> QK^T A-fragments (hi/lo)
    // qacc[n]: rows (m0w+grp, +8), cols n*8 + (2t4, 2t4+1)
    // A-frag i (k-block 16i): {a0,a1,a2,a3} = {(r,k),(r+8,k),(r,k+8),(r+8,k+8)}
    uint32_t qah[4][4], qal[4][4];
    #pragma unroll
    for (int i = 0; i < 4; i++) {
        qah[i][0] = pack_hi(qacc[2*i][0], qacc[2*i][1]);
        qah[i][1] = pack_hi(qacc[2*i][2], qacc[2*i][3]);
        qah[i][2] = pack_hi(qacc[2*i+1][0], qacc[2*i+1][1]);
        qah[i][3] = pack_hi(qacc[2*i+1][2], qacc[2*i+1][3]);
        qal[i][0] = pack_lo(qacc[2*i][0], qacc[2*i][1]);
        qal[i][1] = pack_lo(qacc[2*i][2], qacc[2*i][3]);
        qal[i][2] = pack_lo(qacc[2*i+1][0], qacc[2*i+1][1]);
        qal[i][3] = pack_lo(qacc[2*i+1][2], qacc[2*i+1][3]);
    }

    // ---- QK^T: warp = 16 rows x 96 keys
    {
        float acc[12][4];
        #pragma unroll
        for (int n = 0; n < 12; n++)
            #pragma unroll
            for (int j = 0; j < 4; j++) acc[n][j] = 0.f;

        #pragma unroll
        for (int i = 0; i < 4; i++) {
            const int kk = i * 16;
            #pragma unroll
            for (int n = 0; n < 12; n++) {
                const bf16* kb = sKh + (n * 8 + grp) * QSTR + kk + t4 * 2;
                const bf16* kl = sKl + (n * 8 + grp) * QSTR + kk + t4 * 2;
                uint32_t bh[2] = { ldb(kb), ldb(kb + 8) };
                uint32_t bl[2] = { ldb(kl), ldb(kl + 8) };
                mma_bf16(acc[n], qah[i], bh);
                mma_bf16(acc[n], qah[i], bl);
                mma_bf16(acc[n], qal[i], bh);
            }
        }
        #pragma unroll
        for (int n = 0; n < 12; n++) {
            const int cb = n * 8 + 2 * t4;
            S[(m0w + grp) * SSTR_F + cb]     = acc[n][0] * ATT_SCALE;
            S[(m0w + grp) * SSTR_F + cb + 1] = acc[n][1] * ATT_SCALE;
            S[(m0w + grp + 8) * SSTR_F + cb]     = acc[n][2] * ATT_SCALE;
            S[(m0w + grp + 8) * SSTR_F + cb + 1] = acc[n][3] * ATT_SCALE;
        }
    }
    __syncthreads();

    // ---- softmax per row, fold scales into P
    if (tid < 128) {
        float* Sr = S + tid * SSTR_F;
        float mt = -1e30f, mi = -1e30f;
        for (int j = 0; j < TXT; j++) mt = fmaxf(mt, Sr[j]);
        for (int j = 80; j < 96; j++) mi = fmaxf(mi, Sr[j]);
        float lt = 0.f, li = 0.f;
        for (int j = 0; j < TXT; j++) { float e = __expf(Sr[j] - mt); lt += e; Sr[j] = e; }
        for (int j = 80; j < 96; j++) { float e = __expf(Sr[j] - mi); li += e; Sr[j] = e; }
        const float ct = ts_p[0] / lt;
        const float ci = is_p[0] / li;
        bf16* ph = sPh + tid * PSTR;
        bf16* pl = sPl + tid * PSTR;
        for (int j = 0; j < 96; j++) {
            float p = (j < TXT) ? Sr[j] * ct : ((j >= 80) ? Sr[j] * ci : 0.f);
            bf16 hh, ll;
            split_bf16(p, hh, ll);
            ph[j] = hh; pl[j] = ll;
        }
    }
    __syncthreads();

    // ---- PV: warp = 16 rows x 64 dims, K=96
    {
        float acc[8][4];
        #pragma unroll
        for (int n = 0; n < 8; n++)
            #pragma unroll
            for (int j = 0; j < 4; j++) acc[n][j] = 0.f;

        #pragma unroll
        for (int kk = 0; kk < 96; kk += 16) {
            const bf16* pb = sPh + (m0w + grp) * PSTR + kk + t4 * 2;
            const bf16* pls = sPl + (m0w + grp) * PSTR + kk + t4 * 2;
            uint32_t ah[4], al[4];
            ah[0] = ldb(pb);            ah[1] = ldb(pb + 8 * PSTR);
            ah[2] = ldb(pb + 8);        ah[3] = ldb(pb + 8 * PSTR + 8);
            al[0] = ldb(pls);           al[1] = ldb(pls + 8 * PSTR);
            al[2] = ldb(pls + 8);       al[3] = ldb(pls + 8 * PSTR + 8);
            #pragma unroll
            for (int n = 0; n < 8; n++) {
                const bf16* vb = sVh + (n * 8 + grp) * PSTR + kk + t4 * 2;
                const bf16* vls = sVl + (n * 8 + grp) * PSTR + kk + t4 * 2;
                uint32_t bh[2] = { ldb(vb), ldb(vb + 8) };
                uint32_t bl[2] = { ldb(vls), ldb(vls + 8) };
                mma_bf16(acc[n], ah, bh);
                mma_bf16(acc[n], ah, bl);
                mma_bf16(acc[n], al, bh);
            }
        }
        const size_t rg = qrow0 + m0w + grp;
        #pragma unroll
        for (int n = 0; n < 8; n++) {
            const int col = h * DH + n * 8 + 2 * t4;
            bf16 h0, l0, h1, l1;
            split_bf16(acc[n][0], h0, l0);
            split_bf16(acc[n][1], h1, l1);
            *(bf162*)(Ah + rg * ID + col) = bf162(h0, h1);
            *(bf162*)(Al + rg * ID + col) = bf162(l0, l1);
            split_bf16(acc[n][2], h0, l0);
            split_bf16(acc[n][3], h1, l1);
            *(bf162*)(Ah + (rg + 8) * ID + col) = bf162(h0, h1);
            *(bf162*)(Al + (rg + 8) * ID + col) = bf162(l0, l1);
        }
    }
}

// ---------------- launch ----------------
extern "C" void kernel_launch(void* const* d_in, const int* in_sizes, int n_in,
                              void* d_out, int out_size)
{
    const float* x    = (const float*)d_in[0];
    const float* ctx  = (const float*)d_in[1];
    const float* Wq   = (const float*)d_in[2];
    const float* Wk   = (const float*)d_in[3];
    const float* Wv   = (const float*)d_in[4];
    const float* Wkip = (const float*)d_in[5];
    const float* Wvip = (const float*)d_in[6];
    const float* Wo   = (const float*)d_in[7];
    const float* bo   = (const float*)d_in[8];
    const float* ts   = (const float*)d_in[9];
    const float* isc  = (const float*)d_in[10];
    float* out = (float*)d_out;

    bf16 *gAh, *gAl, *gxh, *gxl, *gWqh, *gWql, *gWoh, *gWol;
    bf16 *gWch, *gWcl, *gcth, *gctl, *gcih, *gcil;
    bf16 *gKh, *gKl, *gVh, *gVl, *gKih, *gKil, *gVih, *gVil;
    cudaGetSymbolAddress((void**)&gAh, g_Ah);
    cudaGetSymbolAddress((void**)&gAl, g_Al);
    cudaGetSymbolAddress((void**)&gxh, g_xh);
    cudaGetSymbolAddress((void**)&gxl, g_xl);
    cudaGetSymbolAddress((void**)&gWqh, g_Wqh);
    cudaGetSymbolAddress((void**)&gWql, g_Wql);
    cudaGetSymbolAddress((void**)&gWoh, g_Woh);
    cudaGetSymbolAddress((void**)&gWol, g_Wol);
    cudaGetSymbolAddress((void**)&gWch, g_Wc_h);
    cudaGetSymbolAddress((void**)&gWcl, g_Wc_l);
    cudaGetSymbolAddress((void**)&gcth, g_cth);
    cudaGetSymbolAddress((void**)&gctl, g_ctl);
    cudaGetSymbolAddress((void**)&gcih, g_cih);
    cudaGetSymbolAddress((void**)&gcil, g_cil);
    cudaGetSymbolAddress((void**)&gKh, g_Kh);
    cudaGetSymbolAddress((void**)&gKl, g_Kl);
    cudaGetSymbolAddress((void**)&gVh, g_Vh);
    cudaGetSymbolAddress((void**)&gVl, g_Vl);
    cudaGetSymbolAddress((void**)&gKih, g_Kih);
    cudaGetSymbolAddress((void**)&gKil, g_Kil);
    cudaGetSymbolAddress((void**)&gVih, g_Vih);
    cudaGetSymbolAddress((void**)&gVil, g_Vil);

    cudaFuncSetAttribute(mma_gemm_kernel,
                         cudaFuncAttributeMaxDynamicSharedMemorySize, GEMM_SMEM);
    cudaFuncSetAttribute(fused_qattn_kernel,
                         cudaFuncAttributeMaxDynamicSharedMemorySize, ATT_SMEM);

    // ---- prep
    wsplit_t_kernel<<<(QD * ID + 255) / 256, 256>>>(Wq, gWqh, gWql, QD, ID);
    wsplit_t_kernel<<<(ID * QD + 255) / 256, 256>>>(Wo, gWoh, gWol, ID, QD);
    {
        dim3 g((CD * ID + 255) / 256, 4);
        wsplit4_kernel<<<g, 256>>>(Wk, Wv, Wkip, Wvip, gWch, gWcl);
    }
    pack_txt_kernel<<<(TXT_PAD * CD / 4 + 255) / 256, 256>>>(ctx, gcth, gctl);
    pack_img_kernel<<<(IMG_ROWS * CD / 4 + 255) / 256, 256>>>(ctx, gcih, gcil);
    split_kernel<<<(MQ * QD / 4 + 255) / 256, 256>>>(x, gxh, gxl, MQ * QD / 4);

    // ---- ctx projections
    {
        dim3 gt(ID / 64, TXT_PAD / 128);
        mma_gemm_kernel<<<gt, 128, GEMM_SMEM>>>(gcth, gctl, gWch + 0 * (size_t)ID * CD,
            gWcl + 0 * (size_t)ID * CD, nullptr, gKh, gKl, nullptr, TXT_PAD, ID, CD);
        mma_gemm_kernel<<<gt, 128, GEMM_SMEM>>>(gcth, gctl, gWch + 1 * (size_t)ID * CD,
            gWcl + 1 * (size_t)ID * CD, nullptr, gVh, gVl, nullptr, TXT_PAD, ID, CD);
        dim3 gi(ID / 64, IMG_ROWS / 128);
        mma_gemm_kernel<<<gi, 128, GEMM_SMEM>>>(gcih, gcil, gWch + 2 * (size_t)ID * CD,
            gWcl + 2 * (size_t)ID * CD, nullptr, gKih, gKil, nullptr, IMG_ROWS, ID, CD);
        mma_gemm_kernel<<<gi, 128, GEMM_SMEM>>>(gcih, gcil, gWch + 3 * (size_t)ID * CD,
            gWcl + 3 * (size_t)ID * CD, nullptr, gVih, gVil, nullptr, IMG_ROWS, ID, CD);
    }

    // ---- fused Q-proj + attention
    {
        dim3 g(NQ / 128, HEADS, BATCH);
        fused_qattn_kernel<<<g, AT_THREADS, ATT_SMEM>>>(gxh, gxl, gWqh, gWql,
                                                        gKh, gKl, gVh, gVl,
                                                        gKih, gKil, gVih, gVil,
                                                        gAh, gAl, ts, isc);
    }

    // ---- out projection (fp32 + bias)
    {
        dim3 g(QD / 64, MQ / 128);
        mma_gemm_kernel<<<g, 128, GEMM_SMEM>>>(gAh, gAl, gWoh, gWol,
                                               out, nullptr, nullptr, bo, MQ, QD, ID);
    }
}

// round 7
// speedup vs baseline: 2.0867x; 1.2676x over previous
#include <cuda_runtime.h>
#include <cuda_fp16.h>
#include <cstdint>
#include <cstddef>

// Problem constants
#define BATCH   16
#define NQ      4096
#define QD      320
#define CD      1024
#define CTX     93
#define TXT     77
#define IMG     16
#define HEADS   8
#define DH      64
#define ID      512
#define MQ      (BATCH*NQ)
#define ATT_SCALE 0.125f

#define TXT_ROWS (BATCH*TXT)
#define TXT_PAD  1280
#define IMG_ROWS (BATCH*IMG)

typedef __half fp16;

// ---------------- scratch ----------------
__device__ fp16 g_Ah[MQ * ID];          // attention out hi (A-operand of out-proj)
__device__ fp16 g_Al[MQ * ID];
__device__ fp16 g_xh[MQ * QD];
__device__ fp16 g_xl[MQ * QD];
__device__ fp16 g_Wq [ID * QD];         // [512][320] transposed, single fp16
__device__ fp16 g_Wo [QD * ID];
__device__ fp16 g_Wc [4][ID * CD];      // Wk, Wv, Wkip, Wvip transposed
__device__ fp16 g_cth[TXT_PAD * CD];    // ctx packed hi/lo (A-operand)
__device__ fp16 g_ctl[TXT_PAD * CD];
__device__ fp16 g_cih[IMG_ROWS * CD];
__device__ fp16 g_cil[IMG_ROWS * CD];
__device__ fp16 g_K  [TXT_PAD * ID];    // single fp16 (B-operands)
__device__ fp16 g_V  [TXT_PAD * ID];
__device__ fp16 g_Ki [IMG_ROWS * ID];
__device__ fp16 g_Vi [IMG_ROWS * ID];

// ---------------- helpers ----------------
__device__ __forceinline__ uint32_t smem_u32(const void* p) {
    uint32_t a;
    asm("{ .reg .u64 t; cvta.to.shared.u64 t, %1; cvt.u32.u64 %0, t; }"
        : "=r"(a) : "l"(p));
    return a;
}
__device__ __forceinline__ void cp16(uint32_t dst, const void* src) {
    asm volatile("cp.async.cg.shared.global [%0], [%1], 16;" :: "r"(dst), "l"(src));
}
#define CP_COMMIT() asm volatile("cp.async.commit_group;" ::: "memory")
#define CP_WAIT(n)  asm volatile("cp.async.wait_group %0;" :: "n"(n) : "memory")

__device__ __forceinline__ void mma_f16(float* c, const uint32_t* a, const uint32_t* b)
{
    asm volatile(
        "mma.sync.aligned.m16n8k16.row.col.f32.f16.f16.f32 "
        "{%0,%1,%2,%3}, {%4,%5,%6,%7}, {%8,%9}, {%0,%1,%2,%3};"
        : "+f"(c[0]), "+f"(c[1]), "+f"(c[2]), "+f"(c[3])
        : "r"(a[0]), "r"(a[1]), "r"(a[2]), "r"(a[3]), "r"(b[0]), "r"(b[1]));
}
__device__ __forceinline__ uint32_t ldb(const fp16* p) { return *(const uint32_t*)p; }
__device__ __forceinline__ void split_f16(float v, fp16& h, fp16& l) {
    h = __float2half_rn(v);
    l = __float2half_rn(v - __half2float(h));
}
__device__ __forceinline__ uint32_t pack2(fp16 a, fp16 b) {
    __half2 p = __halves2half2(a, b);
    return *(uint32_t*)&p;
}
__device__ __forceinline__ uint32_t pack_hi(float a, float b) {
    __half2 p = __floats2half2_rn(a, b);
    return *(uint32_t*)&p;
}
__device__ __forceinline__ uint32_t pack_lo(float a, float b) {
    fp16 ha = __float2half_rn(a), hb = __float2half_rn(b);
    __half2 p = __halves2half2(__float2half_rn(a - __half2float(ha)),
                               __float2half_rn(b - __half2float(hb)));
    return *(uint32_t*)&p;
}

// ---------------- fp16 split-2 GEMM (2-stage cp.async) ----------------
// C[M,N] = (Ah+Al)[M,K] @ W[N,K]^T. Epilogue: fp32 (+bias) | fp16 hi/lo | fp16.
#define GBK 32
#define SSTR 40
#define A_ELEM (128 * SSTR)
#define B_ELEM (64 * SSTR)
#define STAGE_ELEM (2 * A_ELEM + B_ELEM)
#define GEMM_SMEM (2 * STAGE_ELEM * 2)

__global__ __launch_bounds__(128)
void mma_gemm_kernel(const fp16* __restrict__ Ah, const fp16* __restrict__ Al,
                     const fp16* __restrict__ W,
                     float* __restrict__ C, fp16* __restrict__ Ch,
                     fp16* __restrict__ Cl, const float* __restrict__ bias,
                     int M, int N, int K)
{
    extern __shared__ fp16 smem[];
    const uint32_t sbase = smem_u32(smem);

    const int tid = threadIdx.x;
    const int wid = tid >> 5;
    const int lid = tid & 31;
    const int grp = lid >> 2;
    const int t4  = lid & 3;
    const int wm  = wid >> 1;
    const int wn  = wid & 1;
    const int m0  = blockIdx.y * 128;
    const int n0  = blockIdx.x * 64;

    float acc[4][4][4];
    #pragma unroll
    for (int m = 0; m < 4; m++)
        #pragma unroll
        for (int n = 0; n < 4; n++)
            #pragma unroll
            for (int j = 0; j < 4; j++) acc[m][n][j] = 0.f;

    const int nch = K / GBK;

    auto load_stage = [&](int ch, int s) {
        const int k0 = ch * GBK;
        const uint32_t base = sbase + (uint32_t)s * STAGE_ELEM * 2;
        #pragma unroll
        for (int i = 0; i < 4; i++) {
            const int c = tid + i * 128;
            const int r = c >> 2, cb = (c & 3) * 8;
            const uint32_t so = (uint32_t)(r * SSTR + cb) * 2;
            const size_t g = (size_t)(m0 + r) * K + k0 + cb;
            cp16(base + so, Ah + g);
            cp16(base + A_ELEM * 2 + so, Al + g);
        }
        #pragma unroll
        for (int i = 0; i < 2; i++) {
            const int c = tid + i * 128;
            const int r = c >> 2, cb = (c & 3) * 8;
            const uint32_t so = (uint32_t)(r * SSTR + cb) * 2;
            const size_t g = (size_t)(n0 + r) * K + k0 + cb;
            cp16(base + 2 * A_ELEM * 2 + so, W + g);
        }
        CP_COMMIT();
    };

    load_stage(0, 0);
    if (nch > 1) load_stage(1, 1);

    for (int ch = 0; ch < nch; ch++) {
        if (ch + 2 <= nch) { CP_WAIT(1); } else { CP_WAIT(0); }
        __syncthreads();

        const int s = ch & 1;
        const fp16* Ash = smem + s * STAGE_ELEM;
        const fp16* Asl = Ash + A_ELEM;
        const fp16* Bs  = Asl + A_ELEM;

        #pragma unroll
        for (int kk = 0; kk < GBK; kk += 16) {
            uint32_t bh[4][2];
            #pragma unroll
            for (int n = 0; n < 4; n++) {
                const int br = wn * 32 + n * 8 + grp;
                bh[n][0] = ldb(Bs + br * SSTR + kk + t4 * 2);
                bh[n][1] = ldb(Bs + br * SSTR + kk + t4 * 2 + 8);
            }
            #pragma unroll
            for (int m = 0; m < 4; m++) {
                const int ar0 = wm * 64 + m * 16 + grp;
                uint32_t ah[4], al[4];
                ah[0] = ldb(Ash + ar0 * SSTR + kk + t4 * 2);
                ah[1] = ldb(Ash + (ar0 + 8) * SSTR + kk + t4 * 2);
                ah[2] = ldb(Ash + ar0 * SSTR + kk + t4 * 2 + 8);
                ah[3] = ldb(Ash + (ar0 + 8) * SSTR + kk + t4 * 2 + 8);
                al[0] = ldb(Asl + ar0 * SSTR + kk + t4 * 2);
                al[1] = ldb(Asl + (ar0 + 8) * SSTR + kk + t4 * 2);
                al[2] = ldb(Asl + ar0 * SSTR + kk + t4 * 2 + 8);
                al[3] = ldb(Asl + (ar0 + 8) * SSTR + kk + t4 * 2 + 8);
                #pragma unroll
                for (int n = 0; n < 4; n++) {
                    mma_f16(acc[m][n], ah, bh[n]);
                    mma_f16(acc[m][n], al, bh[n]);
                }
            }
        }
        __syncthreads();
        if (ch + 2 < nch) load_stage(ch + 2, s);
    }

    #pragma unroll
    for (int m = 0; m < 4; m++) {
        const int row0 = m0 + wm * 64 + m * 16 + grp;
        #pragma unroll
        for (int n = 0; n < 4; n++) {
            const int col = n0 + wn * 32 + n * 8 + t4 * 2;
            if (C) {
                float b0 = 0.f, b1 = 0.f;
                if (bias) { b0 = bias[col]; b1 = bias[col + 1]; }
                *(float2*)(C + (size_t)row0 * N + col) =
                    make_float2(acc[m][n][0] + b0, acc[m][n][1] + b1);
                *(float2*)(C + (size_t)(row0 + 8) * N + col) =
                    make_float2(acc[m][n][2] + b0, acc[m][n][3] + b1);
            } else if (Cl) {
                *(uint32_t*)(Ch + (size_t)row0 * N + col) = pack_hi(acc[m][n][0], acc[m][n][1]);
                *(uint32_t*)(Cl + (size_t)row0 * N + col) = pack_lo(acc[m][n][0], acc[m][n][1]);
                *(uint32_t*)(Ch + (size_t)(row0 + 8) * N + col) = pack_hi(acc[m][n][2], acc[m][n][3]);
                *(uint32_t*)(Cl + (size_t)(row0 + 8) * N + col) = pack_lo(acc[m][n][2], acc[m][n][3]);
            } else {
                *(uint32_t*)(Ch + (size_t)row0 * N + col) = pack_hi(acc[m][n][0], acc[m][n][1]);
                *(uint32_t*)(Ch + (size_t)(row0 + 8) * N + col) = pack_hi(acc[m][n][2], acc[m][n][3]);
            }
        }
    }
}

// ---------------- prep kernels ----------------
__global__ void split_kernel(const float* __restrict__ X,
                             fp16* __restrict__ H, fp16* __restrict__ L, int n4)
{
    int i = blockIdx.x * blockDim.x + threadIdx.x;
    if (i >= n4) return;
    float4 v = ((const float4*)X)[i];
    float f[4] = {v.x, v.y, v.z, v.w};
    fp16 h[4], l[4];
    #pragma unroll
    for (int j = 0; j < 4; j++) split_f16(f[j], h[j], l[j]);
    ((uint32_t*)H)[2 * i]     = pack2(h[0], h[1]);
    ((uint32_t*)H)[2 * i + 1] = pack2(h[2], h[3]);
    ((uint32_t*)L)[2 * i]     = pack2(l[0], l[1]);
    ((uint32_t*)L)[2 * i + 1] = pack2(l[2], l[3]);
}

__global__ void wsplit_t_kernel(const float* __restrict__ W,
                                fp16* __restrict__ Wt, int K, int N)
{
    int idx = blockIdx.x * blockDim.x + threadIdx.x;
    if (idx >= K * N) return;
    int k = idx / N, n = idx % N;
    Wt[(size_t)n * K + k] = __float2half_rn(W[idx]);
}

__global__ void wsplit4_kernel(const float* __restrict__ W0, const float* __restrict__ W1,
                               const float* __restrict__ W2, const float* __restrict__ W3,
                               fp16* __restrict__ Wt)
{
    int idx = blockIdx.x * blockDim.x + threadIdx.x;
    if (idx >= CD * ID) return;
    const int which = blockIdx.y;
    const float* W = (which == 0) ? W0 : (which == 1) ? W1 : (which == 2) ? W2 : W3;
    int k = idx / ID, n = idx % ID;
    Wt[(size_t)which * ID * CD + (size_t)n * CD + k] = __float2half_rn(W[idx]);
}

__global__ void pack_txt_kernel(const float* __restrict__ ctx,
                                fp16* __restrict__ H, fp16* __restrict__ L)
{
    int i = blockIdx.x * blockDim.x + threadIdx.x;
    if (i >= TXT_PAD * CD / 4) return;
    int r = i / (CD / 4), c4 = i % (CD / 4);
    float4 v = make_float4(0.f, 0.f, 0.f, 0.f);
    if (r < TXT_ROWS) {
        int b = r / TXT, j = r % TXT;
        v = *(const float4*)(ctx + ((size_t)b * CTX + j) * CD + c4 * 4);
    }
    float f[4] = {v.x, v.y, v.z, v.w};
    fp16 h[4], l[4];
    #pragma unroll
    for (int j = 0; j < 4; j++) split_f16(f[j], h[j], l[j]);
    ((uint32_t*)H)[2 * i]     = pack2(h[0], h[1]);
    ((uint32_t*)H)[2 * i + 1] = pack2(h[2], h[3]);
    ((uint32_t*)L)[2 * i]     = pack2(l[0], l[1]);
    ((uint32_t*)L)[2 * i + 1] = pack2(l[2], l[3]);
}

__global__ void pack_img_kernel(const float* __restrict__ ctx,
                                fp16* __restrict__ H, fp16* __restrict__ L)
{
    int i = blockIdx.x * blockDim.x + threadIdx.x;
    if (i >= IMG_ROWS * CD / 4) return;
    int r = i / (CD / 4), c4 = i % (CD / 4);
    int b = r / IMG, j = r % IMG;
    float4 v = *(const float4*)(ctx + ((size_t)b * CTX + TXT + j) * CD + c4 * 4);
    float f[4] = {v.x, v.y, v.z, v.w};
    fp16 h[4], l[4];
    #pragma unroll
    for (int jj = 0; jj < 4; jj++) split_f16(f[jj], h[jj], l[jj]);
    ((uint32_t*)H)[2 * i]     = pack2(h[0], h[1]);
    ((uint32_t*)H)[2 * i + 1] = pack2(h[2], h[3]);
    ((uint32_t*)L)[2 * i]     = pack2(l[0], l[1]);
    ((uint32_t*)L)[2 * i + 1] = pack2(l[2], l[3]);
}

// ---------------- fused Q-proj + attention ----------------
#define AT_THREADS 256
#define QSTR 72
#define PSTR 104
#define SSTR_F 97
#define XSTR 40

#define F_K  0
#define F_V  (F_K + 96*QSTR)
#define F_PH (F_V + 64*PSTR)
#define F_PL (F_PH + 128*PSTR)
#define F_S  (F_PL + 128*PSTR)
#define F_X  (F_S + 128*SSTR_F*2)
#define XSTAGE (128*XSTR)
#define F_W  (F_X + 4*XSTAGE)
#define WSTAGE (64*XSTR)
#define ATT_SMEM ((F_W + 2*WSTAGE) * 2)

__global__ __launch_bounds__(AT_THREADS)
void fused_qattn_kernel(const fp16* __restrict__ xh, const fp16* __restrict__ xl,
                        const fp16* __restrict__ Wq,
                        const fp16* __restrict__ K, const fp16* __restrict__ V,
                        const fp16* __restrict__ Ki, const fp16* __restrict__ Vi,
                        fp16* __restrict__ Ah, fp16* __restrict__ Al,
                        const float* __restrict__ ts_p, const float* __restrict__ is_p)
{
    extern __shared__ fp16 sm[];
    fp16* sK  = sm + F_K;
    fp16* sV  = sm + F_V;   // transposed [d][key]
    fp16* sPh = sm + F_PH;
    fp16* sPl = sm + F_PL;
    float* S  = (float*)(sm + F_S);
    const uint32_t sbase = smem_u32(sm);

    const int b = blockIdx.z, h = blockIdx.y;
    const int tid = threadIdx.x;
    const int wid = tid >> 5, lid = tid & 31;
    const int grp = lid >> 2, t4 = lid & 3;
    const int m0w = wid * 16;
    const size_t qrow0 = (size_t)b * NQ + blockIdx.x * 128;

    auto load_stage = [&](int ch, int s) {
        const int k0 = ch * GBK;
        const uint32_t xb = sbase + (F_X + s * 2 * XSTAGE) * 2;
        const uint32_t wb = sbase + (F_W + s * WSTAGE) * 2;
        #pragma unroll
        for (int i = 0; i < 2; i++) {
            const int c = tid + i * AT_THREADS;
            const int r = c >> 2, cb = (c & 3) * 8;
            const uint32_t so = (uint32_t)(r * XSTR + cb) * 2;
            const size_t g = (qrow0 + r) * QD + k0 + cb;
            cp16(xb + so, xh + g);
            cp16(xb + XSTAGE * 2 + so, xl + g);
        }
        {
            const int c = tid;
            const int r = c >> 2, cb = (c & 3) * 8;
            const uint32_t so = (uint32_t)(r * XSTR + cb) * 2;
            const size_t g = (size_t)(h * DH + r) * QD + k0 + cb;
            cp16(wb + so, Wq + g);
        }
        CP_COMMIT();
    };

    load_stage(0, 0);
    load_stage(1, 1);

    // stage K (96 rows, zero pad 77..79) and V transposed
    for (int i = tid; i < 96 * 8; i += AT_THREADS) {
        const int r = i >> 3, c = i & 7;
        uint4 vk = make_uint4(0, 0, 0, 0);
        if (r < TXT) {
            vk = *(const uint4*)(K + ((size_t)b * TXT + r) * ID + h * DH + c * 8);
        } else if (r >= 80) {
            vk = *(const uint4*)(Ki + ((size_t)b * IMG + (r - 80)) * ID + h * DH + c * 8);
        }
        *(uint4*)(sK + r * QSTR + c * 8) = vk;
    }
    for (int i = tid; i < 96 * 32; i += AT_THREADS) {
        const int j = i >> 5, d = (i & 31) * 2;
        __half2 vv = __halves2half2(__float2half_rn(0.f), __float2half_rn(0.f));
        if (j < TXT) {
            vv = *(const __half2*)(V + ((size_t)b * TXT + j) * ID + h * DH + d);
        } else if (j >= 80) {
            vv = *(const __half2*)(Vi + ((size_t)b * IMG + (j - 80)) * ID + h * DH + d);
        }
        sV[d * PSTR + j] = __low2half(vv);
        sV[(d + 1) * PSTR + j] = __high2half(vv);
    }

    float qacc[8][4];
    #pragma unroll
    for (int n = 0; n < 8; n++)
        #pragma unroll
        for (int j = 0; j < 4; j++) qacc[n][j] = 0.f;

    const int nch = QD / GBK;   // 10
    for (int ch = 0; ch < nch; ch++) {
        if (ch + 2 <= nch) { CP_WAIT(1); } else { CP_WAIT(0); }
        __syncthreads();

        const int s = ch & 1;
        const fp16* Xsh = sm + F_X + s * 2 * XSTAGE;
        const fp16* Xsl = Xsh + XSTAGE;
        const fp16* Ws  = sm + F_W + s * WSTAGE;

        #pragma unroll
        for (int kk = 0; kk < GBK; kk += 16) {
            const fp16* xb = Xsh + (m0w + grp) * XSTR + kk + t4 * 2;
            const fp16* xlp = Xsl + (m0w + grp) * XSTR + kk + t4 * 2;
            uint32_t ah[4], al[4];
            ah[0] = ldb(xb);       ah[1] = ldb(xb + 8 * XSTR);
            ah[2] = ldb(xb + 8);   ah[3] = ldb(xb + 8 * XSTR + 8);
            al[0] = ldb(xlp);      al[1] = ldb(xlp + 8 * XSTR);
            al[2] = ldb(xlp + 8);  al[3] = ldb(xlp + 8 * XSTR + 8);
            #pragma unroll
            for (int n = 0; n < 8; n++) {
                const fp16* wb = Ws + (n * 8 + grp) * XSTR + kk + t4 * 2;
                uint32_t bh[2] = { ldb(wb), ldb(wb + 8) };
                mma_f16(qacc[n], ah, bh);
                mma_f16(qacc[n], al, bh);
            }
        }
        __syncthreads();
        if (ch + 2 < nch) load_stage(ch + 2, s);
    }

    // reshape Q accumulators -> QK^T A-fragments (fp16 hi/lo)
    uint32_t qah[4][4], qal[4][4];
    #pragma unroll
    for (int i = 0; i < 4; i++) {
        qah[i][0] = pack_hi(qacc[2*i][0], qacc[2*i][1]);
        qah[i][1] = pack_hi(qacc[2*i][2], qacc[2*i][3]);
        qah[i][2] = pack_hi(qacc[2*i+1][0], qacc[2*i+1][1]);
        qah[i][3] = pack_hi(qacc[2*i+1][2], qacc[2*i+1][3]);
        qal[i][0] = pack_lo(qacc[2*i][0], qacc[2*i][1]);
        qal[i][1] = pack_lo(qacc[2*i][2], qacc[2*i][3]);
        qal[i][2] = pack_lo(qacc[2*i+1][0], qacc[2*i+1][1]);
        qal[i][3] = pack_lo(qacc[2*i+1][2], qacc[2*i+1][3]);
    }

    // QK^T: warp = 16 rows x 96 keys
    {
        float acc[12][4];
        #pragma unroll
        for (int n = 0; n < 12; n++)
            #pragma unroll
            for (int j = 0; j < 4; j++) acc[n][j] = 0.f;

        #pragma unroll
        for (int i = 0; i < 4; i++) {
            const int kk = i * 16;
            #pragma unroll
            for (int n = 0; n < 12; n++) {
                const fp16* kb = sK + (n * 8 + grp) * QSTR + kk + t4 * 2;
                uint32_t bh[2] = { ldb(kb), ldb(kb + 8) };
                mma_f16(acc[n], qah[i], bh);
                mma_f16(acc[n], qal[i], bh);
            }
        }
        #pragma unroll
        for (int n = 0; n < 12; n++) {
            const int cb = n * 8 + 2 * t4;
            S[(m0w + grp) * SSTR_F + cb]     = acc[n][0] * ATT_SCALE;
            S[(m0w + grp) * SSTR_F + cb + 1] = acc[n][1] * ATT_SCALE;
            S[(m0w + grp + 8) * SSTR_F + cb]     = acc[n][2] * ATT_SCALE;
            S[(m0w + grp + 8) * SSTR_F + cb + 1] = acc[n][3] * ATT_SCALE;
        }
    }
    __syncthreads();

    // softmax per row, fold scales into P (fp16 hi/lo)
    if (tid < 128) {
        float* Sr = S + tid * SSTR_F;
        float mt = -1e30f, mi = -1e30f;
        for (int j = 0; j < TXT; j++) mt = fmaxf(mt, Sr[j]);
        for (int j = 80; j < 96; j++) mi = fmaxf(mi, Sr[j]);
        float lt = 0.f, li = 0.f;
        for (int j = 0; j < TXT; j++) { float e = __expf(Sr[j] - mt); lt += e; Sr[j] = e; }
        for (int j = 80; j < 96; j++) { float e = __expf(Sr[j] - mi); li += e; Sr[j] = e; }
        const float ct = ts_p[0] / lt;
        const float ci = is_p[0] / li;
        fp16* ph = sPh + tid * PSTR;
        fp16* pl = sPl + tid * PSTR;
        for (int j = 0; j < 96; j++) {
            float p = (j < TXT) ? Sr[j] * ct : ((j >= 80) ? Sr[j] * ci : 0.f);
            fp16 hh, ll;
            split_f16(p, hh, ll);
            ph[j] = hh; pl[j] = ll;
        }
    }
    __syncthreads();

    // PV: warp = 16 rows x 64 dims, K=96
    {
        float acc[8][4];
        #pragma unroll
        for (int n = 0; n < 8; n++)
            #pragma unroll
            for (int j = 0; j < 4; j++) acc[n][j] = 0.f;

        #pragma unroll
        for (int kk = 0; kk < 96; kk += 16) {
            const fp16* pb = sPh + (m0w + grp) * PSTR + kk + t4 * 2;
            const fp16* pls = sPl + (m0w + grp) * PSTR + kk + t4 * 2;
            uint32_t ah[4], al[4];
            ah[0] = ldb(pb);            ah[1] = ldb(pb + 8 * PSTR);
            ah[2] = ldb(pb + 8);        ah[3] = ldb(pb + 8 * PSTR + 8);
            al[0] = ldb(pls);           al[1] = ldb(pls + 8 * PSTR);
            al[2] = ldb(pls + 8);       al[3] = ldb(pls + 8 * PSTR + 8);
            #pragma unroll
            for (int n = 0; n < 8; n++) {
                const fp16* vb = sV + (n * 8 + grp) * PSTR + kk + t4 * 2;
                uint32_t bh[2] = { ldb(vb), ldb(vb + 8) };
                mma_f16(acc[n], ah, bh);
                mma_f16(acc[n], al, bh);
            }
        }
        const size_t rg = qrow0 + m0w + grp;
        #pragma unroll
        for (int n = 0; n < 8; n++) {
            const int col = h * DH + n * 8 + 2 * t4;
            *(uint32_t*)(Ah + rg * ID + col) = pack_hi(acc[n][0], acc[n][1]);
            *(uint32_t*)(Al + rg * ID + col) = pack_lo(acc[n][0], acc[n][1]);
            *(uint32_t*)(Ah + (rg + 8) * ID + col) = pack_hi(acc[n][2], acc[n][3]);
            *(uint32_t*)(Al + (rg + 8) * ID + col) = pack_lo(acc[n][2], acc[n][3]);
        }
    }
}

// ---------------- launch ----------------
extern "C" void kernel_launch(void* const* d_in, const int* in_sizes, int n_in,
                              void* d_out, int out_size)
{
    const float* x    = (const float*)d_in[0];
    const float* ctx  = (const float*)d_in[1];
    const float* Wq   = (const float*)d_in[2];
    const float* Wk   = (const float*)d_in[3];
    const float* Wv   = (const float*)d_in[4];
    const float* Wkip = (const float*)d_in[5];
    const float* Wvip = (const float*)d_in[6];
    const float* Wo   = (const float*)d_in[7];
    const float* bo   = (const float*)d_in[8];
    const float* ts   = (const float*)d_in[9];
    const float* isc  = (const float*)d_in[10];
    float* out = (float*)d_out;

    fp16 *gAh, *gAl, *gxh, *gxl, *gWq, *gWo, *gWc;
    fp16 *gcth, *gctl, *gcih, *gcil, *gK, *gV, *gKi, *gVi;
    cudaGetSymbolAddress((void**)&gAh, g_Ah);
    cudaGetSymbolAddress((void**)&gAl, g_Al);
    cudaGetSymbolAddress((void**)&gxh, g_xh);
    cudaGetSymbolAddress((void**)&gxl, g_xl);
    cudaGetSymbolAddress((void**)&gWq, g_Wq);
    cudaGetSymbolAddress((void**)&gWo, g_Wo);
    cudaGetSymbolAddress((void**)&gWc, g_Wc);
    cudaGetSymbolAddress((void**)&gcth, g_cth);
    cudaGetSymbolAddress((void**)&gctl, g_ctl);
    cudaGetSymbolAddress((void**)&gcih, g_cih);
    cudaGetSymbolAddress((void**)&gcil, g_cil);
    cudaGetSymbolAddress((void**)&gK,  g_K);
    cudaGetSymbolAddress((void**)&gV,  g_V);
    cudaGetSymbolAddress((void**)&gKi, g_Ki);
    cudaGetSymbolAddress((void**)&gVi, g_Vi);

    cudaFuncSetAttribute(mma_gemm_kernel,
                         cudaFuncAttributeMaxDynamicSharedMemorySize, GEMM_SMEM);
    cudaFuncSetAttribute(fused_qattn_kernel,
                         cudaFuncAttributeMaxDynamicSharedMemorySize, ATT_SMEM);

    // ---- prep
    wsplit_t_kernel<<<(QD * ID + 255) / 256, 256>>>(Wq, gWq, QD, ID);
    wsplit_t_kernel<<<(ID * QD + 255) / 256, 256>>>(Wo, gWo, ID, QD);
    {
        dim3 g((CD * ID + 255) / 256, 4);
        wsplit4_kernel<<<g, 256>>>(Wk, Wv, Wkip, Wvip, gWc);
    }
    pack_txt_kernel<<<(TXT_PAD * CD / 4 + 255) / 256, 256>>>(ctx, gcth, gctl);
    pack_img_kernel<<<(IMG_ROWS * CD / 4 + 255) / 256, 256>>>(ctx, gcih, gcil);
    split_kernel<<<(MQ * QD / 4 + 255) / 256, 256>>>(x, gxh, gxl, MQ * QD / 4);

    // ---- ctx projections (fp16 single outputs: B-operands of attention)
    {
        dim3 gt(ID / 64, TXT_PAD / 128);
        mma_gemm_kernel<<<gt, 128, GEMM_SMEM>>>(gcth, gctl, gWc + 0 * (size_t)ID * CD,
            nullptr, gK, nullptr, nullptr, TXT_PAD, ID, CD);
        mma_gemm_kernel<<<gt, 128, GEMM_SMEM>>>(gcth, gctl, gWc + 1 * (size_t)ID * CD,
            nullptr, gV, nullptr, nullptr, TXT_PAD, ID, CD);
        dim3 gi(ID / 64, IMG_ROWS / 128);
        mma_gemm_kernel<<<gi, 128, GEMM_SMEM>>>(gcih, gcil, gWc + 2 * (size_t)ID * CD,
            nullptr, gKi, nullptr, nullptr, IMG_ROWS, ID, CD);
        mma_gemm_kernel<<<gi, 128, GEMM_SMEM>>>(gcih, gcil, gWc + 3 * (size_t)ID * CD,
            nullptr, gVi, nullptr, nullptr, IMG_ROWS, ID, CD);
    }

    // ---- fused Q-proj + attention
    {
        dim3 g(NQ / 128, HEADS, BATCH);
        fused_qattn_kernel<<<g, AT_THREADS, ATT_SMEM>>>(gxh, gxl, gWq,
                                                        gK, gV, gKi, gVi,
                                                        gAh, gAl, ts, isc);
    }

    // ---- out projection (fp32 + bias)
    {
        dim3 g(QD / 64, MQ / 128);
        mma_gemm_kernel<<<g, 128, GEMM_SMEM>>>(gAh, gAl, gWo,
                                               out, nullptr, nullptr, bo, MQ, QD, ID);
    }
}

// round 8
// speedup vs baseline: 2.4172x; 1.1584x over previous
#include <cuda_runtime.h>
#include <cuda_fp16.h>
#include <cstdint>
#include <cstddef>

// Problem constants
#define BATCH   16
#define NQ      4096
#define QD      320
#define CD      1024
#define CTX     93
#define TXT     77
#define IMG     16
#define HEADS   8
#define DH      64
#define ID      512
#define MQ      (BATCH*NQ)
#define ATT_SCALE 0.125f

#define TXT_ROWS (BATCH*TXT)
#define TXT_PAD  1280
#define IMG_ROWS (BATCH*IMG)

typedef __half fp16;

// ---------------- scratch ----------------
__device__ fp16 g_A  [MQ * ID];         // attention out, single fp16
__device__ fp16 g_xh [MQ * QD];
__device__ fp16 g_xl [MQ * QD];
__device__ fp16 g_Wq [ID * QD];
__device__ fp16 g_Wo [QD * ID];
__device__ fp16 g_Wc [4][ID * CD];
__device__ fp16 g_cth[TXT_PAD * CD];
__device__ fp16 g_ctl[TXT_PAD * CD];
__device__ fp16 g_cih[IMG_ROWS * CD];
__device__ fp16 g_cil[IMG_ROWS * CD];
__device__ fp16 g_K  [TXT_PAD * ID];
__device__ fp16 g_V  [TXT_PAD * ID];
__device__ fp16 g_Ki [IMG_ROWS * ID];
__device__ fp16 g_Vi [IMG_ROWS * ID];

// ---------------- helpers ----------------
__device__ __forceinline__ uint32_t smem_u32(const void* p) {
    uint32_t a;
    asm("{ .reg .u64 t; cvta.to.shared.u64 t, %1; cvt.u32.u64 %0, t; }"
        : "=r"(a) : "l"(p));
    return a;
}
__device__ __forceinline__ void cp16(uint32_t dst, const void* src) {
    asm volatile("cp.async.cg.shared.global [%0], [%1], 16;" :: "r"(dst), "l"(src));
}
#define CP_COMMIT() asm volatile("cp.async.commit_group;" ::: "memory")
#define CP_WAIT(n)  asm volatile("cp.async.wait_group %0;" :: "n"(n) : "memory")

__device__ __forceinline__ void mma_f16(float* c, const uint32_t* a, const uint32_t* b)
{
    asm volatile(
        "mma.sync.aligned.m16n8k16.row.col.f32.f16.f16.f32 "
        "{%0,%1,%2,%3}, {%4,%5,%6,%7}, {%8,%9}, {%0,%1,%2,%3};"
        : "+f"(c[0]), "+f"(c[1]), "+f"(c[2]), "+f"(c[3])
        : "r"(a[0]), "r"(a[1]), "r"(a[2]), "r"(a[3]), "r"(b[0]), "r"(b[1]));
}
__device__ __forceinline__ uint32_t ldb(const fp16* p) { return *(const uint32_t*)p; }
__device__ __forceinline__ void split_f16(float v, fp16& h, fp16& l) {
    h = __float2half_rn(v);
    l = __float2half_rn(v - __half2float(h));
}
__device__ __forceinline__ uint32_t pack2(fp16 a, fp16 b) {
    __half2 p = __halves2half2(a, b);
    return *(uint32_t*)&p;
}
__device__ __forceinline__ uint32_t pack_hi(float a, float b) {
    __half2 p = __floats2half2_rn(a, b);
    return *(uint32_t*)&p;
}
__device__ __forceinline__ uint32_t pack_lo(float a, float b) {
    fp16 ha = __float2half_rn(a), hb = __float2half_rn(b);
    __half2 p = __halves2half2(__float2half_rn(a - __half2float(ha)),
                               __float2half_rn(b - __half2float(hb)));
    return *(uint32_t*)&p;
}

// ---------------- fp16 GEMM, templated A-terms (2-stage cp.async) ---------
// C[M,N] = A[M,K] @ W[N,K]^T. ATERMS=2: A=Ah+Al. ATERMS=1: A=Ah.
// Epilogue: fp32 (+bias) if C, else fp16 to Ch.
#define GBK 32
#define SSTR 40
#define A_ELEM (128 * SSTR)
#define B_ELEM (64 * SSTR)
#define STAGE_ELEM (2 * A_ELEM + B_ELEM)
#define GEMM_SMEM (2 * STAGE_ELEM * 2)

template<int ATERMS>
__global__ __launch_bounds__(128)
void mma_gemm_kernel(const fp16* __restrict__ Ah, const fp16* __restrict__ Al,
                     const fp16* __restrict__ W,
                     float* __restrict__ C, fp16* __restrict__ Ch,
                     const float* __restrict__ bias,
                     int M, int N, int K)
{
    extern __shared__ fp16 smem[];
    const uint32_t sbase = smem_u32(smem);

    const int tid = threadIdx.x;
    const int wid = tid >> 5;
    const int lid = tid & 31;
    const int grp = lid >> 2;
    const int t4  = lid & 3;
    const int wm  = wid >> 1;
    const int wn  = wid & 1;
    const int m0  = blockIdx.y * 128;
    const int n0  = blockIdx.x * 64;

    float acc[4][4][4];
    #pragma unroll
    for (int m = 0; m < 4; m++)
        #pragma unroll
        for (int n = 0; n < 4; n++)
            #pragma unroll
            for (int j = 0; j < 4; j++) acc[m][n][j] = 0.f;

    const int nch = K / GBK;

    auto load_stage = [&](int ch, int s) {
        const int k0 = ch * GBK;
        const uint32_t base = sbase + (uint32_t)s * STAGE_ELEM * 2;
        #pragma unroll
        for (int i = 0; i < 4; i++) {
            const int c = tid + i * 128;
            const int r = c >> 2, cb = (c & 3) * 8;
            const uint32_t so = (uint32_t)(r * SSTR + cb) * 2;
            const size_t g = (size_t)(m0 + r) * K + k0 + cb;
            cp16(base + so, Ah + g);
            if (ATERMS == 2) cp16(base + A_ELEM * 2 + so, Al + g);
        }
        #pragma unroll
        for (int i = 0; i < 2; i++) {
            const int c = tid + i * 128;
            const int r = c >> 2, cb = (c & 3) * 8;
            const uint32_t so = (uint32_t)(r * SSTR + cb) * 2;
            const size_t g = (size_t)(n0 + r) * K + k0 + cb;
            cp16(base + 2 * A_ELEM * 2 + so, W + g);
        }
        CP_COMMIT();
    };

    load_stage(0, 0);
    if (nch > 1) load_stage(1, 1);

    for (int ch = 0; ch < nch; ch++) {
        if (ch + 2 <= nch) { CP_WAIT(1); } else { CP_WAIT(0); }
        __syncthreads();

        const int s = ch & 1;
        const fp16* Ash = smem + s * STAGE_ELEM;
        const fp16* Asl = Ash + A_ELEM;
        const fp16* Bs  = Ash + 2 * A_ELEM;

        #pragma unroll
        for (int kk = 0; kk < GBK; kk += 16) {
            uint32_t bh[4][2];
            #pragma unroll
            for (int n = 0; n < 4; n++) {
                const int br = wn * 32 + n * 8 + grp;
                bh[n][0] = ldb(Bs + br * SSTR + kk + t4 * 2);
                bh[n][1] = ldb(Bs + br * SSTR + kk + t4 * 2 + 8);
            }
            #pragma unroll
            for (int m = 0; m < 4; m++) {
                const int ar0 = wm * 64 + m * 16 + grp;
                uint32_t ah[4], al[4];
                ah[0] = ldb(Ash + ar0 * SSTR + kk + t4 * 2);
                ah[1] = ldb(Ash + (ar0 + 8) * SSTR + kk + t4 * 2);
                ah[2] = ldb(Ash + ar0 * SSTR + kk + t4 * 2 + 8);
                ah[3] = ldb(Ash + (ar0 + 8) * SSTR + kk + t4 * 2 + 8);
                if (ATERMS == 2) {
                    al[0] = ldb(Asl + ar0 * SSTR + kk + t4 * 2);
                    al[1] = ldb(Asl + (ar0 + 8) * SSTR + kk + t4 * 2);
                    al[2] = ldb(Asl + ar0 * SSTR + kk + t4 * 2 + 8);
                    al[3] = ldb(Asl + (ar0 + 8) * SSTR + kk + t4 * 2 + 8);
                }
                #pragma unroll
                for (int n = 0; n < 4; n++) {
                    mma_f16(acc[m][n], ah, bh[n]);
                    if (ATERMS == 2) mma_f16(acc[m][n], al, bh[n]);
                }
            }
        }
        __syncthreads();
        if (ch + 2 < nch) load_stage(ch + 2, s);
    }

    #pragma unroll
    for (int m = 0; m < 4; m++) {
        const int row0 = m0 + wm * 64 + m * 16 + grp;
        #pragma unroll
        for (int n = 0; n < 4; n++) {
            const int col = n0 + wn * 32 + n * 8 + t4 * 2;
            if (C) {
                float b0 = 0.f, b1 = 0.f;
                if (bias) { b0 = bias[col]; b1 = bias[col + 1]; }
                *(float2*)(C + (size_t)row0 * N + col) =
                    make_float2(acc[m][n][0] + b0, acc[m][n][1] + b1);
                *(float2*)(C + (size_t)(row0 + 8) * N + col) =
                    make_float2(acc[m][n][2] + b0, acc[m][n][3] + b1);
            } else {
                *(uint32_t*)(Ch + (size_t)row0 * N + col) = pack_hi(acc[m][n][0], acc[m][n][1]);
                *(uint32_t*)(Ch + (size_t)(row0 + 8) * N + col) = pack_hi(acc[m][n][2], acc[m][n][3]);
            }
        }
    }
}

// ---------------- prep kernels ----------------
__global__ void split_kernel(const float* __restrict__ X,
                             fp16* __restrict__ H, fp16* __restrict__ L, int n4)
{
    int i = blockIdx.x * blockDim.x + threadIdx.x;
    if (i >= n4) return;
    float4 v = ((const float4*)X)[i];
    float f[4] = {v.x, v.y, v.z, v.w};
    fp16 h[4], l[4];
    #pragma unroll
    for (int j = 0; j < 4; j++) split_f16(f[j], h[j], l[j]);
    ((uint32_t*)H)[2 * i]     = pack2(h[0], h[1]);
    ((uint32_t*)H)[2 * i + 1] = pack2(h[2], h[3]);
    ((uint32_t*)L)[2 * i]     = pack2(l[0], l[1]);
    ((uint32_t*)L)[2 * i + 1] = pack2(l[2], l[3]);
}

__global__ void wsplit_t_kernel(const float* __restrict__ W,
                                fp16* __restrict__ Wt, int K, int N)
{
    int idx = blockIdx.x * blockDim.x + threadIdx.x;
    if (idx >= K * N) return;
    int k = idx / N, n = idx % N;
    Wt[(size_t)n * K + k] = __float2half_rn(W[idx]);
}

__global__ void wsplit4_kernel(const float* __restrict__ W0, const float* __restrict__ W1,
                               const float* __restrict__ W2, const float* __restrict__ W3,
                               fp16* __restrict__ Wt)
{
    int idx = blockIdx.x * blockDim.x + threadIdx.x;
    if (idx >= CD * ID) return;
    const int which = blockIdx.y;
    const float* W = (which == 0) ? W0 : (which == 1) ? W1 : (which == 2) ? W2 : W3;
    int k = idx / ID, n = idx % ID;
    Wt[(size_t)which * ID * CD + (size_t)n * CD + k] = __float2half_rn(W[idx]);
}

__global__ void pack_txt_kernel(const float* __restrict__ ctx,
                                fp16* __restrict__ H, fp16* __restrict__ L)
{
    int i = blockIdx.x * blockDim.x + threadIdx.x;
    if (i >= TXT_PAD * CD / 4) return;
    int r = i / (CD / 4), c4 = i % (CD / 4);
    float4 v = make_float4(0.f, 0.f, 0.f, 0.f);
    if (r < TXT_ROWS) {
        int b = r / TXT, j = r % TXT;
        v = *(const float4*)(ctx + ((size_t)b * CTX + j) * CD + c4 * 4);
    }
    float f[4] = {v.x, v.y, v.z, v.w};
    fp16 h[4], l[4];
    #pragma unroll
    for (int j = 0; j < 4; j++) split_f16(f[j], h[j], l[j]);
    ((uint32_t*)H)[2 * i]     = pack2(h[0], h[1]);
    ((uint32_t*)H)[2 * i + 1] = pack2(h[2], h[3]);
    ((uint32_t*)L)[2 * i]     = pack2(l[0], l[1]);
    ((uint32_t*)L)[2 * i + 1] = pack2(l[2], l[3]);
}

__global__ void pack_img_kernel(const float* __restrict__ ctx,
                                fp16* __restrict__ H, fp16* __restrict__ L)
{
    int i = blockIdx.x * blockDim.x + threadIdx.x;
    if (i >= IMG_ROWS * CD / 4) return;
    int r = i / (CD / 4), c4 = i % (CD / 4);
    int b = r / IMG, j = r % IMG;
    float4 v = *(const float4*)(ctx + ((size_t)b * CTX + TXT + j) * CD + c4 * 4);
    float f[4] = {v.x, v.y, v.z, v.w};
    fp16 h[4], l[4];
    #pragma unroll
    for (int jj = 0; jj < 4; jj++) split_f16(f[jj], h[jj], l[jj]);
    ((uint32_t*)H)[2 * i]     = pack2(h[0], h[1]);
    ((uint32_t*)H)[2 * i + 1] = pack2(h[2], h[3]);
    ((uint32_t*)L)[2 * i]     = pack2(l[0], l[1]);
    ((uint32_t*)L)[2 * i + 1] = pack2(l[2], l[3]);
}

// ---------------- fused Q-proj + attention ----------------
#define AT_THREADS 256
#define QSTR 72
#define PSTR 104
#define SSTR_F 97
#define XSTR 40

#define F_K  0
#define F_V  (F_K + 96*QSTR)
#define F_PH (F_V + 64*PSTR)
#define F_S  (F_PH + 128*PSTR)
#define F_X  (F_S + 128*SSTR_F*2)
#define XSTAGE (128*XSTR)
#define F_W  (F_X + 4*XSTAGE)
#define WSTAGE (64*XSTR)
#define ATT_SMEM ((F_W + 2*WSTAGE) * 2)

__global__ __launch_bounds__(AT_THREADS)
void fused_qattn_kernel(const fp16* __restrict__ xh, const fp16* __restrict__ xl,
                        const fp16* __restrict__ Wq,
                        const fp16* __restrict__ K, const fp16* __restrict__ V,
                        const fp16* __restrict__ Ki, const fp16* __restrict__ Vi,
                        fp16* __restrict__ Aout,
                        const float* __restrict__ ts_p, const float* __restrict__ is_p)
{
    extern __shared__ fp16 sm[];
    fp16* sK  = sm + F_K;
    fp16* sV  = sm + F_V;   // transposed [d][key]
    fp16* sPh = sm + F_PH;
    float* S  = (float*)(sm + F_S);
    const uint32_t sbase = smem_u32(sm);

    const int b = blockIdx.z, h = blockIdx.y;
    const int tid = threadIdx.x;
    const int wid = tid >> 5, lid = tid & 31;
    const int grp = lid >> 2, t4 = lid & 3;
    const int m0w = wid * 16;
    const size_t qrow0 = (size_t)b * NQ + blockIdx.x * 128;

    auto load_stage = [&](int ch, int s) {
        const int k0 = ch * GBK;
        const uint32_t xb = sbase + (F_X + s * 2 * XSTAGE) * 2;
        const uint32_t wb = sbase + (F_W + s * WSTAGE) * 2;
        #pragma unroll
        for (int i = 0; i < 2; i++) {
            const int c = tid + i * AT_THREADS;
            const int r = c >> 2, cb = (c & 3) * 8;
            const uint32_t so = (uint32_t)(r * XSTR + cb) * 2;
            const size_t g = (qrow0 + r) * QD + k0 + cb;
            cp16(xb + so, xh + g);
            cp16(xb + XSTAGE * 2 + so, xl + g);
        }
        {
            const int c = tid;
            const int r = c >> 2, cb = (c & 3) * 8;
            const uint32_t so = (uint32_t)(r * XSTR + cb) * 2;
            const size_t g = (size_t)(h * DH + r) * QD + k0 + cb;
            cp16(wb + so, Wq + g);
        }
        CP_COMMIT();
    };

    load_stage(0, 0);
    load_stage(1, 1);

    // stage K (96 rows, zero pad 77..79) and V transposed
    for (int i = tid; i < 96 * 8; i += AT_THREADS) {
        const int r = i >> 3, c = i & 7;
        uint4 vk = make_uint4(0, 0, 0, 0);
        if (r < TXT) {
            vk = *(const uint4*)(K + ((size_t)b * TXT + r) * ID + h * DH + c * 8);
        } else if (r >= 80) {
            vk = *(const uint4*)(Ki + ((size_t)b * IMG + (r - 80)) * ID + h * DH + c * 8);
        }
        *(uint4*)(sK + r * QSTR + c * 8) = vk;
    }
    for (int i = tid; i < 96 * 32; i += AT_THREADS) {
        const int j = i >> 5, d = (i & 31) * 2;
        __half2 vv = __halves2half2(__float2half_rn(0.f), __float2half_rn(0.f));
        if (j < TXT) {
            vv = *(const __half2*)(V + ((size_t)b * TXT + j) * ID + h * DH + d);
        } else if (j >= 80) {
            vv = *(const __half2*)(Vi + ((size_t)b * IMG + (j - 80)) * ID + h * DH + d);
        }
        sV[d * PSTR + j] = __low2half(vv);
        sV[(d + 1) * PSTR + j] = __high2half(vv);
    }

    float qacc[8][4];
    #pragma unroll
    for (int n = 0; n < 8; n++)
        #pragma unroll
        for (int j = 0; j < 4; j++) qacc[n][j] = 0.f;

    const int nch = QD / GBK;   // 10
    for (int ch = 0; ch < nch; ch++) {
        if (ch + 2 <= nch) { CP_WAIT(1); } else { CP_WAIT(0); }
        __syncthreads();

        const int s = ch & 1;
        const fp16* Xsh = sm + F_X + s * 2 * XSTAGE;
        const fp16* Xsl = Xsh + XSTAGE;
        const fp16* Ws  = sm + F_W + s * WSTAGE;

        #pragma unroll
        for (int kk = 0; kk < GBK; kk += 16) {
            const fp16* xb = Xsh + (m0w + grp) * XSTR + kk + t4 * 2;
            const fp16* xlp = Xsl + (m0w + grp) * XSTR + kk + t4 * 2;
            uint32_t ah[4], al[4];
            ah[0] = ldb(xb);       ah[1] = ldb(xb + 8 * XSTR);
            ah[2] = ldb(xb + 8);   ah[3] = ldb(xb + 8 * XSTR + 8);
            al[0] = ldb(xlp);      al[1] = ldb(xlp + 8 * XSTR);
            al[2] = ldb(xlp + 8);  al[3] = ldb(xlp + 8 * XSTR + 8);
            #pragma unroll
            for (int n = 0; n < 8; n++) {
                const fp16* wb = Ws + (n * 8 + grp) * XSTR + kk + t4 * 2;
                uint32_t bh[2] = { ldb(wb), ldb(wb + 8) };
                mma_f16(qacc[n], ah, bh);
                mma_f16(qacc[n], al, bh);
            }
        }
        __syncthreads();
        if (ch + 2 < nch) load_stage(ch + 2, s);
    }

    // reshape Q accumulators -> QK^T A-fragments (fp16 hi/lo)
    uint32_t qah[4][4], qal[4][4];
    #pragma unroll
    for (int i = 0; i < 4; i++) {
        qah[i][0] = pack_hi(qacc[2*i][0], qacc[2*i][1]);
        qah[i][1] = pack_hi(qacc[2*i][2], qacc[2*i][3]);
        qah[i][2] = pack_hi(qacc[2*i+1][0], qacc[2*i+1][1]);
        qah[i][3] = pack_hi(qacc[2*i+1][2], qacc[2*i+1][3]);
        qal[i][0] = pack_lo(qacc[2*i][0], qacc[2*i][1]);
        qal[i][1] = pack_lo(qacc[2*i][2], qacc[2*i][3]);
        qal[i][2] = pack_lo(qacc[2*i+1][0], qacc[2*i+1][1]);
        qal[i][3] = pack_lo(qacc[2*i+1][2], qacc[2*i+1][3]);
    }

    // QK^T: warp = 16 rows x 96 keys (2-term Q)
    {
        float acc[12][4];
        #pragma unroll
        for (int n = 0; n < 12; n++)
            #pragma unroll
            for (int j = 0; j < 4; j++) acc[n][j] = 0.f;

        #pragma unroll
        for (int i = 0; i < 4; i++) {
            const int kk = i * 16;
            #pragma unroll
            for (int n = 0; n < 12; n++) {
                const fp16* kb = sK + (n * 8 + grp) * QSTR + kk + t4 * 2;
                uint32_t bh[2] = { ldb(kb), ldb(kb + 8) };
                mma_f16(acc[n], qah[i], bh);
                mma_f16(acc[n], qal[i], bh);
            }
        }
        #pragma unroll
        for (int n = 0; n < 12; n++) {
            const int cb = n * 8 + 2 * t4;
            S[(m0w + grp) * SSTR_F + cb]     = acc[n][0] * ATT_SCALE;
            S[(m0w + grp) * SSTR_F + cb + 1] = acc[n][1] * ATT_SCALE;
            S[(m0w + grp + 8) * SSTR_F + cb]     = acc[n][2] * ATT_SCALE;
            S[(m0w + grp + 8) * SSTR_F + cb + 1] = acc[n][3] * ATT_SCALE;
        }
    }
    __syncthreads();

    // softmax per row, fold scales into P (single fp16)
    if (tid < 128) {
        float* Sr = S + tid * SSTR_F;
        float mt = -1e30f, mi = -1e30f;
        for (int j = 0; j < TXT; j++) mt = fmaxf(mt, Sr[j]);
        for (int j = 80; j < 96; j++) mi = fmaxf(mi, Sr[j]);
        float lt = 0.f, li = 0.f;
        for (int j = 0; j < TXT; j++) { float e = __expf(Sr[j] - mt); lt += e; Sr[j] = e; }
        for (int j = 80; j < 96; j++) { float e = __expf(Sr[j] - mi); li += e; Sr[j] = e; }
        const float ct = ts_p[0] / lt;
        const float ci = is_p[0] / li;
        fp16* ph = sPh + tid * PSTR;
        for (int j = 0; j < 96; j++) {
            float p = (j < TXT) ? Sr[j] * ct : ((j >= 80) ? Sr[j] * ci : 0.f);
            ph[j] = __float2half_rn(p);
        }
    }
    __syncthreads();

    // PV: warp = 16 rows x 64 dims, K=96 (single-term P)
    {
        float acc[8][4];
        #pragma unroll
        for (int n = 0; n < 8; n++)
            #pragma unroll
            for (int j = 0; j < 4; j++) acc[n][j] = 0.f;

        #pragma unroll
        for (int kk = 0; kk < 96; kk += 16) {
            const fp16* pb = sPh + (m0w + grp) * PSTR + kk + t4 * 2;
            uint32_t ah[4];
            ah[0] = ldb(pb);            ah[1] = ldb(pb + 8 * PSTR);
            ah[2] = ldb(pb + 8);        ah[3] = ldb(pb + 8 * PSTR + 8);
            #pragma unroll
            for (int n = 0; n < 8; n++) {
                const fp16* vb = sV + (n * 8 + grp) * PSTR + kk + t4 * 2;
                uint32_t bh[2] = { ldb(vb), ldb(vb + 8) };
                mma_f16(acc[n], ah, bh);
            }
        }
        const size_t rg = qrow0 + m0w + grp;
        #pragma unroll
        for (int n = 0; n < 8; n++) {
            const int col = h * DH + n * 8 + 2 * t4;
            *(uint32_t*)(Aout + rg * ID + col) = pack_hi(acc[n][0], acc[n][1]);
            *(uint32_t*)(Aout + (rg + 8) * ID + col) = pack_hi(acc[n][2], acc[n][3]);
        }
    }
}

// ---------------- launch ----------------
extern "C" void kernel_launch(void* const* d_in, const int* in_sizes, int n_in,
                              void* d_out, int out_size)
{
    const float* x    = (const float*)d_in[0];
    const float* ctx  = (const float*)d_in[1];
    const float* Wq   = (const float*)d_in[2];
    const float* Wk   = (const float*)d_in[3];
    const float* Wv   = (const float*)d_in[4];
    const float* Wkip = (const float*)d_in[5];
    const float* Wvip = (const float*)d_in[6];
    const float* Wo   = (const float*)d_in[7];
    const float* bo   = (const float*)d_in[8];
    const float* ts   = (const float*)d_in[9];
    const float* isc  = (const float*)d_in[10];
    float* out = (float*)d_out;

    fp16 *gA, *gxh, *gxl, *gWq, *gWo, *gWc;
    fp16 *gcth, *gctl, *gcih, *gcil, *gK, *gV, *gKi, *gVi;
    cudaGetSymbolAddress((void**)&gA,  g_A);
    cudaGetSymbolAddress((void**)&gxh, g_xh);
    cudaGetSymbolAddress((void**)&gxl, g_xl);
    cudaGetSymbolAddress((void**)&gWq, g_Wq);
    cudaGetSymbolAddress((void**)&gWo, g_Wo);
    cudaGetSymbolAddress((void**)&gWc, g_Wc);
    cudaGetSymbolAddress((void**)&gcth, g_cth);
    cudaGetSymbolAddress((void**)&gctl, g_ctl);
    cudaGetSymbolAddress((void**)&gcih, g_cih);
    cudaGetSymbolAddress((void**)&gcil, g_cil);
    cudaGetSymbolAddress((void**)&gK,  g_K);
    cudaGetSymbolAddress((void**)&gV,  g_V);
    cudaGetSymbolAddress((void**)&gKi, g_Ki);
    cudaGetSymbolAddress((void**)&gVi, g_Vi);

    cudaFuncSetAttribute(mma_gemm_kernel<2>,
                         cudaFuncAttributeMaxDynamicSharedMemorySize, GEMM_SMEM);
    cudaFuncSetAttribute(mma_gemm_kernel<1>,
                         cudaFuncAttributeMaxDynamicSharedMemorySize, GEMM_SMEM);
    cudaFuncSetAttribute(fused_qattn_kernel,
                         cudaFuncAttributeMaxDynamicSharedMemorySize, ATT_SMEM);

    // ---- prep
    wsplit_t_kernel<<<(QD * ID + 255) / 256, 256>>>(Wq, gWq, QD, ID);
    wsplit_t_kernel<<<(ID * QD + 255) / 256, 256>>>(Wo, gWo, ID, QD);
    {
        dim3 g((CD * ID + 255) / 256, 4);
        wsplit4_kernel<<<g, 256>>>(Wk, Wv, Wkip, Wvip, gWc);
    }
    pack_txt_kernel<<<(TXT_PAD * CD / 4 + 255) / 256, 256>>>(ctx, gcth, gctl);
    pack_img_kernel<<<(IMG_ROWS * CD / 4 + 255) / 256, 256>>>(ctx, gcih, gcil);
    split_kernel<<<(MQ * QD / 4 + 255) / 256, 256>>>(x, gxh, gxl, MQ * QD / 4);

    // ---- ctx projections (2-term A; fp16 outputs)
    {
        dim3 gt(ID / 64, TXT_PAD / 128);
        mma_gemm_kernel<2><<<gt, 128, GEMM_SMEM>>>(gcth, gctl, gWc + 0 * (size_t)ID * CD,
            nullptr, gK, nullptr, TXT_PAD, ID, CD);
        mma_gemm_kernel<2><<<gt, 128, GEMM_SMEM>>>(gcth, gctl, gWc + 1 * (size_t)ID * CD,
            nullptr, gV, nullptr, TXT_PAD, ID, CD);
        dim3 gi(ID / 64, IMG_ROWS / 128);
        mma_gemm_kernel<2><<<gi, 128, GEMM_SMEM>>>(gcih, gcil, gWc + 2 * (size_t)ID * CD,
            nullptr, gKi, nullptr, IMG_ROWS, ID, CD);
        mma_gemm_kernel<2><<<gi, 128, GEMM_SMEM>>>(gcih, gcil, gWc + 3 * (size_t)ID * CD,
            nullptr, gVi, nullptr, IMG_ROWS, ID, CD);
    }

    // ---- fused Q-proj + attention (single fp16 output)
    {
        dim3 g(NQ / 128, HEADS, BATCH);
        fused_qattn_kernel<<<g, AT_THREADS, ATT_SMEM>>>(gxh, gxl, gWq,
                                                        gK, gV, gKi, gVi,
                                                        gA, ts, isc);
    }

    // ---- out projection (single-term A, fp32 + bias)
    {
        dim3 g(QD / 64, MQ / 128);
        mma_gemm_kernel<1><<<g, 128, GEMM_SMEM>>>(gA, nullptr, gWo,
                                                  out, nullptr, bo, MQ, QD, ID);
    }
}

// round 9
// speedup vs baseline: 3.4984x; 1.4473x over previous
#include <cuda_runtime.h>
#include <cuda_fp16.h>
#include <cstdint>
#include <cstddef>

// Problem constants
#define BATCH   16
#define NQ      4096
#define QD      320
#define CD      1024
#define CTX     93
#define TXT     77
#define IMG     16
#define HEADS   8
#define DH      64
#define ID      512
#define MQ      (BATCH*NQ)
#define ATT_SCALE 0.125f

#define TXT_ROWS (BATCH*TXT)
#define TXT_PAD  1280
#define IMG_ROWS (BATCH*IMG)

typedef __half fp16;

// ---------------- scratch ----------------
__device__ fp16 g_A  [MQ * ID];         // attention out, single fp16
__device__ fp16 g_x  [MQ * QD];         // x single fp16
__device__ fp16 g_Wq [ID * QD];
__device__ fp16 g_Wo [QD * ID];
__device__ fp16 g_Wc [4][ID * CD];
__device__ fp16 g_cth[TXT_PAD * CD];
__device__ fp16 g_ctl[TXT_PAD * CD];
__device__ fp16 g_cih[IMG_ROWS * CD];
__device__ fp16 g_cil[IMG_ROWS * CD];
__device__ fp16 g_K  [TXT_PAD * ID];
__device__ fp16 g_V  [TXT_PAD * ID];
__device__ fp16 g_Ki [IMG_ROWS * ID];
__device__ fp16 g_Vi [IMG_ROWS * ID];

// ---------------- helpers ----------------
__device__ __forceinline__ uint32_t smem_u32(const void* p) {
    uint32_t a;
    asm("{ .reg .u64 t; cvta.to.shared.u64 t, %1; cvt.u32.u64 %0, t; }"
        : "=r"(a) : "l"(p));
    return a;
}
__device__ __forceinline__ void cp16(uint32_t dst, const void* src) {
    asm volatile("cp.async.cg.shared.global [%0], [%1], 16;" :: "r"(dst), "l"(src));
}
#define CP_COMMIT() asm volatile("cp.async.commit_group;" ::: "memory")
#define CP_WAIT(n)  asm volatile("cp.async.wait_group %0;" :: "n"(n) : "memory")

__device__ __forceinline__ void mma_f16(float* c, const uint32_t* a, const uint32_t* b)
{
    asm volatile(
        "mma.sync.aligned.m16n8k16.row.col.f32.f16.f16.f32 "
        "{%0,%1,%2,%3}, {%4,%5,%6,%7}, {%8,%9}, {%0,%1,%2,%3};"
        : "+f"(c[0]), "+f"(c[1]), "+f"(c[2]), "+f"(c[3])
        : "r"(a[0]), "r"(a[1]), "r"(a[2]), "r"(a[3]), "r"(b[0]), "r"(b[1]));
}
__device__ __forceinline__ uint32_t ldb(const fp16* p) { return *(const uint32_t*)p; }
__device__ __forceinline__ void split_f16(float v, fp16& h, fp16& l) {
    h = __float2half_rn(v);
    l = __float2half_rn(v - __half2float(h));
}
__device__ __forceinline__ uint32_t pack2(fp16 a, fp16 b) {
    __half2 p = __halves2half2(a, b);
    return *(uint32_t*)&p;
}
__device__ __forceinline__ uint32_t pack_hi(float a, float b) {
    __half2 p = __floats2half2_rn(a, b);
    return *(uint32_t*)&p;
}
__device__ __forceinline__ uint32_t pack_lo(float a, float b) {
    fp16 ha = __float2half_rn(a), hb = __float2half_rn(b);
    __half2 p = __halves2half2(__float2half_rn(a - __half2float(ha)),
                               __float2half_rn(b - __half2float(hb)));
    return *(uint32_t*)&p;
}

// ---------------- fp16 GEMM, templated A-terms (2-stage cp.async) ---------
#define GBK 32
#define SSTR 40
#define A_ELEM (128 * SSTR)
#define B_ELEM (64 * SSTR)
#define STAGE_ELEM (2 * A_ELEM + B_ELEM)
#define GEMM_SMEM (2 * STAGE_ELEM * 2)

template<int ATERMS>
__global__ __launch_bounds__(128)
void mma_gemm_kernel(const fp16* __restrict__ Ah, const fp16* __restrict__ Al,
                     const fp16* __restrict__ W,
                     float* __restrict__ C, fp16* __restrict__ Ch,
                     const float* __restrict__ bias,
                     int M, int N, int K)
{
    extern __shared__ fp16 smem[];
    const uint32_t sbase = smem_u32(smem);

    const int tid = threadIdx.x;
    const int wid = tid >> 5;
    const int lid = tid & 31;
    const int grp = lid >> 2;
    const int t4  = lid & 3;
    const int wm  = wid >> 1;
    const int wn  = wid & 1;
    const int m0  = blockIdx.y * 128;
    const int n0  = blockIdx.x * 64;

    float acc[4][4][4];
    #pragma unroll
    for (int m = 0; m < 4; m++)
        #pragma unroll
        for (int n = 0; n < 4; n++)
            #pragma unroll
            for (int j = 0; j < 4; j++) acc[m][n][j] = 0.f;

    const int nch = K / GBK;

    auto load_stage = [&](int ch, int s) {
        const int k0 = ch * GBK;
        const uint32_t base = sbase + (uint32_t)s * STAGE_ELEM * 2;
        #pragma unroll
        for (int i = 0; i < 4; i++) {
            const int c = tid + i * 128;
            const int r = c >> 2, cb = (c & 3) * 8;
            const uint32_t so = (uint32_t)(r * SSTR + cb) * 2;
            const size_t g = (size_t)(m0 + r) * K + k0 + cb;
            cp16(base + so, Ah + g);
            if (ATERMS == 2) cp16(base + A_ELEM * 2 + so, Al + g);
        }
        #pragma unroll
        for (int i = 0; i < 2; i++) {
            const int c = tid + i * 128;
            const int r = c >> 2, cb = (c & 3) * 8;
            const uint32_t so = (uint32_t)(r * SSTR + cb) * 2;
            const size_t g = (size_t)(n0 + r) * K + k0 + cb;
            cp16(base + 2 * A_ELEM * 2 + so, W + g);
        }
        CP_COMMIT();
    };

    load_stage(0, 0);
    if (nch > 1) load_stage(1, 1);

    for (int ch = 0; ch < nch; ch++) {
        if (ch + 2 <= nch) { CP_WAIT(1); } else { CP_WAIT(0); }
        __syncthreads();

        const int s = ch & 1;
        const fp16* Ash = smem + s * STAGE_ELEM;
        const fp16* Asl = Ash + A_ELEM;
        const fp16* Bs  = Ash + 2 * A_ELEM;

        #pragma unroll
        for (int kk = 0; kk < GBK; kk += 16) {
            uint32_t bh[4][2];
            #pragma unroll
            for (int n = 0; n < 4; n++) {
                const int br = wn * 32 + n * 8 + grp;
                bh[n][0] = ldb(Bs + br * SSTR + kk + t4 * 2);
                bh[n][1] = ldb(Bs + br * SSTR + kk + t4 * 2 + 8);
            }
            #pragma unroll
            for (int m = 0; m < 4; m++) {
                const int ar0 = wm * 64 + m * 16 + grp;
                uint32_t ah[4], al[4];
                ah[0] = ldb(Ash + ar0 * SSTR + kk + t4 * 2);
                ah[1] = ldb(Ash + (ar0 + 8) * SSTR + kk + t4 * 2);
                ah[2] = ldb(Ash + ar0 * SSTR + kk + t4 * 2 + 8);
                ah[3] = ldb(Ash + (ar0 + 8) * SSTR + kk + t4 * 2 + 8);
                if (ATERMS == 2) {
                    al[0] = ldb(Asl + ar0 * SSTR + kk + t4 * 2);
                    al[1] = ldb(Asl + (ar0 + 8) * SSTR + kk + t4 * 2);
                    al[2] = ldb(Asl + ar0 * SSTR + kk + t4 * 2 + 8);
                    al[3] = ldb(Asl + (ar0 + 8) * SSTR + kk + t4 * 2 + 8);
                }
                #pragma unroll
                for (int n = 0; n < 4; n++) {
                    mma_f16(acc[m][n], ah, bh[n]);
                    if (ATERMS == 2) mma_f16(acc[m][n], al, bh[n]);
                }
            }
        }
        __syncthreads();
        if (ch + 2 < nch) load_stage(ch + 2, s);
    }

    #pragma unroll
    for (int m = 0; m < 4; m++) {
        const int row0 = m0 + wm * 64 + m * 16 + grp;
        #pragma unroll
        for (int n = 0; n < 4; n++) {
            const int col = n0 + wn * 32 + n * 8 + t4 * 2;
            if (C) {
                float b0 = 0.f, b1 = 0.f;
                if (bias) { b0 = bias[col]; b1 = bias[col + 1]; }
                *(float2*)(C + (size_t)row0 * N + col) =
                    make_float2(acc[m][n][0] + b0, acc[m][n][1] + b1);
                *(float2*)(C + (size_t)(row0 + 8) * N + col) =
                    make_float2(acc[m][n][2] + b0, acc[m][n][3] + b1);
            } else {
                *(uint32_t*)(Ch + (size_t)row0 * N + col) = pack_hi(acc[m][n][0], acc[m][n][1]);
                *(uint32_t*)(Ch + (size_t)(row0 + 8) * N + col) = pack_hi(acc[m][n][2], acc[m][n][3]);
            }
        }
    }
}

// ---------------- prep kernels ----------------
__global__ void cvt_kernel(const float* __restrict__ X,
                           fp16* __restrict__ H, int n4)
{
    int i = blockIdx.x * blockDim.x + threadIdx.x;
    if (i >= n4) return;
    float4 v = ((const float4*)X)[i];
    ((uint32_t*)H)[2 * i]     = pack_hi(v.x, v.y);
    ((uint32_t*)H)[2 * i + 1] = pack_hi(v.z, v.w);
}

__global__ void wsplit_t_kernel(const float* __restrict__ W,
                                fp16* __restrict__ Wt, int K, int N)
{
    int idx = blockIdx.x * blockDim.x + threadIdx.x;
    if (idx >= K * N) return;
    int k = idx / N, n = idx % N;
    Wt[(size_t)n * K + k] = __float2half_rn(W[idx]);
}

__global__ void wsplit4_kernel(const float* __restrict__ W0, const float* __restrict__ W1,
                               const float* __restrict__ W2, const float* __restrict__ W3,
                               fp16* __restrict__ Wt)
{
    int idx = blockIdx.x * blockDim.x + threadIdx.x;
    if (idx >= CD * ID) return;
    const int which = blockIdx.y;
    const float* W = (which == 0) ? W0 : (which == 1) ? W1 : (which == 2) ? W2 : W3;
    int k = idx / ID, n = idx % ID;
    Wt[(size_t)which * ID * CD + (size_t)n * CD + k] = __float2half_rn(W[idx]);
}

__global__ void pack_txt_kernel(const float* __restrict__ ctx,
                                fp16* __restrict__ H, fp16* __restrict__ L)
{
    int i = blockIdx.x * blockDim.x + threadIdx.x;
    if (i >= TXT_PAD * CD / 4) return;
    int r = i / (CD / 4), c4 = i % (CD / 4);
    float4 v = make_float4(0.f, 0.f, 0.f, 0.f);
    if (r < TXT_ROWS) {
        int b = r / TXT, j = r % TXT;
        v = *(const float4*)(ctx + ((size_t)b * CTX + j) * CD + c4 * 4);
    }
    float f[4] = {v.x, v.y, v.z, v.w};
    fp16 h[4], l[4];
    #pragma unroll
    for (int j = 0; j < 4; j++) split_f16(f[j], h[j], l[j]);
    ((uint32_t*)H)[2 * i]     = pack2(h[0], h[1]);
    ((uint32_t*)H)[2 * i + 1] = pack2(h[2], h[3]);
    ((uint32_t*)L)[2 * i]     = pack2(l[0], l[1]);
    ((uint32_t*)L)[2 * i + 1] = pack2(l[2], l[3]);
}

__global__ void pack_img_kernel(const float* __restrict__ ctx,
                                fp16* __restrict__ H, fp16* __restrict__ L)
{
    int i = blockIdx.x * blockDim.x + threadIdx.x;
    if (i >= IMG_ROWS * CD / 4) return;
    int r = i / (CD / 4), c4 = i % (CD / 4);
    int b = r / IMG, j = r % IMG;
    float4 v = *(const float4*)(ctx + ((size_t)b * CTX + TXT + j) * CD + c4 * 4);
    float f[4] = {v.x, v.y, v.z, v.w};
    fp16 h[4], l[4];
    #pragma unroll
    for (int jj = 0; jj < 4; jj++) split_f16(f[jj], h[jj], l[jj]);
    ((uint32_t*)H)[2 * i]     = pack2(h[0], h[1]);
    ((uint32_t*)H)[2 * i + 1] = pack2(h[2], h[3]);
    ((uint32_t*)L)[2 * i]     = pack2(l[0], l[1]);
    ((uint32_t*)L)[2 * i + 1] = pack2(l[2], l[3]);
}

// ---------------- fused Q-proj + attention ----------------
// Smem: fixed region (K, V^T, P) + union region (x/W pipeline OR scores S).
// Aliasing safe: Q-proj loop ends with __syncthreads() after last pipeline
// read; S is only written after that point.
#define AT_THREADS 256
#define QSTR 72
#define PSTR 104
#define SSTR_F 97
#define XSTR 40

#define F_K    0
#define F_V    (F_K + 96*QSTR)
#define F_PH   (F_V + 64*PSTR)
#define F_PIPE (F_PH + 128*PSTR)
#define XSTAGE (128*XSTR)
#define WSTAGE (64*XSTR)
#define PIPE_ELEM (2*XSTAGE + 2*WSTAGE)          // 15360
#define S_ELEM    (128*SSTR_F*2)                 // 24832 (fp16 units)
#define UNION_ELEM (S_ELEM > PIPE_ELEM ? S_ELEM : PIPE_ELEM)
#define ATT_SMEM  ((F_PIPE + UNION_ELEM) * 2)    // 103424 B -> 2 CTA/SM

__global__ __launch_bounds__(AT_THREADS, 2)
void fused_qattn_kernel(const fp16* __restrict__ x,
                        const fp16* __restrict__ Wq,
                        const fp16* __restrict__ K, const fp16* __restrict__ V,
                        const fp16* __restrict__ Ki, const fp16* __restrict__ Vi,
                        fp16* __restrict__ Aout,
                        const float* __restrict__ ts_p, const float* __restrict__ is_p)
{
    extern __shared__ fp16 sm[];
    fp16* sK  = sm + F_K;
    fp16* sV  = sm + F_V;   // transposed [d][key]
    fp16* sPh = sm + F_PH;
    float* S  = (float*)(sm + F_PIPE);
    const uint32_t sbase = smem_u32(sm);

    const int b = blockIdx.z, h = blockIdx.y;
    const int tid = threadIdx.x;
    const int wid = tid >> 5, lid = tid & 31;
    const int grp = lid >> 2, t4 = lid & 3;
    const int m0w = wid * 16;
    const size_t qrow0 = (size_t)b * NQ + blockIdx.x * 128;

    auto load_stage = [&](int ch, int s) {
        const int k0 = ch * GBK;
        const uint32_t xb = sbase + (F_PIPE + s * XSTAGE) * 2;
        const uint32_t wb = sbase + (F_PIPE + 2 * XSTAGE + s * WSTAGE) * 2;
        #pragma unroll
        for (int i = 0; i < 2; i++) {
            const int c = tid + i * AT_THREADS;
            const int r = c >> 2, cb = (c & 3) * 8;
            const uint32_t so = (uint32_t)(r * XSTR + cb) * 2;
            cp16(xb + so, x + (qrow0 + r) * QD + k0 + cb);
        }
        {
            const int r = tid >> 2, cb = (tid & 3) * 8;
            const uint32_t so = (uint32_t)(r * XSTR + cb) * 2;
            cp16(wb + so, Wq + (size_t)(h * DH + r) * QD + k0 + cb);
        }
        CP_COMMIT();
    };

    load_stage(0, 0);
    load_stage(1, 1);

    // stage K (96 rows, zero pad 77..79) and V transposed
    for (int i = tid; i < 96 * 8; i += AT_THREADS) {
        const int r = i >> 3, c = i & 7;
        uint4 vk = make_uint4(0, 0, 0, 0);
        if (r < TXT) {
            vk = *(const uint4*)(K + ((size_t)b * TXT + r) * ID + h * DH + c * 8);
        } else if (r >= 80) {
            vk = *(const uint4*)(Ki + ((size_t)b * IMG + (r - 80)) * ID + h * DH + c * 8);
        }
        *(uint4*)(sK + r * QSTR + c * 8) = vk;
    }
    for (int i = tid; i < 96 * 32; i += AT_THREADS) {
        const int j = i >> 5, d = (i & 31) * 2;
        __half2 vv = __halves2half2(__float2half_rn(0.f), __float2half_rn(0.f));
        if (j < TXT) {
            vv = *(const __half2*)(V + ((size_t)b * TXT + j) * ID + h * DH + d);
        } else if (j >= 80) {
            vv = *(const __half2*)(Vi + ((size_t)b * IMG + (j - 80)) * ID + h * DH + d);
        }
        sV[d * PSTR + j] = __low2half(vv);
        sV[(d + 1) * PSTR + j] = __high2half(vv);
    }

    float qacc[8][4];
    #pragma unroll
    for (int n = 0; n < 8; n++)
        #pragma unroll
        for (int j = 0; j < 4; j++) qacc[n][j] = 0.f;

    const int nch = QD / GBK;   // 10
    for (int ch = 0; ch < nch; ch++) {
        if (ch + 2 <= nch) { CP_WAIT(1); } else { CP_WAIT(0); }
        __syncthreads();

        const int s = ch & 1;
        const fp16* Xs = sm + F_PIPE + s * XSTAGE;
        const fp16* Ws = sm + F_PIPE + 2 * XSTAGE + s * WSTAGE;

        #pragma unroll
        for (int kk = 0; kk < GBK; kk += 16) {
            const fp16* xb = Xs + (m0w + grp) * XSTR + kk + t4 * 2;
            uint32_t ah[4];
            ah[0] = ldb(xb);       ah[1] = ldb(xb + 8 * XSTR);
            ah[2] = ldb(xb + 8);   ah[3] = ldb(xb + 8 * XSTR + 8);
            #pragma unroll
            for (int n = 0; n < 8; n++) {
                const fp16* wb = Ws + (n * 8 + grp) * XSTR + kk + t4 * 2;
                uint32_t bh[2] = { ldb(wb), ldb(wb + 8) };
                mma_f16(qacc[n], ah, bh);
            }
        }
        __syncthreads();
        if (ch + 2 < nch) load_stage(ch + 2, s);
    }
    // After this point the pipeline region is dead; S may alias it.

    // reshape Q accumulators -> QK^T A-fragments (fp16 hi/lo)
    uint32_t qah[4][4], qal[4][4];
    #pragma unroll
    for (int i = 0; i < 4; i++) {
        qah[i][0] = pack_hi(qacc[2*i][0], qacc[2*i][1]);
        qah[i][1] = pack_hi(qacc[2*i][2], qacc[2*i][3]);
        qah[i][2] = pack_hi(qacc[2*i+1][0], qacc[2*i+1][1]);
        qah[i][3] = pack_hi(qacc[2*i+1][2], qacc[2*i+1][3]);
        qal[i][0] = pack_lo(qacc[2*i][0], qacc[2*i][1]);
        qal[i][1] = pack_lo(qacc[2*i][2], qacc[2*i][3]);
        qal[i][2] = pack_lo(qacc[2*i+1][0], qacc[2*i+1][1]);
        qal[i][3] = pack_lo(qacc[2*i+1][2], qacc[2*i+1][3]);
    }

    // QK^T: warp = 16 rows x 96 keys (2-term Q)
    {
        float acc[12][4];
        #pragma unroll
        for (int n = 0; n < 12; n++)
            #pragma unroll
            for (int j = 0; j < 4; j++) acc[n][j] = 0.f;

        #pragma unroll
        for (int i = 0; i < 4; i++) {
            const int kk = i * 16;
            #pragma unroll
            for (int n = 0; n < 12; n++) {
                const fp16* kb = sK + (n * 8 + grp) * QSTR + kk + t4 * 2;
                uint32_t bh[2] = { ldb(kb), ldb(kb + 8) };
                mma_f16(acc[n], qah[i], bh);
                mma_f16(acc[n], qal[i], bh);
            }
        }
        #pragma unroll
        for (int n = 0; n < 12; n++) {
            const int cb = n * 8 + 2 * t4;
            S[(m0w + grp) * SSTR_F + cb]     = acc[n][0] * ATT_SCALE;
            S[(m0w + grp) * SSTR_F + cb + 1] = acc[n][1] * ATT_SCALE;
            S[(m0w + grp + 8) * SSTR_F + cb]     = acc[n][2] * ATT_SCALE;
            S[(m0w + grp + 8) * SSTR_F + cb + 1] = acc[n][3] * ATT_SCALE;
        }
    }
    __syncthreads();

    // softmax per row, fold scales into P (single fp16)
    if (tid < 128) {
        float* Sr = S + tid * SSTR_F;
        float mt = -1e30f, mi = -1e30f;
        for (int j = 0; j < TXT; j++) mt = fmaxf(mt, Sr[j]);
        for (int j = 80; j < 96; j++) mi = fmaxf(mi, Sr[j]);
        float lt = 0.f, li = 0.f;
        for (int j = 0; j < TXT; j++) { float e = __expf(Sr[j] - mt); lt += e; Sr[j] = e; }
        for (int j = 80; j < 96; j++) { float e = __expf(Sr[j] - mi); li += e; Sr[j] = e; }
        const float ct = ts_p[0] / lt;
        const float ci = is_p[0] / li;
        fp16* ph = sPh + tid * PSTR;
        for (int j = 0; j < 96; j++) {
            float p = (j < TXT) ? Sr[j] * ct : ((j >= 80) ? Sr[j] * ci : 0.f);
            ph[j] = __float2half_rn(p);
        }
    }
    __syncthreads();

    // PV: warp = 16 rows x 64 dims, K=96 (single-term P)
    {
        float acc[8][4];
        #pragma unroll
        for (int n = 0; n < 8; n++)
            #pragma unroll
            for (int j = 0; j < 4; j++) acc[n][j] = 0.f;

        #pragma unroll
        for (int kk = 0; kk < 96; kk += 16) {
            const fp16* pb = sPh + (m0w + grp) * PSTR + kk + t4 * 2;
            uint32_t ah[4];
            ah[0] = ldb(pb);            ah[1] = ldb(pb + 8 * PSTR);
            ah[2] = ldb(pb + 8);        ah[3] = ldb(pb + 8 * PSTR + 8);
            #pragma unroll
            for (int n = 0; n < 8; n++) {
                const fp16* vb = sV + (n * 8 + grp) * PSTR + kk + t4 * 2;
                uint32_t bh[2] = { ldb(vb), ldb(vb + 8) };
                mma_f16(acc[n], ah, bh);
            }
        }
        const size_t rg = qrow0 + m0w + grp;
        #pragma unroll
        for (int n = 0; n < 8; n++) {
            const int col = h * DH + n * 8 + 2 * t4;
            *(uint32_t*)(Aout + rg * ID + col) = pack_hi(acc[n][0], acc[n][1]);
            *(uint32_t*)(Aout + (rg + 8) * ID + col) = pack_hi(acc[n][2], acc[n][3]);
        }
    }
}

// ---------------- launch ----------------
extern "C" void kernel_launch(void* const* d_in, const int* in_sizes, int n_in,
                              void* d_out, int out_size)
{
    const float* x    = (const float*)d_in[0];
    const float* ctx  = (const float*)d_in[1];
    const float* Wq   = (const float*)d_in[2];
    const float* Wk   = (const float*)d_in[3];
    const float* Wv   = (const float*)d_in[4];
    const float* Wkip = (const float*)d_in[5];
    const float* Wvip = (const float*)d_in[6];
    const float* Wo   = (const float*)d_in[7];
    const float* bo   = (const float*)d_in[8];
    const float* ts   = (const float*)d_in[9];
    const float* isc  = (const float*)d_in[10];
    float* out = (float*)d_out;

    fp16 *gA, *gx, *gWq, *gWo, *gWc;
    fp16 *gcth, *gctl, *gcih, *gcil, *gK, *gV, *gKi, *gVi;
    cudaGetSymbolAddress((void**)&gA,  g_A);
    cudaGetSymbolAddress((void**)&gx,  g_x);
    cudaGetSymbolAddress((void**)&gWq, g_Wq);
    cudaGetSymbolAddress((void**)&gWo, g_Wo);
    cudaGetSymbolAddress((void**)&gWc, g_Wc);
    cudaGetSymbolAddress((void**)&gcth, g_cth);
    cudaGetSymbolAddress((void**)&gctl, g_ctl);
    cudaGetSymbolAddress((void**)&gcih, g_cih);
    cudaGetSymbolAddress((void**)&gcil, g_cil);
    cudaGetSymbolAddress((void**)&gK,  g_K);
    cudaGetSymbolAddress((void**)&gV,  g_V);
    cudaGetSymbolAddress((void**)&gKi, g_Ki);
    cudaGetSymbolAddress((void**)&gVi, g_Vi);

    cudaFuncSetAttribute(mma_gemm_kernel<2>,
                         cudaFuncAttributeMaxDynamicSharedMemorySize, GEMM_SMEM);
    cudaFuncSetAttribute(mma_gemm_kernel<1>,
                         cudaFuncAttributeMaxDynamicSharedMemorySize, GEMM_SMEM);
    cudaFuncSetAttribute(fused_qattn_kernel,
                         cudaFuncAttributeMaxDynamicSharedMemorySize, ATT_SMEM);

    // ---- prep
    wsplit_t_kernel<<<(QD * ID + 255) / 256, 256>>>(Wq, gWq, QD, ID);
    wsplit_t_kernel<<<(ID * QD + 255) / 256, 256>>>(Wo, gWo, ID, QD);
    {
        dim3 g((CD * ID + 255) / 256, 4);
        wsplit4_kernel<<<g, 256>>>(Wk, Wv, Wkip, Wvip, gWc);
    }
    pack_txt_kernel<<<(TXT_PAD * CD / 4 + 255) / 256, 256>>>(ctx, gcth, gctl);
    pack_img_kernel<<<(IMG_ROWS * CD / 4 + 255) / 256, 256>>>(ctx, gcih, gcil);
    cvt_kernel<<<(MQ * QD / 4 + 255) / 256, 256>>>(x, gx, MQ * QD / 4);

    // ---- ctx projections (2-term A; fp16 outputs)
    {
        dim3 gt(ID / 64, TXT_PAD / 128);
        mma_gemm_kernel<2><<<gt, 128, GEMM_SMEM>>>(gcth, gctl, gWc + 0 * (size_t)ID * CD,
            nullptr, gK, nullptr, TXT_PAD, ID, CD);
        mma_gemm_kernel<2><<<gt, 128, GEMM_SMEM>>>(gcth, gctl, gWc + 1 * (size_t)ID * CD,
            nullptr, gV, nullptr, TXT_PAD, ID, CD);
        dim3 gi(ID / 64, IMG_ROWS / 128);
        mma_gemm_kernel<2><<<gi, 128, GEMM_SMEM>>>(gcih, gcil, gWc + 2 * (size_t)ID * CD,
            nullptr, gKi, nullptr, IMG_ROWS, ID, CD);
        mma_gemm_kernel<2><<<gi, 128, GEMM_SMEM>>>(gcih, gcil, gWc + 3 * (size_t)ID * CD,
            nullptr, gVi, nullptr, IMG_ROWS, ID, CD);
    }

    // ---- fused Q-proj + attention (single-term x)
    {
        dim3 g(NQ / 128, HEADS, BATCH);
        fused_qattn_kernel<<<g, AT_THREADS, ATT_SMEM>>>(gx, gWq,
                                                        gK, gV, gKi, gVi,
                                                        gA, ts, isc);
    }

    // ---- out projection (single-term A, fp32 + bias)
    {
        dim3 g(QD / 64, MQ / 128);
        mma_gemm_kernel<1><<<g, 128, GEMM_SMEM>>>(gA, nullptr, gWo,
                                                  out, nullptr, bo, MQ, QD, ID);
    }
}

// round 10
// speedup vs baseline: 3.9590x; 1.1317x over previous
#include <cuda_runtime.h>
#include <cuda_fp16.h>
#include <cstdint>
#include <cstddef>

// Problem constants
#define BATCH   16
#define NQ      4096
#define QD      320
#define CD      1024
#define CTX     93
#define TXT     77
#define IMG     16
#define HEADS   8
#define DH      64
#define ID      512
#define MQ      (BATCH*NQ)
#define ATT_SCALE 0.125f

#define TXT_ROWS (BATCH*TXT)
#define TXT_PAD  1280
#define IMG_ROWS (BATCH*IMG)
#define KVW      1024          // fused K|V row width

typedef __half fp16;

// ---------------- scratch ----------------
__device__ fp16 g_A  [MQ * ID];          // attention out (single fp16)
__device__ fp16 g_x  [MQ * QD];          // x (single fp16)
__device__ fp16 g_Wq [ID * QD];
__device__ fp16 g_Wo [QD * ID];
__device__ fp16 g_Wc [4][ID * CD];       // [Wk;Wv;Wkip;Wvip]^T — pairs contiguous
__device__ fp16 g_ct [TXT_PAD * CD];     // ctx text packed (single fp16)
__device__ fp16 g_ci [IMG_ROWS * CD];
__device__ fp16 g_KVt[TXT_PAD * KVW];    // [row][K(512) | V(512)]
__device__ fp16 g_KVi[IMG_ROWS * KVW];

// ---------------- helpers ----------------
__device__ __forceinline__ uint32_t smem_u32(const void* p) {
    uint32_t a;
    asm("{ .reg .u64 t; cvta.to.shared.u64 t, %1; cvt.u32.u64 %0, t; }"
        : "=r"(a) : "l"(p));
    return a;
}
__device__ __forceinline__ void cp16(uint32_t dst, const void* src) {
    asm volatile("cp.async.cg.shared.global [%0], [%1], 16;" :: "r"(dst), "l"(src));
}
#define CP_COMMIT() asm volatile("cp.async.commit_group;" ::: "memory")
#define CP_WAIT(n)  asm volatile("cp.async.wait_group %0;" :: "n"(n) : "memory")

__device__ __forceinline__ void mma_f16(float* c, const uint32_t* a, const uint32_t* b)
{
    asm volatile(
        "mma.sync.aligned.m16n8k16.row.col.f32.f16.f16.f32 "
        "{%0,%1,%2,%3}, {%4,%5,%6,%7}, {%8,%9}, {%0,%1,%2,%3};"
        : "+f"(c[0]), "+f"(c[1]), "+f"(c[2]), "+f"(c[3])
        : "r"(a[0]), "r"(a[1]), "r"(a[2]), "r"(a[3]), "r"(b[0]), "r"(b[1]));
}
__device__ __forceinline__ uint32_t ldb(const fp16* p) { return *(const uint32_t*)p; }
__device__ __forceinline__ uint32_t pack_hi(float a, float b) {
    __half2 p = __floats2half2_rn(a, b);
    return *(uint32_t*)&p;
}

// ---------------- fp16 GEMM, single-term A (2-stage cp.async) -------------
// C[M,N] = A[M,K] @ W[N,K]^T. Epilogue: fp32 (+bias) if C, else fp16 to Ch.
#define GBK 32
#define SSTR 40
#define A_ELEM (128 * SSTR)
#define B_ELEM (64 * SSTR)
#define STAGE_ELEM (A_ELEM + B_ELEM)
#define GEMM_SMEM (2 * STAGE_ELEM * 2)   // 30720 B

__global__ __launch_bounds__(128)
void mma_gemm_kernel(const fp16* __restrict__ Ah,
                     const fp16* __restrict__ W,
                     float* __restrict__ C, fp16* __restrict__ Ch,
                     const float* __restrict__ bias,
                     int M, int N, int K)
{
    extern __shared__ fp16 smem[];
    const uint32_t sbase = smem_u32(smem);

    const int tid = threadIdx.x;
    const int wid = tid >> 5;
    const int lid = tid & 31;
    const int grp = lid >> 2;
    const int t4  = lid & 3;
    const int wm  = wid >> 1;
    const int wn  = wid & 1;
    const int m0  = blockIdx.y * 128;
    const int n0  = blockIdx.x * 64;

    float acc[4][4][4];
    #pragma unroll
    for (int m = 0; m < 4; m++)
        #pragma unroll
        for (int n = 0; n < 4; n++)
            #pragma unroll
            for (int j = 0; j < 4; j++) acc[m][n][j] = 0.f;

    const int nch = K / GBK;

    auto load_stage = [&](int ch, int s) {
        const int k0 = ch * GBK;
        const uint32_t base = sbase + (uint32_t)s * STAGE_ELEM * 2;
        #pragma unroll
        for (int i = 0; i < 4; i++) {
            const int c = tid + i * 128;
            const int r = c >> 2, cb = (c & 3) * 8;
            const uint32_t so = (uint32_t)(r * SSTR + cb) * 2;
            cp16(base + so, Ah + (size_t)(m0 + r) * K + k0 + cb);
        }
        #pragma unroll
        for (int i = 0; i < 2; i++) {
            const int c = tid + i * 128;
            const int r = c >> 2, cb = (c & 3) * 8;
            const uint32_t so = (uint32_t)(r * SSTR + cb) * 2;
            cp16(base + A_ELEM * 2 + so, W + (size_t)(n0 + r) * K + k0 + cb);
        }
        CP_COMMIT();
    };

    load_stage(0, 0);
    if (nch > 1) load_stage(1, 1);

    for (int ch = 0; ch < nch; ch++) {
        if (ch + 2 <= nch) { CP_WAIT(1); } else { CP_WAIT(0); }
        __syncthreads();

        const int s = ch & 1;
        const fp16* Ash = smem + s * STAGE_ELEM;
        const fp16* Bs  = Ash + A_ELEM;

        #pragma unroll
        for (int kk = 0; kk < GBK; kk += 16) {
            uint32_t bh[4][2];
            #pragma unroll
            for (int n = 0; n < 4; n++) {
                const int br = wn * 32 + n * 8 + grp;
                bh[n][0] = ldb(Bs + br * SSTR + kk + t4 * 2);
                bh[n][1] = ldb(Bs + br * SSTR + kk + t4 * 2 + 8);
            }
            #pragma unroll
            for (int m = 0; m < 4; m++) {
                const int ar0 = wm * 64 + m * 16 + grp;
                uint32_t ah[4];
                ah[0] = ldb(Ash + ar0 * SSTR + kk + t4 * 2);
                ah[1] = ldb(Ash + (ar0 + 8) * SSTR + kk + t4 * 2);
                ah[2] = ldb(Ash + ar0 * SSTR + kk + t4 * 2 + 8);
                ah[3] = ldb(Ash + (ar0 + 8) * SSTR + kk + t4 * 2 + 8);
                #pragma unroll
                for (int n = 0; n < 4; n++)
                    mma_f16(acc[m][n], ah, bh[n]);
            }
        }
        __syncthreads();
        if (ch + 2 < nch) load_stage(ch + 2, s);
    }

    #pragma unroll
    for (int m = 0; m < 4; m++) {
        const int row0 = m0 + wm * 64 + m * 16 + grp;
        #pragma unroll
        for (int n = 0; n < 4; n++) {
            const int col = n0 + wn * 32 + n * 8 + t4 * 2;
            if (C) {
                float b0 = 0.f, b1 = 0.f;
                if (bias) { b0 = bias[col]; b1 = bias[col + 1]; }
                *(float2*)(C + (size_t)row0 * N + col) =
                    make_float2(acc[m][n][0] + b0, acc[m][n][1] + b1);
                *(float2*)(C + (size_t)(row0 + 8) * N + col) =
                    make_float2(acc[m][n][2] + b0, acc[m][n][3] + b1);
            } else {
                *(uint32_t*)(Ch + (size_t)row0 * N + col) = pack_hi(acc[m][n][0], acc[m][n][1]);
                *(uint32_t*)(Ch + (size_t)(row0 + 8) * N + col) = pack_hi(acc[m][n][2], acc[m][n][3]);
            }
        }
    }
}

// ---------------- prep kernels ----------------
__global__ void cvt_kernel(const float* __restrict__ X,
                           fp16* __restrict__ H, int n4)
{
    int i = blockIdx.x * blockDim.x + threadIdx.x;
    if (i >= n4) return;
    float4 v = ((const float4*)X)[i];
    ((uint32_t*)H)[2 * i]     = pack_hi(v.x, v.y);
    ((uint32_t*)H)[2 * i + 1] = pack_hi(v.z, v.w);
}

__global__ void wsplit_t_kernel(const float* __restrict__ W,
                                fp16* __restrict__ Wt, int K, int N)
{
    int idx = blockIdx.x * blockDim.x + threadIdx.x;
    if (idx >= K * N) return;
    int k = idx / N, n = idx % N;
    Wt[(size_t)n * K + k] = __float2half_rn(W[idx]);
}

__global__ void wsplit4_kernel(const float* __restrict__ W0, const float* __restrict__ W1,
                               const float* __restrict__ W2, const float* __restrict__ W3,
                               fp16* __restrict__ Wt)
{
    int idx = blockIdx.x * blockDim.x + threadIdx.x;
    if (idx >= CD * ID) return;
    const int which = blockIdx.y;
    const float* W = (which == 0) ? W0 : (which == 1) ? W1 : (which == 2) ? W2 : W3;
    int k = idx / ID, n = idx % ID;
    Wt[(size_t)which * ID * CD + (size_t)n * CD + k] = __float2half_rn(W[idx]);
}

__global__ void pack_txt_kernel(const float* __restrict__ ctx,
                                fp16* __restrict__ H)
{
    int i = blockIdx.x * blockDim.x + threadIdx.x;
    if (i >= TXT_PAD * CD / 4) return;
    int r = i / (CD / 4), c4 = i % (CD / 4);
    float4 v = make_float4(0.f, 0.f, 0.f, 0.f);
    if (r < TXT_ROWS) {
        int b = r / TXT, j = r % TXT;
        v = *(const float4*)(ctx + ((size_t)b * CTX + j) * CD + c4 * 4);
    }
    ((uint32_t*)H)[2 * i]     = pack_hi(v.x, v.y);
    ((uint32_t*)H)[2 * i + 1] = pack_hi(v.z, v.w);
}

__global__ void pack_img_kernel(const float* __restrict__ ctx,
                                fp16* __restrict__ H)
{
    int i = blockIdx.x * blockDim.x + threadIdx.x;
    if (i >= IMG_ROWS * CD / 4) return;
    int r = i / (CD / 4), c4 = i % (CD / 4);
    int b = r / IMG, j = r % IMG;
    float4 v = *(const float4*)(ctx + ((size_t)b * CTX + TXT + j) * CD + c4 * 4);
    ((uint32_t*)H)[2 * i]     = pack_hi(v.x, v.y);
    ((uint32_t*)H)[2 * i + 1] = pack_hi(v.z, v.w);
}

// ---------------- fused Q-proj + attention ----------------
// Smem: fixed (K, V^T, P) + union (x/W pipeline | scores S). Aliasing safe:
// Q-proj loop ends with __syncthreads() after last pipeline read.
#define AT_THREADS 256
#define QSTR 72
#define PSTR 104
#define SSTR_F 97
#define XSTR 40

#define F_K    0
#define F_V    (F_K + 96*QSTR)
#define F_PH   (F_V + 64*PSTR)
#define F_PIPE (F_PH + 128*PSTR)
#define XSTAGE (128*XSTR)
#define WSTAGE (64*XSTR)
#define PIPE_ELEM (2*XSTAGE + 2*WSTAGE)
#define S_ELEM    (128*SSTR_F*2)
#define UNION_ELEM (S_ELEM > PIPE_ELEM ? S_ELEM : PIPE_ELEM)
#define ATT_SMEM  ((F_PIPE + UNION_ELEM) * 2)   // ~101 KB -> 2 CTA/SM

__global__ __launch_bounds__(AT_THREADS, 2)
void fused_qattn_kernel(const fp16* __restrict__ x,
                        const fp16* __restrict__ Wq,
                        const fp16* __restrict__ KVt, const fp16* __restrict__ KVi,
                        fp16* __restrict__ Aout,
                        const float* __restrict__ ts_p, const float* __restrict__ is_p)
{
    extern __shared__ fp16 sm[];
    fp16* sK  = sm + F_K;
    fp16* sV  = sm + F_V;   // transposed [d][key]
    fp16* sPh = sm + F_PH;
    float* S  = (float*)(sm + F_PIPE);
    const uint32_t sbase = smem_u32(sm);

    const int b = blockIdx.z, h = blockIdx.y;
    const int tid = threadIdx.x;
    const int wid = tid >> 5, lid = tid & 31;
    const int grp = lid >> 2, t4 = lid & 3;
    const int m0w = wid * 16;
    const size_t qrow0 = (size_t)b * NQ + blockIdx.x * 128;

    auto load_stage = [&](int ch, int s) {
        const int k0 = ch * GBK;
        const uint32_t xb = sbase + (F_PIPE + s * XSTAGE) * 2;
        const uint32_t wb = sbase + (F_PIPE + 2 * XSTAGE + s * WSTAGE) * 2;
        #pragma unroll
        for (int i = 0; i < 2; i++) {
            const int c = tid + i * AT_THREADS;
            const int r = c >> 2, cb = (c & 3) * 8;
            const uint32_t so = (uint32_t)(r * XSTR + cb) * 2;
            cp16(xb + so, x + (qrow0 + r) * QD + k0 + cb);
        }
        {
            const int r = tid >> 2, cb = (tid & 3) * 8;
            const uint32_t so = (uint32_t)(r * XSTR + cb) * 2;
            cp16(wb + so, Wq + (size_t)(h * DH + r) * QD + k0 + cb);
        }
        CP_COMMIT();
    };

    load_stage(0, 0);
    load_stage(1, 1);

    // stage K (96 rows, zero pad 77..79) and V transposed; fused KV layout
    for (int i = tid; i < 96 * 8; i += AT_THREADS) {
        const int r = i >> 3, c = i & 7;
        uint4 vk = make_uint4(0, 0, 0, 0);
        if (r < TXT) {
            vk = *(const uint4*)(KVt + ((size_t)b * TXT + r) * KVW + h * DH + c * 8);
        } else if (r >= 80) {
            vk = *(const uint4*)(KVi + ((size_t)b * IMG + (r - 80)) * KVW + h * DH + c * 8);
        }
        *(uint4*)(sK + r * QSTR + c * 8) = vk;
    }
    for (int i = tid; i < 96 * 32; i += AT_THREADS) {
        const int j = i >> 5, d = (i & 31) * 2;
        __half2 vv = __halves2half2(__float2half_rn(0.f), __float2half_rn(0.f));
        if (j < TXT) {
            vv = *(const __half2*)(KVt + ((size_t)b * TXT + j) * KVW + 512 + h * DH + d);
        } else if (j >= 80) {
            vv = *(const __half2*)(KVi + ((size_t)b * IMG + (j - 80)) * KVW + 512 + h * DH + d);
        }
        sV[d * PSTR + j] = __low2half(vv);
        sV[(d + 1) * PSTR + j] = __high2half(vv);
    }

    float qacc[8][4];
    #pragma unroll
    for (int n = 0; n < 8; n++)
        #pragma unroll
        for (int j = 0; j < 4; j++) qacc[n][j] = 0.f;

    const int nch = QD / GBK;   // 10
    for (int ch = 0; ch < nch; ch++) {
        if (ch + 2 <= nch) { CP_WAIT(1); } else { CP_WAIT(0); }
        __syncthreads();

        const int s = ch & 1;
        const fp16* Xs = sm + F_PIPE + s * XSTAGE;
        const fp16* Ws = sm + F_PIPE + 2 * XSTAGE + s * WSTAGE;

        #pragma unroll
        for (int kk = 0; kk < GBK; kk += 16) {
            const fp16* xb = Xs + (m0w + grp) * XSTR + kk + t4 * 2;
            uint32_t ah[4];
            ah[0] = ldb(xb);       ah[1] = ldb(xb + 8 * XSTR);
            ah[2] = ldb(xb + 8);   ah[3] = ldb(xb + 8 * XSTR + 8);
            #pragma unroll
            for (int n = 0; n < 8; n++) {
                const fp16* wb = Ws + (n * 8 + grp) * XSTR + kk + t4 * 2;
                uint32_t bh[2] = { ldb(wb), ldb(wb + 8) };
                mma_f16(qacc[n], ah, bh);
            }
        }
        __syncthreads();
        if (ch + 2 < nch) load_stage(ch + 2, s);
    }
    // Pipeline region dead; S may alias it.

    // reshape Q accumulators -> QK^T A-fragments (single fp16)
    uint32_t qah[4][4];
    #pragma unroll
    for (int i = 0; i < 4; i++) {
        qah[i][0] = pack_hi(qacc[2*i][0], qacc[2*i][1]);
        qah[i][1] = pack_hi(qacc[2*i][2], qacc[2*i][3]);
        qah[i][2] = pack_hi(qacc[2*i+1][0], qacc[2*i+1][1]);
        qah[i][3] = pack_hi(qacc[2*i+1][2], qacc[2*i+1][3]);
    }

    // QK^T: warp = 16 rows x 96 keys (single-term Q)
    {
        float acc[12][4];
        #pragma unroll
        for (int n = 0; n < 12; n++)
            #pragma unroll
            for (int j = 0; j < 4; j++) acc[n][j] = 0.f;

        #pragma unroll
        for (int i = 0; i < 4; i++) {
            const int kk = i * 16;
            #pragma unroll
            for (int n = 0; n < 12; n++) {
                const fp16* kb = sK + (n * 8 + grp) * QSTR + kk + t4 * 2;
                uint32_t bh[2] = { ldb(kb), ldb(kb + 8) };
                mma_f16(acc[n], qah[i], bh);
            }
        }
        #pragma unroll
        for (int n = 0; n < 12; n++) {
            const int cb = n * 8 + 2 * t4;
            S[(m0w + grp) * SSTR_F + cb]     = acc[n][0] * ATT_SCALE;
            S[(m0w + grp) * SSTR_F + cb + 1] = acc[n][1] * ATT_SCALE;
            S[(m0w + grp + 8) * SSTR_F + cb]     = acc[n][2] * ATT_SCALE;
            S[(m0w + grp + 8) * SSTR_F + cb + 1] = acc[n][3] * ATT_SCALE;
        }
    }
    __syncthreads();

    // softmax per row, fold scales into P (single fp16)
    if (tid < 128) {
        float* Sr = S + tid * SSTR_F;
        float mt = -1e30f, mi = -1e30f;
        for (int j = 0; j < TXT; j++) mt = fmaxf(mt, Sr[j]);
        for (int j = 80; j < 96; j++) mi = fmaxf(mi, Sr[j]);
        float lt = 0.f, li = 0.f;
        for (int j = 0; j < TXT; j++) { float e = __expf(Sr[j] - mt); lt += e; Sr[j] = e; }
        for (int j = 80; j < 96; j++) { float e = __expf(Sr[j] - mi); li += e; Sr[j] = e; }
        const float ct = ts_p[0] / lt;
        const float ci = is_p[0] / li;
        fp16* ph = sPh + tid * PSTR;
        for (int j = 0; j < 96; j++) {
            float p = (j < TXT) ? Sr[j] * ct : ((j >= 80) ? Sr[j] * ci : 0.f);
            ph[j] = __float2half_rn(p);
        }
    }
    __syncthreads();

    // PV: warp = 16 rows x 64 dims, K=96 (single-term P)
    {
        float acc[8][4];
        #pragma unroll
        for (int n = 0; n < 8; n++)
            #pragma unroll
            for (int j = 0; j < 4; j++) acc[n][j] = 0.f;

        #pragma unroll
        for (int kk = 0; kk < 96; kk += 16) {
            const fp16* pb = sPh + (m0w + grp) * PSTR + kk + t4 * 2;
            uint32_t ah[4];
            ah[0] = ldb(pb);            ah[1] = ldb(pb + 8 * PSTR);
            ah[2] = ldb(pb + 8);        ah[3] = ldb(pb + 8 * PSTR + 8);
            #pragma unroll
            for (int n = 0; n < 8; n++) {
                const fp16* vb = sV + (n * 8 + grp) * PSTR + kk + t4 * 2;
                uint32_t bh[2] = { ldb(vb), ldb(vb + 8) };
                mma_f16(acc[n], ah, bh);
            }
        }
        const size_t rg = qrow0 + m0w + grp;
        #pragma unroll
        for (int n = 0; n < 8; n++) {
            const int col = h * DH + n * 8 + 2 * t4;
            *(uint32_t*)(Aout + rg * ID + col) = pack_hi(acc[n][0], acc[n][1]);
            *(uint32_t*)(Aout + (rg + 8) * ID + col) = pack_hi(acc[n][2], acc[n][3]);
        }
    }
}

// ---------------- launch ----------------
extern "C" void kernel_launch(void* const* d_in, const int* in_sizes, int n_in,
                              void* d_out, int out_size)
{
    const float* x    = (const float*)d_in[0];
    const float* ctx  = (const float*)d_in[1];
    const float* Wq   = (const float*)d_in[2];
    const float* Wk   = (const float*)d_in[3];
    const float* Wv   = (const float*)d_in[4];
    const float* Wkip = (const float*)d_in[5];
    const float* Wvip = (const float*)d_in[6];
    const float* Wo   = (const float*)d_in[7];
    const float* bo   = (const float*)d_in[8];
    const float* ts   = (const float*)d_in[9];
    const float* isc  = (const float*)d_in[10];
    float* out = (float*)d_out;

    fp16 *gA, *gx, *gWq, *gWo, *gWc, *gct, *gci, *gKVt, *gKVi;
    cudaGetSymbolAddress((void**)&gA,   g_A);
    cudaGetSymbolAddress((void**)&gx,   g_x);
    cudaGetSymbolAddress((void**)&gWq,  g_Wq);
    cudaGetSymbolAddress((void**)&gWo,  g_Wo);
    cudaGetSymbolAddress((void**)&gWc,  g_Wc);
    cudaGetSymbolAddress((void**)&gct,  g_ct);
    cudaGetSymbolAddress((void**)&gci,  g_ci);
    cudaGetSymbolAddress((void**)&gKVt, g_KVt);
    cudaGetSymbolAddress((void**)&gKVi, g_KVi);

    cudaFuncSetAttribute(mma_gemm_kernel,
                         cudaFuncAttributeMaxDynamicSharedMemorySize, GEMM_SMEM);
    cudaFuncSetAttribute(fused_qattn_kernel,
                         cudaFuncAttributeMaxDynamicSharedMemorySize, ATT_SMEM);

    // ---- prep
    wsplit_t_kernel<<<(QD * ID + 255) / 256, 256>>>(Wq, gWq, QD, ID);
    wsplit_t_kernel<<<(ID * QD + 255) / 256, 256>>>(Wo, gWo, ID, QD);
    {
        dim3 g((CD * ID + 255) / 256, 4);
        wsplit4_kernel<<<g, 256>>>(Wk, Wv, Wkip, Wvip, gWc);
    }
    pack_txt_kernel<<<(TXT_PAD * CD / 4 + 255) / 256, 256>>>(ctx, gct);
    pack_img_kernel<<<(IMG_ROWS * CD / 4 + 255) / 256, 256>>>(ctx, gci);
    cvt_kernel<<<(MQ * QD / 4 + 255) / 256, 256>>>(x, gx, MQ * QD / 4);

    // ---- ctx projections: fused K|V (N=1024), 2 launches
    {
        dim3 gt(KVW / 64, TXT_PAD / 128);
        mma_gemm_kernel<<<gt, 128, GEMM_SMEM>>>(gct, gWc,
            nullptr, gKVt, nullptr, TXT_PAD, KVW, CD);
        dim3 gi(KVW / 64, IMG_ROWS / 128);
        mma_gemm_kernel<<<gi, 128, GEMM_SMEM>>>(gci, gWc + 2 * (size_t)ID * CD,
            nullptr, gKVi, nullptr, IMG_ROWS, KVW, CD);
    }

    // ---- fused Q-proj + attention
    {
        dim3 g(NQ / 128, HEADS, BATCH);
        fused_qattn_kernel<<<g, AT_THREADS, ATT_SMEM>>>(gx, gWq, gKVt, gKVi,
                                                        gA, ts, isc);
    }

    // ---- out projection (fp32 + bias)
    {
        dim3 g(QD / 64, MQ / 128);
        mma_gemm_kernel<<<g, 128, GEMM_SMEM>>>(gA, gWo, out, nullptr, bo,
                                               MQ, QD, ID);
    }
}

// round 11
// speedup vs baseline: 4.1292x; 1.0430x over previous
#include <cuda_runtime.h>
#include <cuda_fp16.h>
#include <cstdint>
#include <cstddef>

// Problem constants
#define BATCH   16
#define NQ      4096
#define QD      320
#define CD      1024
#define CTX     93
#define TXT     77
#define IMG     16
#define HEADS   8
#define DH      64
#define ID      512
#define MQ      (BATCH*NQ)
#define ATT_SCALE 0.125f

#define TXT_ROWS (BATCH*TXT)
#define TXT_PAD  1280
#define IMG_ROWS (BATCH*IMG)
#define KVW      1024

typedef __half fp16;

// ---------------- scratch ----------------
__device__ fp16 g_A  [MQ * ID];
__device__ fp16 g_x  [MQ * QD];
__device__ fp16 g_Wq [ID * QD];
__device__ fp16 g_Wo [QD * ID];
__device__ fp16 g_Wc [4][ID * CD];
__device__ fp16 g_ct [TXT_PAD * CD];
__device__ fp16 g_ci [IMG_ROWS * CD];
__device__ fp16 g_KVt[TXT_PAD * KVW];
__device__ fp16 g_KVi[IMG_ROWS * KVW];

// ---------------- helpers ----------------
__device__ __forceinline__ uint32_t smem_u32(const void* p) {
    uint32_t a;
    asm("{ .reg .u64 t; cvta.to.shared.u64 t, %1; cvt.u32.u64 %0, t; }"
        : "=r"(a) : "l"(p));
    return a;
}
__device__ __forceinline__ void cp16(uint32_t dst, const void* src) {
    asm volatile("cp.async.cg.shared.global [%0], [%1], 16;" :: "r"(dst), "l"(src));
}
#define CP_COMMIT() asm volatile("cp.async.commit_group;" ::: "memory")
#define CP_WAIT(n)  asm volatile("cp.async.wait_group %0;" :: "n"(n) : "memory")

__device__ __forceinline__ void mma_f16(float* c, const uint32_t* a, const uint32_t* b)
{
    asm volatile(
        "mma.sync.aligned.m16n8k16.row.col.f32.f16.f16.f32 "
        "{%0,%1,%2,%3}, {%4,%5,%6,%7}, {%8,%9}, {%0,%1,%2,%3};"
        : "+f"(c[0]), "+f"(c[1]), "+f"(c[2]), "+f"(c[3])
        : "r"(a[0]), "r"(a[1]), "r"(a[2]), "r"(a[3]), "r"(b[0]), "r"(b[1]));
}
__device__ __forceinline__ void ldm_x4(uint32_t& r0, uint32_t& r1,
                                       uint32_t& r2, uint32_t& r3, uint32_t addr)
{
    asm volatile("ldmatrix.sync.aligned.m8n8.x4.shared.b16 {%0,%1,%2,%3}, [%4];"
                 : "=r"(r0), "=r"(r1), "=r"(r2), "=r"(r3) : "r"(addr));
}
__device__ __forceinline__ uint32_t pack_hi(float a, float b) {
    __half2 p = __floats2half2_rn(a, b);
    return *(uint32_t*)&p;
}

// ---------------- fp16 GEMM, single-term A, ldmatrix fragments -----------
#define GBK 32
#define SSTR 40
#define A_ELEM (128 * SSTR)
#define B_ELEM (64 * SSTR)
#define STAGE_ELEM (A_ELEM + B_ELEM)
#define GEMM_SMEM (2 * STAGE_ELEM * 2)

__global__ __launch_bounds__(128)
void mma_gemm_kernel(const fp16* __restrict__ Ah,
                     const fp16* __restrict__ W,
                     float* __restrict__ C, fp16* __restrict__ Ch,
                     const float* __restrict__ bias,
                     int M, int N, int K)
{
    extern __shared__ fp16 smem[];
    const uint32_t sbase = smem_u32(smem);

    const int tid = threadIdx.x;
    const int wid = tid >> 5;
    const int lid = tid & 31;
    const int grp = lid >> 2;
    const int t4  = lid & 3;
    const int wm  = wid >> 1;
    const int wn  = wid & 1;
    const int m0  = blockIdx.y * 128;
    const int n0  = blockIdx.x * 64;

    // ldmatrix per-lane offsets (halves)
    const uint32_t aoff = (uint32_t)((lid & 15) * SSTR + (lid >> 4) * 8);
    const uint32_t boff = (uint32_t)((((lid >> 4) << 3) + (lid & 7)) * SSTR
                                     + ((lid >> 3) & 1) * 8);

    float acc[4][4][4];
    #pragma unroll
    for (int m = 0; m < 4; m++)
        #pragma unroll
        for (int n = 0; n < 4; n++)
            #pragma unroll
            for (int j = 0; j < 4; j++) acc[m][n][j] = 0.f;

    const int nch = K / GBK;

    auto load_stage = [&](int ch, int s) {
        const int k0 = ch * GBK;
        const uint32_t base = sbase + (uint32_t)s * STAGE_ELEM * 2;
        #pragma unroll
        for (int i = 0; i < 4; i++) {
            const int c = tid + i * 128;
            const int r = c >> 2, cb = (c & 3) * 8;
            const uint32_t so = (uint32_t)(r * SSTR + cb) * 2;
            cp16(base + so, Ah + (size_t)(m0 + r) * K + k0 + cb);
        }
        #pragma unroll
        for (int i = 0; i < 2; i++) {
            const int c = tid + i * 128;
            const int r = c >> 2, cb = (c & 3) * 8;
            const uint32_t so = (uint32_t)(r * SSTR + cb) * 2;
            cp16(base + A_ELEM * 2 + so, W + (size_t)(n0 + r) * K + k0 + cb);
        }
        CP_COMMIT();
    };

    load_stage(0, 0);
    if (nch > 1) load_stage(1, 1);

    for (int ch = 0; ch < nch; ch++) {
        if (ch + 2 <= nch) { CP_WAIT(1); } else { CP_WAIT(0); }
        __syncthreads();

        const int s = ch & 1;
        const uint32_t Abase = sbase + (uint32_t)s * STAGE_ELEM * 2;
        const uint32_t Bbase = Abase + A_ELEM * 2;

        #pragma unroll
        for (int kk = 0; kk < GBK; kk += 16) {
            uint32_t bh[4][2];
            ldm_x4(bh[0][0], bh[0][1], bh[1][0], bh[1][1],
                   Bbase + ((uint32_t)((wn * 32) * SSTR + kk) + boff) * 2);
            ldm_x4(bh[2][0], bh[2][1], bh[3][0], bh[3][1],
                   Bbase + ((uint32_t)((wn * 32 + 16) * SSTR + kk) + boff) * 2);
            #pragma unroll
            for (int m = 0; m < 4; m++) {
                uint32_t ah[4];
                ldm_x4(ah[0], ah[1], ah[2], ah[3],
                       Abase + ((uint32_t)((wm * 64 + m * 16) * SSTR + kk) + aoff) * 2);
                #pragma unroll
                for (int n = 0; n < 4; n++)
                    mma_f16(acc[m][n], ah, bh[n]);
            }
        }
        __syncthreads();
        if (ch + 2 < nch) load_stage(ch + 2, s);
    }

    #pragma unroll
    for (int m = 0; m < 4; m++) {
        const int row0 = m0 + wm * 64 + m * 16 + grp;
        #pragma unroll
        for (int n = 0; n < 4; n++) {
            const int col = n0 + wn * 32 + n * 8 + t4 * 2;
            if (C) {
                float b0 = 0.f, b1 = 0.f;
                if (bias) { b0 = bias[col]; b1 = bias[col + 1]; }
                *(float2*)(C + (size_t)row0 * N + col) =
                    make_float2(acc[m][n][0] + b0, acc[m][n][1] + b1);
                *(float2*)(C + (size_t)(row0 + 8) * N + col) =
                    make_float2(acc[m][n][2] + b0, acc[m][n][3] + b1);
            } else {
                *(uint32_t*)(Ch + (size_t)row0 * N + col) = pack_hi(acc[m][n][0], acc[m][n][1]);
                *(uint32_t*)(Ch + (size_t)(row0 + 8) * N + col) = pack_hi(acc[m][n][2], acc[m][n][3]);
            }
        }
    }
}

// ---------------- prep kernels ----------------
__global__ void cvt_kernel(const float* __restrict__ X,
                           fp16* __restrict__ H, int n4)
{
    int i = blockIdx.x * blockDim.x + threadIdx.x;
    if (i >= n4) return;
    float4 v = ((const float4*)X)[i];
    ((uint32_t*)H)[2 * i]     = pack_hi(v.x, v.y);
    ((uint32_t*)H)[2 * i + 1] = pack_hi(v.z, v.w);
}

__global__ void wsplit_t_kernel(const float* __restrict__ W,
                                fp16* __restrict__ Wt, int K, int N)
{
    int idx = blockIdx.x * blockDim.x + threadIdx.x;
    if (idx >= K * N) return;
    int k = idx / N, n = idx % N;
    Wt[(size_t)n * K + k] = __float2half_rn(W[idx]);
}

__global__ void wsplit4_kernel(const float* __restrict__ W0, const float* __restrict__ W1,
                               const float* __restrict__ W2, const float* __restrict__ W3,
                               fp16* __restrict__ Wt)
{
    int idx = blockIdx.x * blockDim.x + threadIdx.x;
    if (idx >= CD * ID) return;
    const int which = blockIdx.y;
    const float* W = (which == 0) ? W0 : (which == 1) ? W1 : (which == 2) ? W2 : W3;
    int k = idx / ID, n = idx % ID;
    Wt[(size_t)which * ID * CD + (size_t)n * CD + k] = __float2half_rn(W[idx]);
}

__global__ void pack_txt_kernel(const float* __restrict__ ctx,
                                fp16* __restrict__ H)
{
    int i = blockIdx.x * blockDim.x + threadIdx.x;
    if (i >= TXT_PAD * CD / 4) return;
    int r = i / (CD / 4), c4 = i % (CD / 4);
    float4 v = make_float4(0.f, 0.f, 0.f, 0.f);
    if (r < TXT_ROWS) {
        int b = r / TXT, j = r % TXT;
        v = *(const float4*)(ctx + ((size_t)b * CTX + j) * CD + c4 * 4);
    }
    ((uint32_t*)H)[2 * i]     = pack_hi(v.x, v.y);
    ((uint32_t*)H)[2 * i + 1] = pack_hi(v.z, v.w);
}

__global__ void pack_img_kernel(const float* __restrict__ ctx,
                                fp16* __restrict__ H)
{
    int i = blockIdx.x * blockDim.x + threadIdx.x;
    if (i >= IMG_ROWS * CD / 4) return;
    int r = i / (CD / 4), c4 = i % (CD / 4);
    int b = r / IMG, j = r % IMG;
    float4 v = *(const float4*)(ctx + ((size_t)b * CTX + TXT + j) * CD + c4 * 4);
    ((uint32_t*)H)[2 * i]     = pack_hi(v.x, v.y);
    ((uint32_t*)H)[2 * i + 1] = pack_hi(v.z, v.w);
}

// ---------------- fused Q-proj + attention ----------------
#define AT_THREADS 256
#define QSTR 72
#define PSTR 104
#define SSTR_F 97
#define XSTR 40

#define F_K    0
#define F_V    (F_K + 96*QSTR)
#define F_PH   (F_V + 64*PSTR)
#define F_PIPE (F_PH + 128*PSTR)
#define XSTAGE (128*XSTR)
#define WSTAGE (64*XSTR)
#define PIPE_ELEM (2*XSTAGE + 2*WSTAGE)
#define S_ELEM    (128*SSTR_F*2)
#define UNION_ELEM (S_ELEM > PIPE_ELEM ? S_ELEM : PIPE_ELEM)
#define ATT_SMEM  ((F_PIPE + UNION_ELEM) * 2)

__global__ __launch_bounds__(AT_THREADS, 2)
void fused_qattn_kernel(const fp16* __restrict__ x,
                        const fp16* __restrict__ Wq,
                        const fp16* __restrict__ KVt, const fp16* __restrict__ KVi,
                        fp16* __restrict__ Aout,
                        const float* __restrict__ ts_p, const float* __restrict__ is_p)
{
    extern __shared__ fp16 sm[];
    fp16* sK  = sm + F_K;
    fp16* sV  = sm + F_V;
    fp16* sPh = sm + F_PH;
    float* S  = (float*)(sm + F_PIPE);
    const uint32_t sbase = smem_u32(sm);

    const int b = blockIdx.z, h = blockIdx.y;
    const int tid = threadIdx.x;
    const int wid = tid >> 5, lid = tid & 31;
    const int grp = lid >> 2, t4 = lid & 3;
    const int m0w = wid * 16;
    const size_t qrow0 = (size_t)b * NQ + blockIdx.x * 128;

    // ldmatrix lane offsets (halves) per stride
    const uint32_t aoffX = (uint32_t)((lid & 15) * XSTR + (lid >> 4) * 8);
    const uint32_t boffX = (uint32_t)((((lid >> 4) << 3) + (lid & 7)) * XSTR
                                      + ((lid >> 3) & 1) * 8);
    const uint32_t boffK = (uint32_t)((((lid >> 4) << 3) + (lid & 7)) * QSTR
                                      + ((lid >> 3) & 1) * 8);
    const uint32_t aoffP = (uint32_t)((lid & 15) * PSTR + (lid >> 4) * 8);
    const uint32_t boffV = (uint32_t)((((lid >> 4) << 3) + (lid & 7)) * PSTR
                                      + ((lid >> 3) & 1) * 8);

    auto load_stage = [&](int ch, int s) {
        const int k0 = ch * GBK;
        const uint32_t xb = sbase + (F_PIPE + s * XSTAGE) * 2;
        const uint32_t wb = sbase + (F_PIPE + 2 * XSTAGE + s * WSTAGE) * 2;
        #pragma unroll
        for (int i = 0; i < 2; i++) {
            const int c = tid + i * AT_THREADS;
            const int r = c >> 2, cb = (c & 3) * 8;
            const uint32_t so = (uint32_t)(r * XSTR + cb) * 2;
            cp16(xb + so, x + (qrow0 + r) * QD + k0 + cb);
        }
        {
            const int r = tid >> 2, cb = (tid & 3) * 8;
            const uint32_t so = (uint32_t)(r * XSTR + cb) * 2;
            cp16(wb + so, Wq + (size_t)(h * DH + r) * QD + k0 + cb);
        }
        CP_COMMIT();
    };

    load_stage(0, 0);
    load_stage(1, 1);

    // stage K (96 rows, zero pad 77..79) and V transposed; fused KV layout
    for (int i = tid; i < 96 * 8; i += AT_THREADS) {
        const int r = i >> 3, c = i & 7;
        uint4 vk = make_uint4(0, 0, 0, 0);
        if (r < TXT) {
            vk = *(const uint4*)(KVt + ((size_t)b * TXT + r) * KVW + h * DH + c * 8);
        } else if (r >= 80) {
            vk = *(const uint4*)(KVi + ((size_t)b * IMG + (r - 80)) * KVW + h * DH + c * 8);
        }
        *(uint4*)(sK + r * QSTR + c * 8) = vk;
    }
    for (int i = tid; i < 96 * 32; i += AT_THREADS) {
        const int j = i >> 5, d = (i & 31) * 2;
        __half2 vv = __halves2half2(__float2half_rn(0.f), __float2half_rn(0.f));
        if (j < TXT) {
            vv = *(const __half2*)(KVt + ((size_t)b * TXT + j) * KVW + 512 + h * DH + d);
        } else if (j >= 80) {
            vv = *(const __half2*)(KVi + ((size_t)b * IMG + (j - 80)) * KVW + 512 + h * DH + d);
        }
        sV[d * PSTR + j] = __low2half(vv);
        sV[(d + 1) * PSTR + j] = __high2half(vv);
    }

    float qacc[8][4];
    #pragma unroll
    for (int n = 0; n < 8; n++)
        #pragma unroll
        for (int j = 0; j < 4; j++) qacc[n][j] = 0.f;

    const int nch = QD / GBK;   // 10
    for (int ch = 0; ch < nch; ch++) {
        if (ch + 2 <= nch) { CP_WAIT(1); } else { CP_WAIT(0); }
        __syncthreads();

        const int s = ch & 1;
        const uint32_t Xbase = sbase + (F_PIPE + s * XSTAGE) * 2;
        const uint32_t Wbase = sbase + (F_PIPE + 2 * XSTAGE + s * WSTAGE) * 2;

        #pragma unroll
        for (int kk = 0; kk < GBK; kk += 16) {
            uint32_t ah[4];
            ldm_x4(ah[0], ah[1], ah[2], ah[3],
                   Xbase + ((uint32_t)(m0w * XSTR + kk) + aoffX) * 2);
            #pragma unroll
            for (int np = 0; np < 4; np++) {
                uint32_t b0[2], b1[2];
                ldm_x4(b0[0], b0[1], b1[0], b1[1],
                       Wbase + ((uint32_t)((np * 16) * XSTR + kk) + boffX) * 2);
                mma_f16(qacc[2 * np],     ah, b0);
                mma_f16(qacc[2 * np + 1], ah, b1);
            }
        }
        __syncthreads();
        if (ch + 2 < nch) load_stage(ch + 2, s);
    }
    // Pipeline region dead; S may alias it.

    // reshape Q accumulators -> QK^T A-fragments (single fp16)
    uint32_t qah[4][4];
    #pragma unroll
    for (int i = 0; i < 4; i++) {
        qah[i][0] = pack_hi(qacc[2*i][0], qacc[2*i][1]);
        qah[i][1] = pack_hi(qacc[2*i][2], qacc[2*i][3]);
        qah[i][2] = pack_hi(qacc[2*i+1][0], qacc[2*i+1][1]);
        qah[i][3] = pack_hi(qacc[2*i+1][2], qacc[2*i+1][3]);
    }

    // QK^T: warp = 16 rows x 96 keys (single-term Q, ldmatrix K)
    {
        float acc[12][4];
        #pragma unroll
        for (int n = 0; n < 12; n++)
            #pragma unroll
            for (int j = 0; j < 4; j++) acc[n][j] = 0.f;

        #pragma unroll
        for (int i = 0; i < 4; i++) {
            const int kk = i * 16;
            #pragma unroll
            for (int np = 0; np < 6; np++) {
                uint32_t b0[2], b1[2];
                ldm_x4(b0[0], b0[1], b1[0], b1[1],
                       sbase + (F_K) * 2 + ((uint32_t)((np * 16) * QSTR + kk) + boffK) * 2);
                mma_f16(acc[2 * np],     qah[i], b0);
                mma_f16(acc[2 * np + 1], qah[i], b1);
            }
        }
        #pragma unroll
        for (int n = 0; n < 12; n++) {
            const int cb = n * 8 + 2 * t4;
            S[(m0w + grp) * SSTR_F + cb]     = acc[n][0] * ATT_SCALE;
            S[(m0w + grp) * SSTR_F + cb + 1] = acc[n][1] * ATT_SCALE;
            S[(m0w + grp + 8) * SSTR_F + cb]     = acc[n][2] * ATT_SCALE;
            S[(m0w + grp + 8) * SSTR_F + cb + 1] = acc[n][3] * ATT_SCALE;
        }
    }
    __syncthreads();

    // softmax per row, fold scales into P (single fp16)
    if (tid < 128) {
        float* Sr = S + tid * SSTR_F;
        float mt = -1e30f, mi = -1e30f;
        for (int j = 0; j < TXT; j++) mt = fmaxf(mt, Sr[j]);
        for (int j = 80; j < 96; j++) mi = fmaxf(mi, Sr[j]);
        float lt = 0.f, li = 0.f;
        for (int j = 0; j < TXT; j++) { float e = __expf(Sr[j] - mt); lt += e; Sr[j] = e; }
        for (int j = 80; j < 96; j++) { float e = __expf(Sr[j] - mi); li += e; Sr[j] = e; }
        const float ct = ts_p[0] / lt;
        const float ci = is_p[0] / li;
        fp16* ph = sPh + tid * PSTR;
        for (int j = 0; j < 96; j++) {
            float p = (j < TXT) ? Sr[j] * ct : ((j >= 80) ? Sr[j] * ci : 0.f);
            ph[j] = __float2half_rn(p);
        }
    }
    __syncthreads();

    // PV: warp = 16 rows x 64 dims, K=96 (single-term P, ldmatrix)
    {
        float acc[8][4];
        #pragma unroll
        for (int n = 0; n < 8; n++)
            #pragma unroll
            for (int j = 0; j < 4; j++) acc[n][j] = 0.f;

        #pragma unroll
        for (int kk = 0; kk < 96; kk += 16) {
            uint32_t ah[4];
            ldm_x4(ah[0], ah[1], ah[2], ah[3],
                   sbase + (F_PH) * 2 + ((uint32_t)(m0w * PSTR + kk) + aoffP) * 2);
            #pragma unroll
            for (int np = 0; np < 4; np++) {
                uint32_t b0[2], b1[2];
                ldm_x4(b0[0], b0[1], b1[0], b1[1],
                       sbase + (F_V) * 2 + ((uint32_t)((np * 16) * PSTR + kk) + boffV) * 2);
                mma_f16(acc[2 * np],     ah, b0);
                mma_f16(acc[2 * np + 1], ah, b1);
            }
        }
        const size_t rg = qrow0 + m0w + grp;
        #pragma unroll
        for (int n = 0; n < 8; n++) {
            const int col = h * DH + n * 8 + 2 * t4;
            *(uint32_t*)(Aout + rg * ID + col) = pack_hi(acc[n][0], acc[n][1]);
            *(uint32_t*)(Aout + (rg + 8) * ID + col) = pack_hi(acc[n][2], acc[n][3]);
        }
    }
}

// ---------------- launch ----------------
extern "C" void kernel_launch(void* const* d_in, const int* in_sizes, int n_in,
                              void* d_out, int out_size)
{
    const float* x    = (const float*)d_in[0];
    const float* ctx  = (const float*)d_in[1];
    const float* Wq   = (const float*)d_in[2];
    const float* Wk   = (const float*)d_in[3];
    const float* Wv   = (const float*)d_in[4];
    const float* Wkip = (const float*)d_in[5];
    const float* Wvip = (const float*)d_in[6];
    const float* Wo   = (const float*)d_in[7];
    const float* bo   = (const float*)d_in[8];
    const float* ts   = (const float*)d_in[9];
    const float* isc  = (const float*)d_in[10];
    float* out = (float*)d_out;

    fp16 *gA, *gx, *gWq, *gWo, *gWc, *gct, *gci, *gKVt, *gKVi;
    cudaGetSymbolAddress((void**)&gA,   g_A);
    cudaGetSymbolAddress((void**)&gx,   g_x);
    cudaGetSymbolAddress((void**)&gWq,  g_Wq);
    cudaGetSymbolAddress((void**)&gWo,  g_Wo);
    cudaGetSymbolAddress((void**)&gWc,  g_Wc);
    cudaGetSymbolAddress((void**)&gct,  g_ct);
    cudaGetSymbolAddress((void**)&gci,  g_ci);
    cudaGetSymbolAddress((void**)&gKVt, g_KVt);
    cudaGetSymbolAddress((void**)&gKVi, g_KVi);

    cudaFuncSetAttribute(mma_gemm_kernel,
                         cudaFuncAttributeMaxDynamicSharedMemorySize, GEMM_SMEM);
    cudaFuncSetAttribute(fused_qattn_kernel,
                         cudaFuncAttributeMaxDynamicSharedMemorySize, ATT_SMEM);

    // ---- prep
    wsplit_t_kernel<<<(QD * ID + 255) / 256, 256>>>(Wq, gWq, QD, ID);
    wsplit_t_kernel<<<(ID * QD + 255) / 256, 256>>>(Wo, gWo, ID, QD);
    {
        dim3 g((CD * ID + 255) / 256, 4);
        wsplit4_kernel<<<g, 256>>>(Wk, Wv, Wkip, Wvip, gWc);
    }
    pack_txt_kernel<<<(TXT_PAD * CD / 4 + 255) / 256, 256>>>(ctx, gct);
    pack_img_kernel<<<(IMG_ROWS * CD / 4 + 255) / 256, 256>>>(ctx, gci);
    cvt_kernel<<<(MQ * QD / 4 + 255) / 256, 256>>>(x, gx, MQ * QD / 4);

    // ---- ctx projections: fused K|V (N=1024), 2 launches
    {
        dim3 gt(KVW / 64, TXT_PAD / 128);
        mma_gemm_kernel<<<gt, 128, GEMM_SMEM>>>(gct, gWc,
            nullptr, gKVt, nullptr, TXT_PAD, KVW, CD);
        dim3 gi(KVW / 64, IMG_ROWS / 128);
        mma_gemm_kernel<<<gi, 128, GEMM_SMEM>>>(gci, gWc + 2 * (size_t)ID * CD,
            nullptr, gKVi, nullptr, IMG_ROWS, KVW, CD);
    }

    // ---- fused Q-proj + attention
    {
        dim3 g(NQ / 128, HEADS, BATCH);
        fused_qattn_kernel<<<g, AT_THREADS, ATT_SMEM>>>(gx, gWq, gKVt, gKVi,
                                                        gA, ts, isc);
    }

    // ---- out projection (fp32 + bias)
    {
        dim3 g(QD / 64, MQ / 128);
        mma_gemm_kernel<<<g, 128, GEMM_SMEM>>>(gA, gWo, out, nullptr, bo,
                                               MQ, QD, ID);
    }
}